// round 8
// baseline (speedup 1.0000x reference)
#include <cuda_runtime.h>
#include <cuda_fp16.h>
#include <math.h>
#include <stdint.h>

#define B_  2
#define S_  2048
#define D_  1024
#define H_  16
#define HD_ 64

#define TQ  16
#define KCA 256              // attention key-chunk

#define MSZ (B_*S_)          // 4096 rows

// ---------------------------------------------------------------------------
// Scratch (allocation-free rule: __device__ globals)
// ---------------------------------------------------------------------------
__device__ float g_q [B_*S_*D_];
__device__ float g_k [B_*S_*D_];
__device__ float g_v [B_*S_*D_];

__device__ __half g_xhi[MSZ*D_];
__device__ __half g_xlo[MSZ*D_];
__device__ __half g_whi[4*D_*D_];   // Wq, Wk, Wv, Wo
__device__ __half g_wlo[4*D_*D_];
__device__ __half g_aohi[MSZ*D_];
__device__ __half g_aolo[MSZ*D_];

__device__ __half g_qhi[MSZ*D_];
__device__ __half g_qlo[MSZ*D_];
__device__ __half g_khi[MSZ*D_];
__device__ __half g_klo[MSZ*D_];
__device__ __half g_vthi[MSZ*D_];   // [B][H][64][S]
__device__ __half g_vtlo[MSZ*D_];

// ---------------------------------------------------------------------------
// fp32 -> fp16 (hi, lo) split
// ---------------------------------------------------------------------------
__global__ __launch_bounds__(256)
void convert_split(const float4* __restrict__ in,
                   uint2* __restrict__ hi, uint2* __restrict__ lo, int n4)
{
    int i = blockIdx.x * 256 + threadIdx.x;
    if (i >= n4) return;
    float4 v = in[i];
    __half2 h0 = __floats2half2_rn(v.x, v.y);
    __half2 h1 = __floats2half2_rn(v.z, v.w);
    __half2 l0 = __floats2half2_rn(v.x - __low2float(h0), v.y - __high2float(h0));
    __half2 l1 = __floats2half2_rn(v.z - __low2float(h1), v.w - __high2float(h1));
    uint2 H, L;
    H.x = *(const uint32_t*)&h0; H.y = *(const uint32_t*)&h1;
    L.x = *(const uint32_t*)&l0; L.y = *(const uint32_t*)&l1;
    hi[i] = H; lo[i] = L;
}

// ---------------------------------------------------------------------------
// V: [b, s, h*64+d] fp32  ->  VT hi/lo fp16 [b, h, d(64), s]
// ---------------------------------------------------------------------------
__global__ __launch_bounds__(256)
void transpose_split_v(const float* __restrict__ v,
                       __half* __restrict__ vthi, __half* __restrict__ vtlo)
{
    __shared__ float tile[32][33];
    const int s0 = blockIdx.x * 32, d0 = blockIdx.y * 32, b = blockIdx.z;
    const int c = threadIdx.x & 31, r4 = threadIdx.x >> 5;
    #pragma unroll
    for (int i = 0; i < 4; i++) {
        int r = r4 + i * 8;
        tile[r][c] = v[(size_t)(b*S_ + s0 + r) * D_ + d0 + c];
    }
    __syncthreads();
    #pragma unroll
    for (int i = 0; i < 4; i++) {
        int d = d0 + r4 + i * 8;
        int s = s0 + c;
        float f = tile[c][r4 + i*8];
        __half hb = __float2half_rn(f);
        float lo = f - __half2float(hb);
        size_t o = ((size_t)(b*H_ + (d >> 6)) * 64 + (d & 63)) * S_ + s;
        vthi[o] = hb;
        vtlo[o] = __float2half_rn(lo);
    }
}

// ---------------------------------------------------------------------------
// PTX helpers (non-variant ISA)
// ---------------------------------------------------------------------------
__device__ __forceinline__ uint32_t smem_u32(const void* p) {
    uint32_t a;
    asm("{ .reg .u64 t; cvta.to.shared.u64 t, %1; cvt.u32.u64 %0, t; }" : "=r"(a) : "l"(p));
    return a;
}
__device__ __forceinline__ void ldm_x4(uint32_t* r, uint32_t addr) {
    asm volatile("ldmatrix.sync.aligned.m8n8.x4.shared.b16 {%0,%1,%2,%3}, [%4];"
        : "=r"(r[0]), "=r"(r[1]), "=r"(r[2]), "=r"(r[3]) : "r"(addr));
}
__device__ __forceinline__ void ldm_x2(uint32_t* r, uint32_t addr) {
    asm volatile("ldmatrix.sync.aligned.m8n8.x2.shared.b16 {%0,%1}, [%2];"
        : "=r"(r[0]), "=r"(r[1]) : "r"(addr));
}
// fp16 inputs, fp32 accumulate (main term)
__device__ __forceinline__ void mma_f32(float* c, const uint32_t* a,
                                        uint32_t b0, uint32_t b1) {
    asm volatile(
        "mma.sync.aligned.m16n8k16.row.col.f32.f16.f16.f32 "
        "{%0,%1,%2,%3}, {%4,%5,%6,%7}, {%8,%9}, {%0,%1,%2,%3};"
        : "+f"(c[0]), "+f"(c[1]), "+f"(c[2]), "+f"(c[3])
        : "r"(a[0]), "r"(a[1]), "r"(a[2]), "r"(a[3]), "r"(b0), "r"(b1));
}
// fp16 inputs, fp16 accumulate (correction terms; c = 2x f16x2)
__device__ __forceinline__ void mma_f16(uint32_t* c, const uint32_t* a,
                                        uint32_t b0, uint32_t b1) {
    asm volatile(
        "mma.sync.aligned.m16n8k16.row.col.f16.f16.f16.f16 "
        "{%0,%1}, {%2,%3,%4,%5}, {%6,%7}, {%0,%1};"
        : "+r"(c[0]), "+r"(c[1])
        : "r"(a[0]), "r"(a[1]), "r"(a[2]), "r"(a[3]), "r"(b0), "r"(b1));
}
__device__ __forceinline__ void corr_merge(float* c, const uint32_t* cc) {
    __half2 h0 = *(const __half2*)&cc[0];
    __half2 h1 = *(const __half2*)&cc[1];
    c[0] += __low2float(h0); c[1] += __high2float(h0);
    c[2] += __low2float(h1); c[3] += __high2float(h1);
}
__device__ __forceinline__ void cp16(uint32_t dst, const void* src) {
    asm volatile("cp.async.cg.shared.global [%0], [%1], 16;" :: "r"(dst), "l"(src));
}
#define CP_COMMIT() asm volatile("cp.async.commit_group;" ::: "memory")

// ---------------------------------------------------------------------------
// HMMA GEMM: C = A @ W^T + bias, fp16 hi/lo 3-term.
// Main term f32-acc; corrections f16-acc. 3-stage cp.async, 1 CTA/SM.
// ---------------------------------------------------------------------------
#define LDT 40
#define TILE_B   (128*LDT*2)         // 10240 bytes per tile
#define STAGE_B  (4*TILE_B)          // 40960 bytes per stage
#define SM_GEMM  (3*STAGE_B)         // 122880 bytes

__global__ __launch_bounds__(256)
void gemm_hmma(const __half* __restrict__ Ahi, const __half* __restrict__ Alo,
               const __half* __restrict__ Bhi, const __half* __restrict__ Blo,
               const float* __restrict__ bias, float* __restrict__ C,
               __half* __restrict__ Chi, __half* __restrict__ Clo,
               int M, int N, int K)
{
    extern __shared__ __half dsm[];
    const uint32_t sb = smem_u32(dsm);

    const int tid = threadIdx.x;
    const int lane = tid & 31;
    const int wid  = tid >> 5;
    const int wm = wid & 1;
    const int wn = wid >> 1;
    const int m0 = blockIdx.y * 128;
    const int n0 = blockIdx.x * 128;

    const int sub = lane >> 3, rr = lane & 7;
    const int rowoff = ((sub & 1) << 3) + rr;
    const int koffb  = (sub >> 1) << 4;

    const uint32_t offA = (uint32_t)((wm*64 + rowoff) * (LDT*2) + koffb);
    const uint32_t offB = (uint32_t)((wn*32 + rowoff) * (LDT*2) + koffb);

    const int crow0 = tid >> 2, cvv = tid & 3;
    const __half* gsrc[4] = {
        Ahi + (size_t)m0 * K, Alo + (size_t)m0 * K,
        Bhi + (size_t)n0 * K, Blo + (size_t)n0 * K };

    float acc[4][4][4];
    uint32_t corr[4][4][2];
    #pragma unroll
    for (int i = 0; i < 4; i++)
        #pragma unroll
        for (int j = 0; j < 4; j++) {
            #pragma unroll
            for (int q = 0; q < 4; q++) acc[i][j][q] = 0.f;
            corr[i][j][0] = 0u; corr[i][j][1] = 0u;
        }

    const int nChunk = K / 32;

    auto issue = [&](int chunk, int stage) {
        const int kk = chunk * 32;
        const uint32_t stg = sb + (uint32_t)(stage * STAGE_B);
        #pragma unroll
        for (int t = 0; t < 4; t++) {
            #pragma unroll
            for (int it = 0; it < 2; it++) {
                int row = crow0 + it * 64;
                cp16(stg + (uint32_t)(t*TILE_B + row*(LDT*2) + cvv*16),
                     gsrc[t] + (size_t)row * K + kk + cvv*8);
            }
        }
    };

    issue(0, 0); CP_COMMIT();
    issue(1, 1); CP_COMMIT();

    for (int c = 0; c < nChunk; c++) {
        if (c + 1 < nChunk)
            asm volatile("cp.async.wait_group 1;" ::: "memory");
        else
            asm volatile("cp.async.wait_group 0;" ::: "memory");
        __syncthreads();

        if (c + 2 < nChunk) { issue(c + 2, (c + 2) % 3); CP_COMMIT(); }

        const uint32_t stg = (uint32_t)((c % 3) * STAGE_B);
        const uint32_t aHi = sb + stg + offA;
        const uint32_t aLo = aHi + TILE_B;
        const uint32_t bHi = sb + stg + 2*TILE_B + offB;
        const uint32_t bLo = bHi + TILE_B;

        #pragma unroll
        for (int ks = 0; ks < 2; ks++) {
            const uint32_t kb = (uint32_t)(ks * 32);
            uint32_t ah[4][4], bh[2][4], bl[2][4];
            #pragma unroll
            for (int mt = 0; mt < 4; mt++) ldm_x4(ah[mt], aHi + mt * (16*LDT*2) + kb);
            ldm_x4(bh[0], bHi + kb);
            ldm_x4(bh[1], bHi + 16*LDT*2 + kb);
            ldm_x4(bl[0], bLo + kb);
            ldm_x4(bl[1], bLo + 16*LDT*2 + kb);

            #pragma unroll
            for (int mt = 0; mt < 4; mt++)
                #pragma unroll
                for (int nf = 0; nf < 4; nf++) {
                    const int nb = nf >> 1, sel = nf & 1;
                    mma_f32(acc[mt][nf], ah[mt], bh[nb][sel], bh[nb][2+sel]);
                    mma_f16(corr[mt][nf], ah[mt], bl[nb][sel], bl[nb][2+sel]);
                }

            uint32_t al[4][4];
            #pragma unroll
            for (int mt = 0; mt < 4; mt++) ldm_x4(al[mt], aLo + mt * (16*LDT*2) + kb);
            #pragma unroll
            for (int mt = 0; mt < 4; mt++)
                #pragma unroll
                for (int nf = 0; nf < 4; nf++) {
                    const int nb = nf >> 1, sel = nf & 1;
                    mma_f16(corr[mt][nf], al[mt], bh[nb][sel], bh[nb][2+sel]);
                }
        }
    }

    const int g = lane >> 2, t = lane & 3;
    #pragma unroll
    for (int mt = 0; mt < 4; mt++) {
        const int row = m0 + wm*64 + mt*16 + g;
        #pragma unroll
        for (int nf = 0; nf < 4; nf++) {
            corr_merge(acc[mt][nf], corr[mt][nf]);
            const int col = n0 + wn*32 + nf*8 + t*2;
            const float b0 = bias[col], b1 = bias[col+1];
            float v00 = acc[mt][nf][0] + b0, v01 = acc[mt][nf][1] + b1;
            float v10 = acc[mt][nf][2] + b0, v11 = acc[mt][nf][3] + b1;
            if (Chi) {
                __half2 h0 = __floats2half2_rn(v00, v01);
                __half2 l0 = __floats2half2_rn(v00 - __low2float(h0), v01 - __high2float(h0));
                __half2 h1 = __floats2half2_rn(v10, v11);
                __half2 l1 = __floats2half2_rn(v10 - __low2float(h1), v11 - __high2float(h1));
                *(uint32_t*)(Chi + (size_t)row * N + col)       = *(const uint32_t*)&h0;
                *(uint32_t*)(Clo + (size_t)row * N + col)       = *(const uint32_t*)&l0;
                *(uint32_t*)(Chi + (size_t)(row + 8) * N + col) = *(const uint32_t*)&h1;
                *(uint32_t*)(Clo + (size_t)(row + 8) * N + col) = *(const uint32_t*)&l1;
            } else {
                float2 lo2 = { v00, v01 };
                float2 hi2 = { v10, v11 };
                *(float2*)(C + (size_t)row * N + col)       = lo2;
                *(float2*)(C + (size_t)(row + 8) * N + col) = hi2;
            }
        }
    }
}

// ---------------------------------------------------------------------------
// HMMA fused causal attention (R6 structure, fp16 + f16-acc corrections).
// ---------------------------------------------------------------------------
#define KST 72
#define VST 264

#define OFF_KV 131072
#define OFF_P  204800
#define OFF_Q  221696
#define SM_ATT 226304

__global__ __launch_bounds__(512)
void attn_hmma(const __half* __restrict__ qhi, const __half* __restrict__ qlo,
               const __half* __restrict__ khi, const __half* __restrict__ klo,
               const __half* __restrict__ vthi, const __half* __restrict__ vtlo,
               float* __restrict__ attnw,
               __half* __restrict__ aohi, __half* __restrict__ aolo)
{
    extern __shared__ char smb[];
    float* rows = (float*)smb;
    __half* Khi = (__half*)(smb + OFF_KV);
    __half* Klo = Khi + 256*KST;
    __half* VThi = (__half*)(smb + OFF_KV);
    __half* VTlo = VThi + 64*VST;
    __half* Phi = (__half*)(smb + OFF_P);
    __half* Plo = Phi + 16*VST;
    __half* Qhi = (__half*)(smb + OFF_Q);
    __half* Qlo = Qhi + 16*KST;
    float* pbuf = (float*)(smb + OFF_Q);

    const int qt = blockIdx.x, h = blockIdx.y, b = blockIdx.z;
    const int q0 = qt * TQ;
    const int tid  = threadIdx.x;
    const int lane = tid & 31;
    const int wid  = tid >> 5;
    const int nk   = q0 + TQ;
    const int nChunk = (nk + KCA - 1) / KCA;
    const int nkc = nChunk * KCA;
    const float scale = 0.125f;

    const int sub = lane >> 3, rr = lane & 7;
    const int arow = ((sub & 1) << 3) + rr;
    const int akoff = (sub >> 1) << 4;

    {
        const size_t qgb = ((size_t)(b*S_ + q0)) * D_ + h*HD_;
        for (int i = tid; i < 256; i += 512) {
            int which = i >> 7, u = i & 127;
            int token = u >> 3, seg = u & 7;
            const __half* src = (which ? qlo : qhi) + qgb + (size_t)token * D_ + seg*8;
            __half* dst = (which ? Qlo : Qhi) + token*KST + seg*8;
            *(uint4*)dst = *(const uint4*)src;
        }
    }
    __syncthreads();

    uint32_t qfh[4][4], qfl[4][4];
    {
        const uint32_t qa_hi = smem_u32(Qhi) + (uint32_t)(arow*(KST*2) + akoff);
        const uint32_t qa_lo = smem_u32(Qlo) + (uint32_t)(arow*(KST*2) + akoff);
        #pragma unroll
        for (int ks = 0; ks < 4; ks++) {
            ldm_x4(qfh[ks], qa_hi + ks*32);
            ldm_x4(qfl[ks], qa_lo + ks*32);
        }
    }

    const uint32_t kB_hi = smem_u32(Khi) + (uint32_t)((wid*16 + arow)*(KST*2) + akoff);
    const uint32_t kB_lo = smem_u32(Klo) + (uint32_t)((wid*16 + arow)*(KST*2) + akoff);
    const int gq = lane >> 2, t2 = (lane & 3) << 1;
    const size_t kgb = ((size_t)b*S_) * D_ + h*HD_;

    for (int c = 0; c < nChunk; c++) {
        const int k0c = c * KCA;
        __syncthreads();
        #pragma unroll
        for (int it = 0; it < 8; it++) {
            int u = tid + it * 512;
            int which = u >> 11, uu = u & 2047;
            int token = uu >> 3, seg = uu & 7;
            const __half* src = (which ? klo : khi) + kgb
                + (size_t)(k0c + token) * D_ + seg*8;
            __half* dst = (which ? Klo : Khi) + token*KST + seg*8;
            *(uint4*)dst = *(const uint4*)src;
        }
        __syncthreads();

        float sc[2][4];
        uint32_t scc[2][2];
        #pragma unroll
        for (int ns = 0; ns < 2; ns++) {
            #pragma unroll
            for (int j = 0; j < 4; j++) sc[ns][j] = 0.f;
            scc[ns][0] = 0u; scc[ns][1] = 0u;
        }

        #pragma unroll
        for (int ks = 0; ks < 4; ks++) {
            uint32_t kh[4], kl[4];
            ldm_x4(kh, kB_hi + ks*32);
            ldm_x4(kl, kB_lo + ks*32);
            #pragma unroll
            for (int ns = 0; ns < 2; ns++) {
                mma_f32(sc[ns], qfh[ks], kh[ns], kh[2+ns]);
                mma_f16(scc[ns], qfh[ks], kl[ns], kl[2+ns]);
                mma_f16(scc[ns], qfl[ks], kh[ns], kh[2+ns]);
            }
        }

        #pragma unroll
        for (int ns = 0; ns < 2; ns++) {
            corr_merge(sc[ns], scc[ns]);
            const int kg = k0c + wid*16 + ns*8 + t2;
            rows[(size_t)gq*S_ + kg]      = (kg   <= q0+gq) ? sc[ns][0]*scale : -INFINITY;
            rows[(size_t)gq*S_ + kg+1]    = (kg+1 <= q0+gq) ? sc[ns][1]*scale : -INFINITY;
            rows[(size_t)(gq+8)*S_ + kg]  = (kg   <= q0+gq+8) ? sc[ns][2]*scale : -INFINITY;
            rows[(size_t)(gq+8)*S_ + kg+1]= (kg+1 <= q0+gq+8) ? sc[ns][3]*scale : -INFINITY;
        }
    }
    __syncthreads();

    {
        const int r = wid;
        float* prow = rows + (size_t)r * S_;
        float m = -INFINITY;
        for (int i = lane; i < nkc; i += 32) m = fmaxf(m, prow[i]);
        #pragma unroll
        for (int off = 16; off; off >>= 1) m = fmaxf(m, __shfl_xor_sync(0xffffffffu, m, off));
        float s = 0.f;
        for (int i = lane; i < nkc; i += 32) {
            float e = __expf(prow[i] - m);
            prow[i] = e;
            s += e;
        }
        #pragma unroll
        for (int off = 16; off; off >>= 1) s += __shfl_xor_sync(0xffffffffu, s, off);
        float inv = 1.f / s;
        for (int i = lane; i < nkc; i += 32) prow[i] *= inv;
    }
    __syncthreads();

    {
        size_t abase = (((size_t)b * H_ + h) * S_ + q0) * (size_t)S_;
        for (int i = tid; i < TQ * S_; i += 512) {
            int r   = i >> 11;
            int col = i & (S_ - 1);
            float v = 0.f;
            if (col <= q0 + r) v = rows[(size_t)r * S_ + col];
            attnw[abase + (size_t)r * S_ + col] = v;
        }
    }

    const int khalf = wid >> 3, ntile = wid & 7;
    const uint32_t pA_hi = smem_u32(Phi) + (uint32_t)(arow*(VST*2) + akoff + khalf*256);
    const uint32_t pA_lo = smem_u32(Plo) + (uint32_t)(arow*(VST*2) + akoff + khalf*256);
    const uint32_t vB_hi = smem_u32(VThi) + (uint32_t)((ntile*8 + rr)*(VST*2)
                          + (((lane >> 3) & 1) << 4) + khalf*256);
    const uint32_t vB_lo = vB_hi + (uint32_t)(64*VST*2);
    const size_t vgb = ((size_t)(b*H_ + h)) * 64 * S_;

    float oc[4] = {0.f, 0.f, 0.f, 0.f};
    uint32_t occ[2] = {0u, 0u};
    for (int c = 0; c < nChunk; c++) {
        const int k0c = c * KCA;
        __syncthreads();
        #pragma unroll
        for (int it = 0; it < 8; it++) {
            int u = tid + it * 512;
            int which = u >> 11, uu = u & 2047;
            int d = uu >> 5, seg = uu & 31;
            const __half* src = (which ? vtlo : vthi) + vgb
                + (size_t)d * S_ + k0c + seg*8;
            __half* dst = (which ? VTlo : VThi) + d*VST + seg*8;
            *(uint4*)dst = *(const uint4*)src;
        }
        #pragma unroll
        for (int it = 0; it < 4; it++) {
            int p = tid + it * 512;
            int r = p >> 7, j2 = (p & 127) << 1;
            float v0 = rows[(size_t)r*S_ + k0c + j2];
            float v1 = rows[(size_t)r*S_ + k0c + j2 + 1];
            __half2 hb = __floats2half2_rn(v0, v1);
            __half2 lb = __floats2half2_rn(v0 - __low2float(hb), v1 - __high2float(hb));
            *(uint32_t*)(Phi + r*VST + j2) = *(const uint32_t*)&hb;
            *(uint32_t*)(Plo + r*VST + j2) = *(const uint32_t*)&lb;
        }
        __syncthreads();

        #pragma unroll
        for (int ks = 0; ks < 8; ks++) {
            uint32_t ph[4], pl[4], vh[2], vl[2];
            ldm_x4(ph, pA_hi + ks*32);
            ldm_x4(pl, pA_lo + ks*32);
            ldm_x2(vh, vB_hi + ks*32);
            ldm_x2(vl, vB_lo + ks*32);
            mma_f32(oc, ph, vh[0], vh[1]);
            mma_f16(occ, ph, vl[0], vl[1]);
            mma_f16(occ, pl, vh[0], vh[1]);
        }
    }
    corr_merge(oc, occ);

    __syncthreads();
    if (khalf == 1) {
        pbuf[gq*HD_ + ntile*8 + t2]       = oc[0];
        pbuf[gq*HD_ + ntile*8 + t2 + 1]   = oc[1];
        pbuf[(gq+8)*HD_ + ntile*8 + t2]   = oc[2];
        pbuf[(gq+8)*HD_ + ntile*8 + t2+1] = oc[3];
    }
    __syncthreads();
    if (khalf == 0) {
        const int col = h*HD_ + ntile*8 + t2;
        const size_t o0 = ((size_t)(b*S_ + q0 + gq)) * D_ + col;
        const size_t o1 = ((size_t)(b*S_ + q0 + gq + 8)) * D_ + col;
        float v00 = oc[0] + pbuf[gq*HD_ + ntile*8 + t2];
        float v01 = oc[1] + pbuf[gq*HD_ + ntile*8 + t2 + 1];
        float v10 = oc[2] + pbuf[(gq+8)*HD_ + ntile*8 + t2];
        float v11 = oc[3] + pbuf[(gq+8)*HD_ + ntile*8 + t2 + 1];
        __half2 h0 = __floats2half2_rn(v00, v01);
        __half2 l0 = __floats2half2_rn(v00 - __low2float(h0), v01 - __high2float(h0));
        __half2 h1 = __floats2half2_rn(v10, v11);
        __half2 l1 = __floats2half2_rn(v10 - __low2float(h1), v11 - __high2float(h1));
        *(uint32_t*)(aohi + o0) = *(const uint32_t*)&h0;
        *(uint32_t*)(aolo + o0) = *(const uint32_t*)&l0;
        *(uint32_t*)(aohi + o1) = *(const uint32_t*)&h1;
        *(uint32_t*)(aolo + o1) = *(const uint32_t*)&l1;
    }
}

// ---------------------------------------------------------------------------
extern "C" void kernel_launch(void* const* d_in, const int* in_sizes, int n_in,
                              void* d_out, int out_size)
{
    const float* x  = (const float*)d_in[0];
    const float* Wq = (const float*)d_in[1];
    const float* bq = (const float*)d_in[2];
    const float* Wk = (const float*)d_in[3];
    const float* bk = (const float*)d_in[4];
    const float* Wv = (const float*)d_in[5];
    const float* bv = (const float*)d_in[6];
    const float* Wo = (const float*)d_in[7];
    const float* bo = (const float*)d_in[8];

    float* out   = (float*)d_out;                       // [B,S,D]
    float* attnw = out + (size_t)B_ * S_ * D_;          // [B,H,S,S]

    float *q, *k, *v;
    __half *xhi, *xlo, *whi, *wlo, *aohi, *aolo;
    __half *qhi, *qlo, *khi, *klo, *vthi, *vtlo;
    cudaGetSymbolAddress((void**)&q,  g_q);
    cudaGetSymbolAddress((void**)&k,  g_k);
    cudaGetSymbolAddress((void**)&v,  g_v);
    cudaGetSymbolAddress((void**)&xhi, g_xhi);
    cudaGetSymbolAddress((void**)&xlo, g_xlo);
    cudaGetSymbolAddress((void**)&whi, g_whi);
    cudaGetSymbolAddress((void**)&wlo, g_wlo);
    cudaGetSymbolAddress((void**)&aohi, g_aohi);
    cudaGetSymbolAddress((void**)&aolo, g_aolo);
    cudaGetSymbolAddress((void**)&qhi, g_qhi);
    cudaGetSymbolAddress((void**)&qlo, g_qlo);
    cudaGetSymbolAddress((void**)&khi, g_khi);
    cudaGetSymbolAddress((void**)&klo, g_klo);
    cudaGetSymbolAddress((void**)&vthi, g_vthi);
    cudaGetSymbolAddress((void**)&vtlo, g_vtlo);

    const int M = MSZ;               // 4096
    const int WSZ = D_ * D_;         // 1048576
    const int NPX = M * D_ / 4;

    convert_split<<<(NPX + 255)/256, 256>>>((const float4*)x, (uint2*)xhi, (uint2*)xlo, NPX);
    const float* Ws[4] = { Wq, Wk, Wv, Wo };
    for (int i = 0; i < 4; i++)
        convert_split<<<(WSZ/4 + 255)/256, 256>>>((const float4*)Ws[i],
            (uint2*)(whi + (size_t)i*WSZ), (uint2*)(wlo + (size_t)i*WSZ), WSZ/4);

    cudaFuncSetAttribute(gemm_hmma, cudaFuncAttributeMaxDynamicSharedMemorySize, SM_GEMM);
    dim3 ggrid(D_ / 128, M / 128);   // (8, 32)

    gemm_hmma<<<ggrid, 256, SM_GEMM>>>(xhi, xlo, whi + 0*(size_t)WSZ, wlo + 0*(size_t)WSZ,
                                       bq, nullptr, qhi, qlo, M, D_, D_);
    gemm_hmma<<<ggrid, 256, SM_GEMM>>>(xhi, xlo, whi + 1*(size_t)WSZ, wlo + 1*(size_t)WSZ,
                                       bk, nullptr, khi, klo, M, D_, D_);
    gemm_hmma<<<ggrid, 256, SM_GEMM>>>(xhi, xlo, whi + 2*(size_t)WSZ, wlo + 2*(size_t)WSZ,
                                       bv, v, nullptr, nullptr, M, D_, D_);

    {
        dim3 tg(S_/32, D_/32, B_);
        transpose_split_v<<<tg, 256>>>(v, vthi, vtlo);
    }

    cudaFuncSetAttribute(attn_hmma, cudaFuncAttributeMaxDynamicSharedMemorySize, SM_ATT);
    dim3 attn_grid(S_ / TQ, H_, B_);
    attn_hmma<<<attn_grid, 512, SM_ATT>>>(qhi, qlo, khi, klo, vthi, vtlo, attnw, aohi, aolo);

    gemm_hmma<<<ggrid, 256, SM_GEMM>>>(aohi, aolo, whi + 3*(size_t)WSZ, wlo + 3*(size_t)WSZ,
                                       bo, out, nullptr, nullptr, M, D_, D_);
}

// round 9
// speedup vs baseline: 1.5238x; 1.5238x over previous
#include <cuda_runtime.h>
#include <cuda_fp16.h>
#include <math.h>
#include <stdint.h>

#define B_  2
#define S_  2048
#define D_  1024
#define H_  16
#define HD_ 64

#define TQ  16
#define KCA 256              // attention key-chunk

#define MSZ (B_*S_)          // 4096 rows
#define WSZ (D_*D_)

// ---------------------------------------------------------------------------
// Scratch (allocation-free rule: __device__ globals)
// ---------------------------------------------------------------------------
__device__ __half g_xhi [MSZ*D_];
__device__ __half g_whi [4*D_*D_];   // Wq, Wk, Wv, Wo stacked
__device__ __half g_wlo [4*D_*D_];
__device__ __half g_aohi[MSZ*D_];
__device__ __half g_qhi [MSZ*D_];
__device__ __half g_qlo [MSZ*D_];
__device__ __half g_khi [MSZ*D_];
__device__ __half g_vhi [MSZ*D_];    // v row-major fp16
__device__ __half g_vthi[MSZ*D_];    // [B][H][64][S]

// ---------------------------------------------------------------------------
// fp32 -> fp16 hi-only
// ---------------------------------------------------------------------------
__global__ __launch_bounds__(256)
void convert_hi(const float4* __restrict__ in, uint2* __restrict__ hi, int n4)
{
    int i = blockIdx.x * 256 + threadIdx.x;
    if (i >= n4) return;
    float4 v = in[i];
    __half2 h0 = __floats2half2_rn(v.x, v.y);
    __half2 h1 = __floats2half2_rn(v.z, v.w);
    uint2 H;
    H.x = *(const uint32_t*)&h0; H.y = *(const uint32_t*)&h1;
    hi[i] = H;
}

// all four weights, fp32 -> fp16 (hi, lo), one launch
__global__ __launch_bounds__(256)
void convert_w4(const float4* __restrict__ w0, const float4* __restrict__ w1,
                const float4* __restrict__ w2, const float4* __restrict__ w3,
                uint2* __restrict__ hi, uint2* __restrict__ lo)
{
    int i = blockIdx.x * 256 + threadIdx.x;      // 0 .. 4*WSZ/4-1
    int which = i >> 18;                         // WSZ/4 = 262144 = 2^18
    int j = i & 262143;
    const float4* src = (which == 0) ? w0 : (which == 1) ? w1 : (which == 2) ? w2 : w3;
    float4 v = src[j];
    __half2 h0 = __floats2half2_rn(v.x, v.y);
    __half2 h1 = __floats2half2_rn(v.z, v.w);
    __half2 l0 = __floats2half2_rn(v.x - __low2float(h0), v.y - __high2float(h0));
    __half2 l1 = __floats2half2_rn(v.z - __low2float(h1), v.w - __high2float(h1));
    uint2 H, L;
    H.x = *(const uint32_t*)&h0; H.y = *(const uint32_t*)&h1;
    L.x = *(const uint32_t*)&l0; L.y = *(const uint32_t*)&l1;
    hi[i] = H; lo[i] = L;
}

// ---------------------------------------------------------------------------
// V fp16 [b, s, d] -> VT fp16 [b, h, d(64), s]
// ---------------------------------------------------------------------------
__global__ __launch_bounds__(256)
void transpose_v(const __half* __restrict__ v, __half* __restrict__ vt)
{
    __shared__ __half tile[32][34];
    const int s0 = blockIdx.x * 32, d0 = blockIdx.y * 32, b = blockIdx.z;
    const int c = threadIdx.x & 31, r4 = threadIdx.x >> 5;
    #pragma unroll
    for (int i = 0; i < 4; i++) {
        int r = r4 + i * 8;
        tile[r][c] = v[(size_t)(b*S_ + s0 + r) * D_ + d0 + c];
    }
    __syncthreads();
    #pragma unroll
    for (int i = 0; i < 4; i++) {
        int d = d0 + r4 + i * 8;
        int s = s0 + c;
        vt[((size_t)(b*H_ + (d >> 6)) * 64 + (d & 63)) * S_ + s] = tile[c][r4 + i*8];
    }
}

// ---------------------------------------------------------------------------
// PTX helpers (non-variant ISA)
// ---------------------------------------------------------------------------
__device__ __forceinline__ uint32_t smem_u32(const void* p) {
    uint32_t a;
    asm("{ .reg .u64 t; cvta.to.shared.u64 t, %1; cvt.u32.u64 %0, t; }" : "=r"(a) : "l"(p));
    return a;
}
__device__ __forceinline__ void ldm_x4(uint32_t* r, uint32_t addr) {
    asm volatile("ldmatrix.sync.aligned.m8n8.x4.shared.b16 {%0,%1,%2,%3}, [%4];"
        : "=r"(r[0]), "=r"(r[1]), "=r"(r[2]), "=r"(r[3]) : "r"(addr));
}
__device__ __forceinline__ void ldm_x2(uint32_t* r, uint32_t addr) {
    asm volatile("ldmatrix.sync.aligned.m8n8.x2.shared.b16 {%0,%1}, [%2];"
        : "=r"(r[0]), "=r"(r[1]) : "r"(addr));
}
__device__ __forceinline__ void mma_f32(float* c, const uint32_t* a,
                                        uint32_t b0, uint32_t b1) {
    asm volatile(
        "mma.sync.aligned.m16n8k16.row.col.f32.f16.f16.f32 "
        "{%0,%1,%2,%3}, {%4,%5,%6,%7}, {%8,%9}, {%0,%1,%2,%3};"
        : "+f"(c[0]), "+f"(c[1]), "+f"(c[2]), "+f"(c[3])
        : "r"(a[0]), "r"(a[1]), "r"(a[2]), "r"(a[3]), "r"(b0), "r"(b1));
}
__device__ __forceinline__ void cp16(uint32_t dst, const void* src) {
    asm volatile("cp.async.cg.shared.global [%0], [%1], 16;" :: "r"(dst), "l"(src));
}
#define CP_COMMIT() asm volatile("cp.async.commit_group;" ::: "memory")
#define CP_WAIT0()  asm volatile("cp.async.wait_group 0;" ::: "memory")

// ---------------------------------------------------------------------------
// HMMA GEMM, 2-term fp16 split: C = (A) @ (Whi + Wlo)^T + bias, f32 accum.
// A is single fp16. 128x128 tile, K-chunks of 32, 2-stage cp.async, 2 CTA/SM.
// Output modes: Cf32 != null -> fp32 C. Else segmented (fused QKV):
//   seg0 -> oQhi/oQlo (hi/lo split), seg1 -> oKhi, seg2 -> oVhi.
// ---------------------------------------------------------------------------
#define LDT 40
#define TILE_B   (128*LDT*2)         // 10240 bytes
#define STAGE_B  (3*TILE_B)          // 30720 bytes
#define SM_GEMM  (2*STAGE_B)         // 61440 bytes

__global__ __launch_bounds__(256, 2)
void gemm2(const __half* __restrict__ A,
           const __half* __restrict__ Bhi, const __half* __restrict__ Blo,
           const float* __restrict__ bs0, const float* __restrict__ bs1,
           const float* __restrict__ bs2,
           float* __restrict__ Cf32,
           __half* __restrict__ oQhi, __half* __restrict__ oQlo,
           __half* __restrict__ oKhi, __half* __restrict__ oVhi,
           int M, int N, int K)
{
    extern __shared__ __half dsm[];
    const uint32_t sb = smem_u32(dsm);

    const int tid = threadIdx.x;
    const int lane = tid & 31;
    const int wid  = tid >> 5;
    const int wm = wid & 1;
    const int wn = wid >> 1;
    const int m0 = blockIdx.y * 128;
    const int n0 = blockIdx.x * 128;

    const int sub = lane >> 3, rr = lane & 7;
    const int rowoff = ((sub & 1) << 3) + rr;
    const int koffb  = (sub >> 1) << 4;

    const uint32_t offA = (uint32_t)((wm*64 + rowoff) * 80 + koffb);
    const uint32_t offB = (uint32_t)((wn*32 + rowoff) * 80 + koffb);

    const int crow0 = tid >> 2, cvv = tid & 3;
    const __half* gsrc[3] = {
        A + (size_t)m0 * K, Bhi + (size_t)n0 * K, Blo + (size_t)n0 * K };

    float acc[4][4][4];
    #pragma unroll
    for (int i = 0; i < 4; i++)
        #pragma unroll
        for (int j = 0; j < 4; j++)
            #pragma unroll
            for (int q = 0; q < 4; q++) acc[i][j][q] = 0.f;

    const int nChunk = K / 32;

    // prologue: chunk 0 -> stage 0
    #pragma unroll
    for (int t = 0; t < 3; t++)
        #pragma unroll
        for (int it = 0; it < 2; it++) {
            int row = crow0 + it * 64;
            cp16(sb + (uint32_t)(t*TILE_B + row*80 + cvv*16),
                 gsrc[t] + (size_t)row * K + cvv*8);
        }
    CP_COMMIT();

    for (int c = 0; c < nChunk; c++) {
        CP_WAIT0();
        __syncthreads();

        if (c + 1 < nChunk) {
            const int k1 = (c + 1) * 32;
            const uint32_t stg = (uint32_t)(((c + 1) & 1) * STAGE_B);
            #pragma unroll
            for (int t = 0; t < 3; t++)
                #pragma unroll
                for (int it = 0; it < 2; it++) {
                    int row = crow0 + it * 64;
                    cp16(sb + stg + (uint32_t)(t*TILE_B + row*80 + cvv*16),
                         gsrc[t] + (size_t)row * K + k1 + cvv*8);
                }
            CP_COMMIT();
        }

        const uint32_t stg = (uint32_t)((c & 1) * STAGE_B);
        const uint32_t aBase = sb + stg + offA;
        const uint32_t bHi = sb + stg + TILE_B + offB;
        const uint32_t bLo = bHi + TILE_B;

        #pragma unroll
        for (int ks = 0; ks < 2; ks++) {
            const uint32_t kb = (uint32_t)(ks * 32);
            uint32_t ah[4][4], bh[2][4], bl[2][4];
            #pragma unroll
            for (int mt = 0; mt < 4; mt++) ldm_x4(ah[mt], aBase + mt * (16*80) + kb);
            ldm_x4(bh[0], bHi + kb);
            ldm_x4(bh[1], bHi + 16*80 + kb);
            ldm_x4(bl[0], bLo + kb);
            ldm_x4(bl[1], bLo + 16*80 + kb);

            #pragma unroll
            for (int mt = 0; mt < 4; mt++)
                #pragma unroll
                for (int nf = 0; nf < 4; nf++) {
                    const int nb = nf >> 1, sel = nf & 1;
                    mma_f32(acc[mt][nf], ah[mt], bh[nb][sel], bh[nb][2+sel]);
                    mma_f32(acc[mt][nf], ah[mt], bl[nb][sel], bl[nb][2+sel]);
                }
        }
    }

    const int g = lane >> 2, t = lane & 3;
    #pragma unroll
    for (int mt = 0; mt < 4; mt++) {
        const int row = m0 + wm*64 + mt*16 + g;
        #pragma unroll
        for (int nf = 0; nf < 4; nf++) {
            const int colg = n0 + wn*32 + nf*8 + t*2;
            if (Cf32) {
                const float b0 = bs0[colg], b1 = bs0[colg+1];
                float2 lo2 = { acc[mt][nf][0] + b0, acc[mt][nf][1] + b1 };
                float2 hi2 = { acc[mt][nf][2] + b0, acc[mt][nf][3] + b1 };
                *(float2*)(Cf32 + (size_t)row * N + colg)       = lo2;
                *(float2*)(Cf32 + (size_t)(row + 8) * N + colg) = hi2;
            } else {
                const int seg = colg >> 10;
                const int col = colg & 1023;
                const float* bp = (seg == 0) ? bs0 : (seg == 1) ? bs1 : bs2;
                const float b0 = bp[col], b1 = bp[col+1];
                float v00 = acc[mt][nf][0] + b0, v01 = acc[mt][nf][1] + b1;
                float v10 = acc[mt][nf][2] + b0, v11 = acc[mt][nf][3] + b1;
                __half2 h0 = __floats2half2_rn(v00, v01);
                __half2 h1 = __floats2half2_rn(v10, v11);
                const size_t o0 = (size_t)row * D_ + col;
                const size_t o1 = (size_t)(row + 8) * D_ + col;
                if (seg == 0) {
                    __half2 l0 = __floats2half2_rn(v00 - __low2float(h0), v01 - __high2float(h0));
                    __half2 l1 = __floats2half2_rn(v10 - __low2float(h1), v11 - __high2float(h1));
                    *(uint32_t*)(oQhi + o0) = *(const uint32_t*)&h0;
                    *(uint32_t*)(oQlo + o0) = *(const uint32_t*)&l0;
                    *(uint32_t*)(oQhi + o1) = *(const uint32_t*)&h1;
                    *(uint32_t*)(oQlo + o1) = *(const uint32_t*)&l1;
                } else if (seg == 1) {
                    *(uint32_t*)(oKhi + o0) = *(const uint32_t*)&h0;
                    *(uint32_t*)(oKhi + o1) = *(const uint32_t*)&h1;
                } else {
                    *(uint32_t*)(oVhi + o0) = *(const uint32_t*)&h0;
                    *(uint32_t*)(oVhi + o1) = *(const uint32_t*)&h1;
                }
            }
        }
    }
}

// ---------------------------------------------------------------------------
// HMMA fused causal attention, 2-term: (Qhi+Qlo)*Khi, (Phi+Plo)*VThi.
// cp.async double-buffered K / VT chunk loads. 512 threads.
// smem: rows[16][2048] f32 | KV dbuf 2x36864 | Phi/Plo [16][264] | Qhi/Qlo
// ---------------------------------------------------------------------------
#define KST 72     // 144 B rows
#define VST 264    // 528 B rows
#define OFF_KV 131072
#define KVBUF  36864
#define OFF_P  204800
#define OFF_Q  221696
#define SM_ATT 226304

__global__ __launch_bounds__(512)
void attn_hmma(const __half* __restrict__ qhi, const __half* __restrict__ qlo,
               const __half* __restrict__ khi, const __half* __restrict__ vthi,
               float* __restrict__ attnw, __half* __restrict__ aohi)
{
    extern __shared__ char smb[];
    const uint32_t sbm = smem_u32(smb);
    float* rows = (float*)smb;
    __half* Phi = (__half*)(smb + OFF_P);
    __half* Plo = Phi + 16*VST;
    __half* Qhi = (__half*)(smb + OFF_Q);
    __half* Qlo = Qhi + 16*KST;
    float* pbuf = (float*)(smb + OFF_Q);      // reused after phase 1

    const int qt = blockIdx.x, h = blockIdx.y, b = blockIdx.z;
    const int q0 = qt * TQ;
    const int tid  = threadIdx.x;
    const int lane = tid & 31;
    const int wid  = tid >> 5;
    const int nk   = q0 + TQ;
    const int nChunk = (nk + KCA - 1) / KCA;
    const int nkc = nChunk * KCA;
    const float scale = 0.125f;

    const int sub = lane >> 3, rr = lane & 7;
    const int arow = ((sub & 1) << 3) + rr;
    const int akoff = (sub >> 1) << 4;

    // ---- Q tile (hi/lo) ----
    {
        const size_t qgb = ((size_t)(b*S_ + q0)) * D_ + h*HD_;
        for (int i = tid; i < 256; i += 512) {
            int which = i >> 7, u = i & 127;
            int token = u >> 3, seg = u & 7;
            const __half* src = (which ? qlo : qhi) + qgb + (size_t)token * D_ + seg*8;
            __half* dst = (which ? Qlo : Qhi) + token*KST + seg*8;
            *(uint4*)dst = *(const uint4*)src;
        }
    }
    __syncthreads();

    uint32_t qfh[4][4], qfl[4][4];
    {
        const uint32_t qa_hi = smem_u32(Qhi) + (uint32_t)(arow*144 + akoff);
        const uint32_t qa_lo = smem_u32(Qlo) + (uint32_t)(arow*144 + akoff);
        #pragma unroll
        for (int ks = 0; ks < 4; ks++) {
            ldm_x4(qfh[ks], qa_hi + ks*32);
            ldm_x4(qfl[ks], qa_lo + ks*32);
        }
    }

    const int gq = lane >> 2, t2 = (lane & 3) << 1;
    const size_t kgb = ((size_t)b*S_) * D_ + h*HD_;

    // ---- Phase 1: scores, cp.async double-buffered K ----
    {
        #pragma unroll
        for (int it = 0; it < 4; it++) {            // chunk 0 -> buf 0
            int u = tid + it * 512;
            int token = u >> 3, seg = u & 7;
            cp16(sbm + OFF_KV + (uint32_t)(token*144 + seg*16),
                 khi + kgb + (size_t)token * D_ + seg*8);
        }
        CP_COMMIT();
    }

    for (int c = 0; c < nChunk; c++) {
        CP_WAIT0();
        __syncthreads();

        if (c + 1 < nChunk) {
            const int k1 = (c + 1) * KCA;
            const uint32_t dstb = sbm + OFF_KV + (uint32_t)(((c + 1) & 1) * KVBUF);
            #pragma unroll
            for (int it = 0; it < 4; it++) {
                int u = tid + it * 512;
                int token = u >> 3, seg = u & 7;
                cp16(dstb + (uint32_t)(token*144 + seg*16),
                     khi + kgb + (size_t)(k1 + token) * D_ + seg*8);
            }
            CP_COMMIT();
        }

        const uint32_t kbase = sbm + OFF_KV + (uint32_t)((c & 1) * KVBUF)
                             + (uint32_t)((wid*16 + arow)*144 + akoff);
        float sc[2][4];
        #pragma unroll
        for (int ns = 0; ns < 2; ns++)
            #pragma unroll
            for (int j = 0; j < 4; j++) sc[ns][j] = 0.f;

        #pragma unroll
        for (int ks = 0; ks < 4; ks++) {
            uint32_t kh[4];
            ldm_x4(kh, kbase + ks*32);
            #pragma unroll
            for (int ns = 0; ns < 2; ns++) {
                mma_f32(sc[ns], qfh[ks], kh[ns], kh[2+ns]);
                mma_f32(sc[ns], qfl[ks], kh[ns], kh[2+ns]);
            }
        }

        const int k0c = c * KCA;
        #pragma unroll
        for (int ns = 0; ns < 2; ns++) {
            const int kg = k0c + wid*16 + ns*8 + t2;
            rows[(size_t)gq*S_ + kg]      = (kg   <= q0+gq) ? sc[ns][0]*scale : -INFINITY;
            rows[(size_t)gq*S_ + kg+1]    = (kg+1 <= q0+gq) ? sc[ns][1]*scale : -INFINITY;
            rows[(size_t)(gq+8)*S_ + kg]  = (kg   <= q0+gq+8) ? sc[ns][2]*scale : -INFINITY;
            rows[(size_t)(gq+8)*S_ + kg+1]= (kg+1 <= q0+gq+8) ? sc[ns][3]*scale : -INFINITY;
        }
    }
    __syncthreads();

    // ---- Phase 2: exact softmax, one warp per row ----
    {
        const int r = wid;
        float* prow = rows + (size_t)r * S_;
        float m = -INFINITY;
        for (int i = lane; i < nkc; i += 32) m = fmaxf(m, prow[i]);
        #pragma unroll
        for (int off = 16; off; off >>= 1) m = fmaxf(m, __shfl_xor_sync(0xffffffffu, m, off));
        float s = 0.f;
        for (int i = lane; i < nkc; i += 32) {
            float e = __expf(prow[i] - m);
            prow[i] = e;
            s += e;
        }
        #pragma unroll
        for (int off = 16; off; off >>= 1) s += __shfl_xor_sync(0xffffffffu, s, off);
        float inv = 1.f / s;
        for (int i = lane; i < nkc; i += 32) prow[i] *= inv;
    }
    __syncthreads();

    // ---- Phase 3: write normalized attn_weights ----
    {
        size_t abase = (((size_t)b * H_ + h) * S_ + q0) * (size_t)S_;
        for (int i = tid; i < TQ * S_; i += 512) {
            int r   = i >> 11;
            int col = i & (S_ - 1);
            float v = 0.f;
            if (col <= q0 + r) v = rows[(size_t)r * S_ + col];
            attnw[abase + (size_t)r * S_ + col] = v;
        }
    }

    // ---- Phase 4: AV, cp.async double-buffered VT ----
    const int khalf = wid >> 3, ntile = wid & 7;
    const uint32_t pA_hi = smem_u32(Phi) + (uint32_t)(arow*528 + akoff + khalf*256);
    const uint32_t pA_lo = smem_u32(Plo) + (uint32_t)(arow*528 + akoff + khalf*256);
    const size_t vgb = ((size_t)(b*H_ + h)) * 64 * S_;

    {
        #pragma unroll
        for (int it = 0; it < 4; it++) {            // chunk 0 -> buf 0
            int u = tid + it * 512;
            int d = u >> 5, seg = u & 31;
            cp16(sbm + OFF_KV + (uint32_t)(d*528 + seg*16),
                 vthi + vgb + (size_t)d * S_ + seg*8);
        }
        CP_COMMIT();
    }

    float oc[4] = {0.f, 0.f, 0.f, 0.f};
    for (int c = 0; c < nChunk; c++) {
        CP_WAIT0();
        __syncthreads();

        if (c + 1 < nChunk) {
            const int k1 = (c + 1) * KCA;
            const uint32_t dstb = sbm + OFF_KV + (uint32_t)(((c + 1) & 1) * KVBUF);
            #pragma unroll
            for (int it = 0; it < 4; it++) {
                int u = tid + it * 512;
                int d = u >> 5, seg = u & 31;
                cp16(dstb + (uint32_t)(d*528 + seg*16),
                     vthi + vgb + (size_t)d * S_ + k1 + seg*8);
            }
            CP_COMMIT();
        }

        const int k0c = c * KCA;
        // convert P chunk fp32 -> fp16 hi/lo
        #pragma unroll
        for (int it = 0; it < 4; it++) {
            int p = tid + it * 512;
            int r = p >> 7, j2 = (p & 127) << 1;
            float v0 = rows[(size_t)r*S_ + k0c + j2];
            float v1 = rows[(size_t)r*S_ + k0c + j2 + 1];
            __half2 hb = __floats2half2_rn(v0, v1);
            __half2 lb = __floats2half2_rn(v0 - __low2float(hb), v1 - __high2float(hb));
            *(uint32_t*)(Phi + r*VST + j2) = *(const uint32_t*)&hb;
            *(uint32_t*)(Plo + r*VST + j2) = *(const uint32_t*)&lb;
        }
        __syncthreads();

        const uint32_t vbase = sbm + OFF_KV + (uint32_t)((c & 1) * KVBUF)
                             + (uint32_t)((ntile*8 + rr)*528
                             + (((lane >> 3) & 1) << 4) + khalf*256);
        #pragma unroll
        for (int ks = 0; ks < 8; ks++) {
            uint32_t ph[4], pl[4], vh[2];
            ldm_x4(ph, pA_hi + ks*32);
            ldm_x4(pl, pA_lo + ks*32);
            ldm_x2(vh, vbase + ks*32);
            mma_f32(oc, ph, vh[0], vh[1]);
            mma_f32(oc, pl, vh[0], vh[1]);
        }
    }

    // combine k-halves via pbuf
    __syncthreads();
    if (khalf == 1) {
        pbuf[gq*HD_ + ntile*8 + t2]       = oc[0];
        pbuf[gq*HD_ + ntile*8 + t2 + 1]   = oc[1];
        pbuf[(gq+8)*HD_ + ntile*8 + t2]   = oc[2];
        pbuf[(gq+8)*HD_ + ntile*8 + t2+1] = oc[3];
    }
    __syncthreads();
    if (khalf == 0) {
        const int col = h*HD_ + ntile*8 + t2;
        const size_t o0 = ((size_t)(b*S_ + q0 + gq)) * D_ + col;
        const size_t o1 = ((size_t)(b*S_ + q0 + gq + 8)) * D_ + col;
        float v00 = oc[0] + pbuf[gq*HD_ + ntile*8 + t2];
        float v01 = oc[1] + pbuf[gq*HD_ + ntile*8 + t2 + 1];
        float v10 = oc[2] + pbuf[(gq+8)*HD_ + ntile*8 + t2];
        float v11 = oc[3] + pbuf[(gq+8)*HD_ + ntile*8 + t2 + 1];
        __half2 h0 = __floats2half2_rn(v00, v01);
        __half2 h1 = __floats2half2_rn(v10, v11);
        *(uint32_t*)(aohi + o0) = *(const uint32_t*)&h0;
        *(uint32_t*)(aohi + o1) = *(const uint32_t*)&h1;
    }
}

// ---------------------------------------------------------------------------
extern "C" void kernel_launch(void* const* d_in, const int* in_sizes, int n_in,
                              void* d_out, int out_size)
{
    const float* x  = (const float*)d_in[0];
    const float* Wq = (const float*)d_in[1];
    const float* bq = (const float*)d_in[2];
    const float* Wk = (const float*)d_in[3];
    const float* bk = (const float*)d_in[4];
    const float* Wv = (const float*)d_in[5];
    const float* bv = (const float*)d_in[6];
    const float* Wo = (const float*)d_in[7];
    const float* bo = (const float*)d_in[8];

    float* out   = (float*)d_out;                       // [B,S,D]
    float* attnw = out + (size_t)B_ * S_ * D_;          // [B,H,S,S]

    __half *xhi, *whi, *wlo, *aohi, *qhi, *qlo, *khi, *vhi, *vthi;
    cudaGetSymbolAddress((void**)&xhi,  g_xhi);
    cudaGetSymbolAddress((void**)&whi,  g_whi);
    cudaGetSymbolAddress((void**)&wlo,  g_wlo);
    cudaGetSymbolAddress((void**)&aohi, g_aohi);
    cudaGetSymbolAddress((void**)&qhi,  g_qhi);
    cudaGetSymbolAddress((void**)&qlo,  g_qlo);
    cudaGetSymbolAddress((void**)&khi,  g_khi);
    cudaGetSymbolAddress((void**)&vhi,  g_vhi);
    cudaGetSymbolAddress((void**)&vthi, g_vthi);

    const int M = MSZ;               // 4096
    const int NPX = M * D_ / 4;

    convert_hi<<<(NPX + 255)/256, 256>>>((const float4*)x, (uint2*)xhi, NPX);
    convert_w4<<<(4*WSZ/4 + 255)/256, 256>>>(
        (const float4*)Wq, (const float4*)Wk, (const float4*)Wv, (const float4*)Wo,
        (uint2*)whi, (uint2*)wlo);

    cudaFuncSetAttribute(gemm2, cudaFuncAttributeMaxDynamicSharedMemorySize, SM_GEMM);

    // fused QKV: N = 3072 (Wq|Wk|Wv stacked in whi/wlo)
    {
        dim3 g(3072/128, M/128);     // (24, 32)
        gemm2<<<g, 256, SM_GEMM>>>(xhi, whi, wlo, bq, bk, bv,
                                   nullptr, qhi, qlo, khi, vhi, M, 3072, D_);
    }
    {
        dim3 tg(S_/32, D_/32, B_);
        transpose_v<<<tg, 256>>>(vhi, vthi);
    }

    cudaFuncSetAttribute(attn_hmma, cudaFuncAttributeMaxDynamicSharedMemorySize, SM_ATT);
    dim3 attn_grid(S_ / TQ, H_, B_);
    attn_hmma<<<attn_grid, 512, SM_ATT>>>(qhi, qlo, khi, vthi, attnw, aohi);

    // output projection
    {
        dim3 g(D_/128, M/128);       // (8, 32)
        gemm2<<<g, 256, SM_GEMM>>>(aohi, whi + 3*(size_t)WSZ, wlo + 3*(size_t)WSZ,
                                   bo, nullptr, nullptr, out,
                                   nullptr, nullptr, nullptr, nullptr, M, D_, D_);
    }
}

// round 10
// speedup vs baseline: 1.5338x; 1.0065x over previous
#include <cuda_runtime.h>
#include <cuda_fp16.h>
#include <math.h>
#include <stdint.h>

#define B_  2
#define S_  2048
#define D_  1024
#define H_  16
#define HD_ 64

#define TQ  16
#define KCA 256              // attention key-chunk

#define MSZ (B_*S_)          // 4096 rows
#define WSZ (D_*D_)

// ---------------------------------------------------------------------------
// Scratch (allocation-free rule: __device__ globals)
// ---------------------------------------------------------------------------
__device__ __half g_xhi [MSZ*D_];
__device__ __half g_whi [4*D_*D_];   // Wq, Wk, Wv, Wo stacked
__device__ __half g_wlo [4*D_*D_];
__device__ __half g_aohi[MSZ*D_];
__device__ __half g_qhi [MSZ*D_];
__device__ __half g_qlo [MSZ*D_];
__device__ __half g_khi [MSZ*D_];
__device__ __half g_vhi [MSZ*D_];    // v row-major fp16
__device__ __half g_vthi[MSZ*D_];    // [B][H][64][S]

// ---------------------------------------------------------------------------
// fp32 -> fp16 hi-only
// ---------------------------------------------------------------------------
__global__ __launch_bounds__(256)
void convert_hi(const float4* __restrict__ in, uint2* __restrict__ hi, int n4)
{
    int i = blockIdx.x * 256 + threadIdx.x;
    if (i >= n4) return;
    float4 v = in[i];
    __half2 h0 = __floats2half2_rn(v.x, v.y);
    __half2 h1 = __floats2half2_rn(v.z, v.w);
    uint2 H;
    H.x = *(const uint32_t*)&h0; H.y = *(const uint32_t*)&h1;
    hi[i] = H;
}

// all four weights, fp32 -> fp16 (hi, lo), one launch
__global__ __launch_bounds__(256)
void convert_w4(const float4* __restrict__ w0, const float4* __restrict__ w1,
                const float4* __restrict__ w2, const float4* __restrict__ w3,
                uint2* __restrict__ hi, uint2* __restrict__ lo)
{
    int i = blockIdx.x * 256 + threadIdx.x;      // 0 .. 4*WSZ/4-1
    int which = i >> 18;                         // WSZ/4 = 262144 = 2^18
    int j = i & 262143;
    const float4* src = (which == 0) ? w0 : (which == 1) ? w1 : (which == 2) ? w2 : w3;
    float4 v = src[j];
    __half2 h0 = __floats2half2_rn(v.x, v.y);
    __half2 h1 = __floats2half2_rn(v.z, v.w);
    __half2 l0 = __floats2half2_rn(v.x - __low2float(h0), v.y - __high2float(h0));
    __half2 l1 = __floats2half2_rn(v.z - __low2float(h1), v.w - __high2float(h1));
    uint2 H, L;
    H.x = *(const uint32_t*)&h0; H.y = *(const uint32_t*)&h1;
    L.x = *(const uint32_t*)&l0; L.y = *(const uint32_t*)&l1;
    hi[i] = H; lo[i] = L;
}

// ---------------------------------------------------------------------------
// V fp16 [b, s, d] -> VT fp16 [b, h, d(64), s]
// ---------------------------------------------------------------------------
__global__ __launch_bounds__(256)
void transpose_v(const __half* __restrict__ v, __half* __restrict__ vt)
{
    __shared__ __half tile[32][34];
    const int s0 = blockIdx.x * 32, d0 = blockIdx.y * 32, b = blockIdx.z;
    const int c = threadIdx.x & 31, r4 = threadIdx.x >> 5;
    #pragma unroll
    for (int i = 0; i < 4; i++) {
        int r = r4 + i * 8;
        tile[r][c] = v[(size_t)(b*S_ + s0 + r) * D_ + d0 + c];
    }
    __syncthreads();
    #pragma unroll
    for (int i = 0; i < 4; i++) {
        int d = d0 + r4 + i * 8;
        int s = s0 + c;
        vt[((size_t)(b*H_ + (d >> 6)) * 64 + (d & 63)) * S_ + s] = tile[c][r4 + i*8];
    }
}

// ---------------------------------------------------------------------------
// PTX helpers (non-variant ISA)
// ---------------------------------------------------------------------------
__device__ __forceinline__ uint32_t smem_u32(const void* p) {
    uint32_t a;
    asm("{ .reg .u64 t; cvta.to.shared.u64 t, %1; cvt.u32.u64 %0, t; }" : "=r"(a) : "l"(p));
    return a;
}
__device__ __forceinline__ void ldm_x4(uint32_t* r, uint32_t addr) {
    asm volatile("ldmatrix.sync.aligned.m8n8.x4.shared.b16 {%0,%1,%2,%3}, [%4];"
        : "=r"(r[0]), "=r"(r[1]), "=r"(r[2]), "=r"(r[3]) : "r"(addr));
}
__device__ __forceinline__ void ldm_x2(uint32_t* r, uint32_t addr) {
    asm volatile("ldmatrix.sync.aligned.m8n8.x2.shared.b16 {%0,%1}, [%2];"
        : "=r"(r[0]), "=r"(r[1]) : "r"(addr));
}
__device__ __forceinline__ void mma_f32(float* c, const uint32_t* a,
                                        uint32_t b0, uint32_t b1) {
    asm volatile(
        "mma.sync.aligned.m16n8k16.row.col.f32.f16.f16.f32 "
        "{%0,%1,%2,%3}, {%4,%5,%6,%7}, {%8,%9}, {%0,%1,%2,%3};"
        : "+f"(c[0]), "+f"(c[1]), "+f"(c[2]), "+f"(c[3])
        : "r"(a[0]), "r"(a[1]), "r"(a[2]), "r"(a[3]), "r"(b0), "r"(b1));
}
__device__ __forceinline__ void cp16(uint32_t dst, const void* src) {
    asm volatile("cp.async.cg.shared.global [%0], [%1], 16;" :: "r"(dst), "l"(src));
}
#define CP_COMMIT() asm volatile("cp.async.commit_group;" ::: "memory")
#define CP_WAIT0()  asm volatile("cp.async.wait_group 0;" ::: "memory")

// ---------------------------------------------------------------------------
// HMMA GEMM, 2-term fp16 split (bench-proven R9): C = A @ (Whi+Wlo)^T + bias.
// ---------------------------------------------------------------------------
#define LDT 40
#define TILE_B   (128*LDT*2)         // 10240 bytes
#define STAGE_B  (3*TILE_B)          // 30720 bytes
#define SM_GEMM  (2*STAGE_B)         // 61440 bytes

__global__ __launch_bounds__(256, 2)
void gemm2(const __half* __restrict__ A,
           const __half* __restrict__ Bhi, const __half* __restrict__ Blo,
           const float* __restrict__ bs0, const float* __restrict__ bs1,
           const float* __restrict__ bs2,
           float* __restrict__ Cf32,
           __half* __restrict__ oQhi, __half* __restrict__ oQlo,
           __half* __restrict__ oKhi, __half* __restrict__ oVhi,
           int M, int N, int K)
{
    extern __shared__ __half dsm[];
    const uint32_t sb = smem_u32(dsm);

    const int tid = threadIdx.x;
    const int lane = tid & 31;
    const int wid  = tid >> 5;
    const int wm = wid & 1;
    const int wn = wid >> 1;
    const int m0 = blockIdx.y * 128;
    const int n0 = blockIdx.x * 128;

    const int sub = lane >> 3, rr = lane & 7;
    const int rowoff = ((sub & 1) << 3) + rr;
    const int koffb  = (sub >> 1) << 4;

    const uint32_t offA = (uint32_t)((wm*64 + rowoff) * 80 + koffb);
    const uint32_t offB = (uint32_t)((wn*32 + rowoff) * 80 + koffb);

    const int crow0 = tid >> 2, cvv = tid & 3;
    const __half* gsrc[3] = {
        A + (size_t)m0 * K, Bhi + (size_t)n0 * K, Blo + (size_t)n0 * K };

    float acc[4][4][4];
    #pragma unroll
    for (int i = 0; i < 4; i++)
        #pragma unroll
        for (int j = 0; j < 4; j++)
            #pragma unroll
            for (int q = 0; q < 4; q++) acc[i][j][q] = 0.f;

    const int nChunk = K / 32;

    #pragma unroll
    for (int t = 0; t < 3; t++)
        #pragma unroll
        for (int it = 0; it < 2; it++) {
            int row = crow0 + it * 64;
            cp16(sb + (uint32_t)(t*TILE_B + row*80 + cvv*16),
                 gsrc[t] + (size_t)row * K + cvv*8);
        }
    CP_COMMIT();

    for (int c = 0; c < nChunk; c++) {
        CP_WAIT0();
        __syncthreads();

        if (c + 1 < nChunk) {
            const int k1 = (c + 1) * 32;
            const uint32_t stg = (uint32_t)(((c + 1) & 1) * STAGE_B);
            #pragma unroll
            for (int t = 0; t < 3; t++)
                #pragma unroll
                for (int it = 0; it < 2; it++) {
                    int row = crow0 + it * 64;
                    cp16(sb + stg + (uint32_t)(t*TILE_B + row*80 + cvv*16),
                         gsrc[t] + (size_t)row * K + k1 + cvv*8);
                }
            CP_COMMIT();
        }

        const uint32_t stg = (uint32_t)((c & 1) * STAGE_B);
        const uint32_t aBase = sb + stg + offA;
        const uint32_t bHi = sb + stg + TILE_B + offB;
        const uint32_t bLo = bHi + TILE_B;

        #pragma unroll
        for (int ks = 0; ks < 2; ks++) {
            const uint32_t kb = (uint32_t)(ks * 32);
            uint32_t ah[4][4], bh[2][4], bl[2][4];
            #pragma unroll
            for (int mt = 0; mt < 4; mt++) ldm_x4(ah[mt], aBase + mt * (16*80) + kb);
            ldm_x4(bh[0], bHi + kb);
            ldm_x4(bh[1], bHi + 16*80 + kb);
            ldm_x4(bl[0], bLo + kb);
            ldm_x4(bl[1], bLo + 16*80 + kb);

            #pragma unroll
            for (int mt = 0; mt < 4; mt++)
                #pragma unroll
                for (int nf = 0; nf < 4; nf++) {
                    const int nb = nf >> 1, sel = nf & 1;
                    mma_f32(acc[mt][nf], ah[mt], bh[nb][sel], bh[nb][2+sel]);
                    mma_f32(acc[mt][nf], ah[mt], bl[nb][sel], bl[nb][2+sel]);
                }
        }
    }

    const int g = lane >> 2, t = lane & 3;
    #pragma unroll
    for (int mt = 0; mt < 4; mt++) {
        const int row = m0 + wm*64 + mt*16 + g;
        #pragma unroll
        for (int nf = 0; nf < 4; nf++) {
            const int colg = n0 + wn*32 + nf*8 + t*2;
            if (Cf32) {
                const float b0 = bs0[colg], b1 = bs0[colg+1];
                float2 lo2 = { acc[mt][nf][0] + b0, acc[mt][nf][1] + b1 };
                float2 hi2 = { acc[mt][nf][2] + b0, acc[mt][nf][3] + b1 };
                *(float2*)(Cf32 + (size_t)row * N + colg)       = lo2;
                *(float2*)(Cf32 + (size_t)(row + 8) * N + colg) = hi2;
            } else {
                const int seg = colg >> 10;
                const int col = colg & 1023;
                const float* bp = (seg == 0) ? bs0 : (seg == 1) ? bs1 : bs2;
                const float b0 = bp[col], b1 = bp[col+1];
                float v00 = acc[mt][nf][0] + b0, v01 = acc[mt][nf][1] + b1;
                float v10 = acc[mt][nf][2] + b0, v11 = acc[mt][nf][3] + b1;
                __half2 h0 = __floats2half2_rn(v00, v01);
                __half2 h1 = __floats2half2_rn(v10, v11);
                const size_t o0 = (size_t)row * D_ + col;
                const size_t o1 = (size_t)(row + 8) * D_ + col;
                if (seg == 0) {
                    __half2 l0 = __floats2half2_rn(v00 - __low2float(h0), v01 - __high2float(h0));
                    __half2 l1 = __floats2half2_rn(v10 - __low2float(h1), v11 - __high2float(h1));
                    *(uint32_t*)(oQhi + o0) = *(const uint32_t*)&h0;
                    *(uint32_t*)(oQlo + o0) = *(const uint32_t*)&l0;
                    *(uint32_t*)(oQhi + o1) = *(const uint32_t*)&h1;
                    *(uint32_t*)(oQlo + o1) = *(const uint32_t*)&l1;
                } else if (seg == 1) {
                    *(uint32_t*)(oKhi + o0) = *(const uint32_t*)&h0;
                    *(uint32_t*)(oKhi + o1) = *(const uint32_t*)&h1;
                } else {
                    *(uint32_t*)(oVhi + o0) = *(const uint32_t*)&h0;
                    *(uint32_t*)(oVhi + o1) = *(const uint32_t*)&h1;
                }
            }
        }
    }
}

// ---------------------------------------------------------------------------
// HMMA fused causal attention, 2-term; attnw write fused into AV's P-convert;
// vectorized zero-fill beyond nkc; causal MMA skips. 512 threads.
// ---------------------------------------------------------------------------
#define KST 72     // 144 B rows
#define VST 264    // 528 B rows
#define OFF_KV 131072
#define KVBUF  36864
#define OFF_P  204800
#define OFF_Q  221696
#define SM_ATT 226304

__global__ __launch_bounds__(512)
void attn_hmma(const __half* __restrict__ qhi, const __half* __restrict__ qlo,
               const __half* __restrict__ khi, const __half* __restrict__ vthi,
               float* __restrict__ attnw, __half* __restrict__ aohi)
{
    extern __shared__ char smb[];
    const uint32_t sbm = smem_u32(smb);
    float* rows = (float*)smb;
    __half* Phi = (__half*)(smb + OFF_P);
    __half* Plo = Phi + 16*VST;
    __half* Qhi = (__half*)(smb + OFF_Q);
    __half* Qlo = Qhi + 16*KST;
    float* pbuf = (float*)(smb + OFF_Q);      // reused after phase 1

    const int qt = blockIdx.x, h = blockIdx.y, b = blockIdx.z;
    const int q0 = qt * TQ;
    const int tid  = threadIdx.x;
    const int lane = tid & 31;
    const int wid  = tid >> 5;
    const int nk   = q0 + TQ;
    const int nChunk = (nk + KCA - 1) / KCA;
    const int nkc = nChunk * KCA;
    const float scale = 0.125f;
    const size_t abase = (((size_t)b * H_ + h) * S_ + q0) * (size_t)S_;

    const int sub = lane >> 3, rr = lane & 7;
    const int arow = ((sub & 1) << 3) + rr;
    const int akoff = (sub >> 1) << 4;

    // ---- Q tile (hi/lo) ----
    {
        const size_t qgb = ((size_t)(b*S_ + q0)) * D_ + h*HD_;
        for (int i = tid; i < 256; i += 512) {
            int which = i >> 7, u = i & 127;
            int token = u >> 3, seg = u & 7;
            const __half* src = (which ? qlo : qhi) + qgb + (size_t)token * D_ + seg*8;
            __half* dst = (which ? Qlo : Qhi) + token*KST + seg*8;
            *(uint4*)dst = *(const uint4*)src;
        }
    }
    __syncthreads();

    uint32_t qfh[4][4], qfl[4][4];
    {
        const uint32_t qa_hi = smem_u32(Qhi) + (uint32_t)(arow*144 + akoff);
        const uint32_t qa_lo = smem_u32(Qlo) + (uint32_t)(arow*144 + akoff);
        #pragma unroll
        for (int ks = 0; ks < 4; ks++) {
            ldm_x4(qfh[ks], qa_hi + ks*32);
            ldm_x4(qfl[ks], qa_lo + ks*32);
        }
    }

    const int gq = lane >> 2, t2 = (lane & 3) << 1;
    const size_t kgb = ((size_t)b*S_) * D_ + h*HD_;

    // ---- Phase 1: scores, cp.async double-buffered K ----
    {
        #pragma unroll
        for (int it = 0; it < 4; it++) {            // chunk 0 -> buf 0
            int u = tid + it * 512;
            int token = u >> 3, seg = u & 7;
            cp16(sbm + OFF_KV + (uint32_t)(token*144 + seg*16),
                 khi + kgb + (size_t)token * D_ + seg*8);
        }
        CP_COMMIT();
    }

    for (int c = 0; c < nChunk; c++) {
        CP_WAIT0();
        __syncthreads();

        if (c + 1 < nChunk) {
            const int k1 = (c + 1) * KCA;
            const uint32_t dstb = sbm + OFF_KV + (uint32_t)(((c + 1) & 1) * KVBUF);
            #pragma unroll
            for (int it = 0; it < 4; it++) {
                int u = tid + it * 512;
                int token = u >> 3, seg = u & 7;
                cp16(dstb + (uint32_t)(token*144 + seg*16),
                     khi + kgb + (size_t)(k1 + token) * D_ + seg*8);
            }
            CP_COMMIT();
        }

        const int k0c = c * KCA;
        float sc[2][4];
        #pragma unroll
        for (int ns = 0; ns < 2; ns++)
            #pragma unroll
            for (int j = 0; j < 4; j++) sc[ns][j] = 0.f;

        if (k0c + wid*16 <= q0 + 15) {          // causal skip: any unmasked key?
            const uint32_t kbase = sbm + OFF_KV + (uint32_t)((c & 1) * KVBUF)
                                 + (uint32_t)((wid*16 + arow)*144 + akoff);
            #pragma unroll
            for (int ks = 0; ks < 4; ks++) {
                uint32_t kh[4];
                ldm_x4(kh, kbase + ks*32);
                #pragma unroll
                for (int ns = 0; ns < 2; ns++) {
                    mma_f32(sc[ns], qfh[ks], kh[ns], kh[2+ns]);
                    mma_f32(sc[ns], qfl[ks], kh[ns], kh[2+ns]);
                }
            }
        }

        #pragma unroll
        for (int ns = 0; ns < 2; ns++) {
            const int kg = k0c + wid*16 + ns*8 + t2;
            rows[(size_t)gq*S_ + kg]      = (kg   <= q0+gq) ? sc[ns][0]*scale : -INFINITY;
            rows[(size_t)gq*S_ + kg+1]    = (kg+1 <= q0+gq) ? sc[ns][1]*scale : -INFINITY;
            rows[(size_t)(gq+8)*S_ + kg]  = (kg   <= q0+gq+8) ? sc[ns][2]*scale : -INFINITY;
            rows[(size_t)(gq+8)*S_ + kg+1]= (kg+1 <= q0+gq+8) ? sc[ns][3]*scale : -INFINITY;
        }
    }
    __syncthreads();

    // ---- Phase 2: exact softmax, one warp per row ----
    {
        const int r = wid;
        float* prow = rows + (size_t)r * S_;
        float m = -INFINITY;
        for (int i = lane; i < nkc; i += 32) m = fmaxf(m, prow[i]);
        #pragma unroll
        for (int off = 16; off; off >>= 1) m = fmaxf(m, __shfl_xor_sync(0xffffffffu, m, off));
        float s = 0.f;
        for (int i = lane; i < nkc; i += 32) {
            float e = __expf(prow[i] - m);
            prow[i] = e;
            s += e;
        }
        #pragma unroll
        for (int off = 16; off; off >>= 1) s += __shfl_xor_sync(0xffffffffu, s, off);
        float inv = 1.f / s;
        for (int i = lane; i < nkc; i += 32) prow[i] *= inv;
    }

    // ---- zero-fill attnw cols [nkc, S) — warp w owns row w; overlaps ahead ----
    if (nkc < S_) {
        float* zrow = attnw + abase + (size_t)wid * S_;
        const float4 z4 = {0.f, 0.f, 0.f, 0.f};
        for (int j = nkc + lane*4; j < S_; j += 128)
            *(float4*)(zrow + j) = z4;
    }
    __syncthreads();

    // ---- Phase 4: AV with fused attnw write; cp.async double-buffered VT ----
    const int khalf = wid >> 3, ntile = wid & 7;
    const uint32_t pA_hi = smem_u32(Phi) + (uint32_t)(arow*528 + akoff + khalf*256);
    const uint32_t pA_lo = smem_u32(Plo) + (uint32_t)(arow*528 + akoff + khalf*256);
    const size_t vgb = ((size_t)(b*H_ + h)) * 64 * S_;

    {
        #pragma unroll
        for (int it = 0; it < 4; it++) {            // chunk 0 -> buf 0
            int u = tid + it * 512;
            int d = u >> 5, seg = u & 31;
            cp16(sbm + OFF_KV + (uint32_t)(d*528 + seg*16),
                 vthi + vgb + (size_t)d * S_ + seg*8);
        }
        CP_COMMIT();
    }

    float oc[4] = {0.f, 0.f, 0.f, 0.f};
    for (int c = 0; c < nChunk; c++) {
        CP_WAIT0();
        __syncthreads();

        if (c + 1 < nChunk) {
            const int k1 = (c + 1) * KCA;
            const uint32_t dstb = sbm + OFF_KV + (uint32_t)(((c + 1) & 1) * KVBUF);
            #pragma unroll
            for (int it = 0; it < 4; it++) {
                int u = tid + it * 512;
                int d = u >> 5, seg = u & 31;
                cp16(dstb + (uint32_t)(d*528 + seg*16),
                     vthi + vgb + (size_t)d * S_ + k1 + seg*8);
            }
            CP_COMMIT();
        }

        const int k0c = c * KCA;
        // fused: rows -> (attnw fp32 store) + (Phi/Plo fp16 convert)
        #pragma unroll
        for (int it = 0; it < 4; it++) {
            int p = tid + it * 512;
            int r = p >> 7, j2 = (p & 127) << 1;
            float v0 = rows[(size_t)r*S_ + k0c + j2];
            float v1 = rows[(size_t)r*S_ + k0c + j2 + 1];
            float2 w2 = { v0, v1 };
            *(float2*)(attnw + abase + (size_t)r*S_ + k0c + j2) = w2;
            __half2 hb = __floats2half2_rn(v0, v1);
            __half2 lb = __floats2half2_rn(v0 - __low2float(hb), v1 - __high2float(hb));
            *(uint32_t*)(Phi + r*VST + j2) = *(const uint32_t*)&hb;
            *(uint32_t*)(Plo + r*VST + j2) = *(const uint32_t*)&lb;
        }
        __syncthreads();

        if (k0c + khalf*128 < nk) {               // skip all-zero-P half-chunks
            const uint32_t vbase = sbm + OFF_KV + (uint32_t)((c & 1) * KVBUF)
                                 + (uint32_t)((ntile*8 + rr)*528
                                 + (((lane >> 3) & 1) << 4) + khalf*256);
            #pragma unroll
            for (int ks = 0; ks < 8; ks++) {
                uint32_t ph[4], pl[4], vh[2];
                ldm_x4(ph, pA_hi + ks*32);
                ldm_x4(pl, pA_lo + ks*32);
                ldm_x2(vh, vbase + ks*32);
                mma_f32(oc, ph, vh[0], vh[1]);
                mma_f32(oc, pl, vh[0], vh[1]);
            }
        }
    }

    // combine k-halves via pbuf
    __syncthreads();
    if (khalf == 1) {
        pbuf[gq*HD_ + ntile*8 + t2]       = oc[0];
        pbuf[gq*HD_ + ntile*8 + t2 + 1]   = oc[1];
        pbuf[(gq+8)*HD_ + ntile*8 + t2]   = oc[2];
        pbuf[(gq+8)*HD_ + ntile*8 + t2+1] = oc[3];
    }
    __syncthreads();
    if (khalf == 0) {
        const int col = h*HD_ + ntile*8 + t2;
        const size_t o0 = ((size_t)(b*S_ + q0 + gq)) * D_ + col;
        const size_t o1 = ((size_t)(b*S_ + q0 + gq + 8)) * D_ + col;
        float v00 = oc[0] + pbuf[gq*HD_ + ntile*8 + t2];
        float v01 = oc[1] + pbuf[gq*HD_ + ntile*8 + t2 + 1];
        float v10 = oc[2] + pbuf[(gq+8)*HD_ + ntile*8 + t2];
        float v11 = oc[3] + pbuf[(gq+8)*HD_ + ntile*8 + t2 + 1];
        __half2 h0 = __floats2half2_rn(v00, v01);
        __half2 h1 = __floats2half2_rn(v10, v11);
        *(uint32_t*)(aohi + o0) = *(const uint32_t*)&h0;
        *(uint32_t*)(aohi + o1) = *(const uint32_t*)&h1;
    }
}

// ---------------------------------------------------------------------------
extern "C" void kernel_launch(void* const* d_in, const int* in_sizes, int n_in,
                              void* d_out, int out_size)
{
    const float* x  = (const float*)d_in[0];
    const float* Wq = (const float*)d_in[1];
    const float* bq = (const float*)d_in[2];
    const float* Wk = (const float*)d_in[3];
    const float* bk = (const float*)d_in[4];
    const float* Wv = (const float*)d_in[5];
    const float* bv = (const float*)d_in[6];
    const float* Wo = (const float*)d_in[7];
    const float* bo = (const float*)d_in[8];

    float* out   = (float*)d_out;                       // [B,S,D]
    float* attnw = out + (size_t)B_ * S_ * D_;          // [B,H,S,S]

    __half *xhi, *whi, *wlo, *aohi, *qhi, *qlo, *khi, *vhi, *vthi;
    cudaGetSymbolAddress((void**)&xhi,  g_xhi);
    cudaGetSymbolAddress((void**)&whi,  g_whi);
    cudaGetSymbolAddress((void**)&wlo,  g_wlo);
    cudaGetSymbolAddress((void**)&aohi, g_aohi);
    cudaGetSymbolAddress((void**)&qhi,  g_qhi);
    cudaGetSymbolAddress((void**)&qlo,  g_qlo);
    cudaGetSymbolAddress((void**)&khi,  g_khi);
    cudaGetSymbolAddress((void**)&vhi,  g_vhi);
    cudaGetSymbolAddress((void**)&vthi, g_vthi);

    const int M = MSZ;               // 4096
    const int NPX = M * D_ / 4;

    convert_hi<<<(NPX + 255)/256, 256>>>((const float4*)x, (uint2*)xhi, NPX);
    convert_w4<<<(4*WSZ/4 + 255)/256, 256>>>(
        (const float4*)Wq, (const float4*)Wk, (const float4*)Wv, (const float4*)Wo,
        (uint2*)whi, (uint2*)wlo);

    cudaFuncSetAttribute(gemm2, cudaFuncAttributeMaxDynamicSharedMemorySize, SM_GEMM);

    // fused QKV: N = 3072 (Wq|Wk|Wv stacked in whi/wlo)
    {
        dim3 g(3072/128, M/128);     // (24, 32)
        gemm2<<<g, 256, SM_GEMM>>>(xhi, whi, wlo, bq, bk, bv,
                                   nullptr, qhi, qlo, khi, vhi, M, 3072, D_);
    }
    {
        dim3 tg(S_/32, D_/32, B_);
        transpose_v<<<tg, 256>>>(vhi, vthi);
    }

    cudaFuncSetAttribute(attn_hmma, cudaFuncAttributeMaxDynamicSharedMemorySize, SM_ATT);
    dim3 attn_grid(S_ / TQ, H_, B_);
    attn_hmma<<<attn_grid, 512, SM_ATT>>>(qhi, qlo, khi, vthi, attnw, aohi);

    // output projection
    {
        dim3 g(D_/128, M/128);       // (8, 32)
        gemm2<<<g, 256, SM_GEMM>>>(aohi, whi + 3*(size_t)WSZ, wlo + 3*(size_t)WSZ,
                                   bo, nullptr, nullptr, out,
                                   nullptr, nullptr, nullptr, nullptr, M, D_, D_);
    }
}

// round 11
// speedup vs baseline: 1.6029x; 1.0451x over previous
#include <cuda_runtime.h>
#include <cuda_fp16.h>
#include <math.h>
#include <stdint.h>

#define B_  2
#define S_  2048
#define D_  1024
#define H_  16
#define HD_ 64

#define TQ  16
#define KCA 256              // attention key-chunk

#define MSZ (B_*S_)          // 4096 rows
#define WSZ (D_*D_)

// ---------------------------------------------------------------------------
// Scratch (allocation-free rule: __device__ globals)
// ---------------------------------------------------------------------------
__device__ __half g_xhi [MSZ*D_];
__device__ __half g_whi [4*D_*D_];   // Wq, Wk, Wv, Wo stacked
__device__ __half g_wlo [4*D_*D_];
__device__ __half g_aohi[MSZ*D_];
__device__ __half g_qhi [MSZ*D_];
__device__ __half g_qlo [MSZ*D_];
__device__ __half g_khi [MSZ*D_];
__device__ __half g_vhi [MSZ*D_];    // v row-major fp16
__device__ __half g_vthi[MSZ*D_];    // [B][H][64][S]

// ---------------------------------------------------------------------------
// fp32 -> fp16 hi-only, 4 float4 per thread (MLP=4)
// ---------------------------------------------------------------------------
__global__ __launch_bounds__(256)
void convert_hi4(const float4* __restrict__ in, uint2* __restrict__ hi)
{
    const int base = blockIdx.x * 1024 + threadIdx.x;
    float4 v[4];
    #pragma unroll
    for (int j = 0; j < 4; j++) v[j] = in[base + j*256];
    #pragma unroll
    for (int j = 0; j < 4; j++) {
        __half2 h0 = __floats2half2_rn(v[j].x, v[j].y);
        __half2 h1 = __floats2half2_rn(v[j].z, v[j].w);
        uint2 H;
        H.x = *(const uint32_t*)&h0; H.y = *(const uint32_t*)&h1;
        hi[base + j*256] = H;
    }
}

// all four weights, fp32 -> fp16 (hi, lo), 4 float4 per thread
__global__ __launch_bounds__(256)
void convert_w4(const float4* __restrict__ w0, const float4* __restrict__ w1,
                const float4* __restrict__ w2, const float4* __restrict__ w3,
                uint2* __restrict__ hi, uint2* __restrict__ lo)
{
    const int base = blockIdx.x * 1024 + threadIdx.x;
    float4 v[4];
    #pragma unroll
    for (int j = 0; j < 4; j++) {
        int i = base + j*256;
        int which = i >> 18;                 // WSZ/4 = 262144
        int idx = i & 262143;
        const float4* src = (which == 0) ? w0 : (which == 1) ? w1
                          : (which == 2) ? w2 : w3;
        v[j] = src[idx];
    }
    #pragma unroll
    for (int j = 0; j < 4; j++) {
        int i = base + j*256;
        __half2 h0 = __floats2half2_rn(v[j].x, v[j].y);
        __half2 h1 = __floats2half2_rn(v[j].z, v[j].w);
        __half2 l0 = __floats2half2_rn(v[j].x - __low2float(h0), v[j].y - __high2float(h0));
        __half2 l1 = __floats2half2_rn(v[j].z - __low2float(h1), v[j].w - __high2float(h1));
        uint2 H, L;
        H.x = *(const uint32_t*)&h0; H.y = *(const uint32_t*)&h1;
        L.x = *(const uint32_t*)&l0; L.y = *(const uint32_t*)&l1;
        hi[i] = H; lo[i] = L;
    }
}

// ---------------------------------------------------------------------------
// V fp16 [b, s, d] -> VT fp16 [b, h, d(64), s]
// ---------------------------------------------------------------------------
__global__ __launch_bounds__(256)
void transpose_v(const __half* __restrict__ v, __half* __restrict__ vt)
{
    __shared__ __half tile[32][34];
    const int s0 = blockIdx.x * 32, d0 = blockIdx.y * 32, b = blockIdx.z;
    const int c = threadIdx.x & 31, r4 = threadIdx.x >> 5;
    #pragma unroll
    for (int i = 0; i < 4; i++) {
        int r = r4 + i * 8;
        tile[r][c] = v[(size_t)(b*S_ + s0 + r) * D_ + d0 + c];
    }
    __syncthreads();
    #pragma unroll
    for (int i = 0; i < 4; i++) {
        int d = d0 + r4 + i * 8;
        int s = s0 + c;
        vt[((size_t)(b*H_ + (d >> 6)) * 64 + (d & 63)) * S_ + s] = tile[c][r4 + i*8];
    }
}

// ---------------------------------------------------------------------------
// PTX helpers (non-variant ISA)
// ---------------------------------------------------------------------------
__device__ __forceinline__ uint32_t smem_u32(const void* p) {
    uint32_t a;
    asm("{ .reg .u64 t; cvta.to.shared.u64 t, %1; cvt.u32.u64 %0, t; }" : "=r"(a) : "l"(p));
    return a;
}
__device__ __forceinline__ void ldm_x4(uint32_t* r, uint32_t addr) {
    asm volatile("ldmatrix.sync.aligned.m8n8.x4.shared.b16 {%0,%1,%2,%3}, [%4];"
        : "=r"(r[0]), "=r"(r[1]), "=r"(r[2]), "=r"(r[3]) : "r"(addr));
}
__device__ __forceinline__ void ldm_x2(uint32_t* r, uint32_t addr) {
    asm volatile("ldmatrix.sync.aligned.m8n8.x2.shared.b16 {%0,%1}, [%2];"
        : "=r"(r[0]), "=r"(r[1]) : "r"(addr));
}
__device__ __forceinline__ void mma_f32(float* c, const uint32_t* a,
                                        uint32_t b0, uint32_t b1) {
    asm volatile(
        "mma.sync.aligned.m16n8k16.row.col.f32.f16.f16.f32 "
        "{%0,%1,%2,%3}, {%4,%5,%6,%7}, {%8,%9}, {%0,%1,%2,%3};"
        : "+f"(c[0]), "+f"(c[1]), "+f"(c[2]), "+f"(c[3])
        : "r"(a[0]), "r"(a[1]), "r"(a[2]), "r"(a[3]), "r"(b0), "r"(b1));
}
// fp16 accumulate (correction terms)
__device__ __forceinline__ void mma_f16(uint32_t* c, const uint32_t* a,
                                        uint32_t b0, uint32_t b1) {
    asm volatile(
        "mma.sync.aligned.m16n8k16.row.col.f16.f16.f16.f16 "
        "{%0,%1}, {%2,%3,%4,%5}, {%6,%7}, {%0,%1};"
        : "+r"(c[0]), "+r"(c[1])
        : "r"(a[0]), "r"(a[1]), "r"(a[2]), "r"(a[3]), "r"(b0), "r"(b1));
}
__device__ __forceinline__ void corr_merge(float* c, const uint32_t* cc) {
    __half2 h0 = *(const __half2*)&cc[0];
    __half2 h1 = *(const __half2*)&cc[1];
    c[0] += __low2float(h0); c[1] += __high2float(h0);
    c[2] += __low2float(h1); c[3] += __high2float(h1);
}
__device__ __forceinline__ void cp16(uint32_t dst, const void* src) {
    asm volatile("cp.async.cg.shared.global [%0], [%1], 16;" :: "r"(dst), "l"(src));
}
#define CP_COMMIT() asm volatile("cp.async.commit_group;" ::: "memory")
#define CP_WAIT0()  asm volatile("cp.async.wait_group 0;" ::: "memory")
__device__ __forceinline__ void stg_cs_f2(float* p, float a, float b) {
    asm volatile("st.global.cs.v2.f32 [%0], {%1,%2};" :: "l"(p), "f"(a), "f"(b) : "memory");
}
__device__ __forceinline__ void stg_cs_f4z(float* p) {
    asm volatile("st.global.cs.v4.f32 [%0], {%1,%1,%1,%1};" :: "l"(p), "f"(0.f) : "memory");
}

// ---------------------------------------------------------------------------
// HMMA GEMM, 2-term fp16 split (bench-proven R9/R10): C = A @ (Whi+Wlo)^T + bias.
// ---------------------------------------------------------------------------
#define LDT 40
#define TILE_B   (128*LDT*2)         // 10240 bytes
#define STAGE_B  (3*TILE_B)          // 30720 bytes
#define SM_GEMM  (2*STAGE_B)         // 61440 bytes

__global__ __launch_bounds__(256, 2)
void gemm2(const __half* __restrict__ A,
           const __half* __restrict__ Bhi, const __half* __restrict__ Blo,
           const float* __restrict__ bs0, const float* __restrict__ bs1,
           const float* __restrict__ bs2,
           float* __restrict__ Cf32,
           __half* __restrict__ oQhi, __half* __restrict__ oQlo,
           __half* __restrict__ oKhi, __half* __restrict__ oVhi,
           int M, int N, int K)
{
    extern __shared__ __half dsm[];
    const uint32_t sb = smem_u32(dsm);

    const int tid = threadIdx.x;
    const int lane = tid & 31;
    const int wid  = tid >> 5;
    const int wm = wid & 1;
    const int wn = wid >> 1;
    const int m0 = blockIdx.y * 128;
    const int n0 = blockIdx.x * 128;

    const int sub = lane >> 3, rr = lane & 7;
    const int rowoff = ((sub & 1) << 3) + rr;
    const int koffb  = (sub >> 1) << 4;

    const uint32_t offA = (uint32_t)((wm*64 + rowoff) * 80 + koffb);
    const uint32_t offB = (uint32_t)((wn*32 + rowoff) * 80 + koffb);

    const int crow0 = tid >> 2, cvv = tid & 3;
    const __half* gsrc[3] = {
        A + (size_t)m0 * K, Bhi + (size_t)n0 * K, Blo + (size_t)n0 * K };

    float acc[4][4][4];
    #pragma unroll
    for (int i = 0; i < 4; i++)
        #pragma unroll
        for (int j = 0; j < 4; j++)
            #pragma unroll
            for (int q = 0; q < 4; q++) acc[i][j][q] = 0.f;

    const int nChunk = K / 32;

    #pragma unroll
    for (int t = 0; t < 3; t++)
        #pragma unroll
        for (int it = 0; it < 2; it++) {
            int row = crow0 + it * 64;
            cp16(sb + (uint32_t)(t*TILE_B + row*80 + cvv*16),
                 gsrc[t] + (size_t)row * K + cvv*8);
        }
    CP_COMMIT();

    for (int c = 0; c < nChunk; c++) {
        CP_WAIT0();
        __syncthreads();

        if (c + 1 < nChunk) {
            const int k1 = (c + 1) * 32;
            const uint32_t stg = (uint32_t)(((c + 1) & 1) * STAGE_B);
            #pragma unroll
            for (int t = 0; t < 3; t++)
                #pragma unroll
                for (int it = 0; it < 2; it++) {
                    int row = crow0 + it * 64;
                    cp16(sb + stg + (uint32_t)(t*TILE_B + row*80 + cvv*16),
                         gsrc[t] + (size_t)row * K + k1 + cvv*8);
                }
            CP_COMMIT();
        }

        const uint32_t stg = (uint32_t)((c & 1) * STAGE_B);
        const uint32_t aBase = sb + stg + offA;
        const uint32_t bHi = sb + stg + TILE_B + offB;
        const uint32_t bLo = bHi + TILE_B;

        #pragma unroll
        for (int ks = 0; ks < 2; ks++) {
            const uint32_t kb = (uint32_t)(ks * 32);
            uint32_t ah[4][4], bh[2][4], bl[2][4];
            #pragma unroll
            for (int mt = 0; mt < 4; mt++) ldm_x4(ah[mt], aBase + mt * (16*80) + kb);
            ldm_x4(bh[0], bHi + kb);
            ldm_x4(bh[1], bHi + 16*80 + kb);
            ldm_x4(bl[0], bLo + kb);
            ldm_x4(bl[1], bLo + 16*80 + kb);

            #pragma unroll
            for (int mt = 0; mt < 4; mt++)
                #pragma unroll
                for (int nf = 0; nf < 4; nf++) {
                    const int nb = nf >> 1, sel = nf & 1;
                    mma_f32(acc[mt][nf], ah[mt], bh[nb][sel], bh[nb][2+sel]);
                    mma_f32(acc[mt][nf], ah[mt], bl[nb][sel], bl[nb][2+sel]);
                }
        }
    }

    const int g = lane >> 2, t = lane & 3;
    #pragma unroll
    for (int mt = 0; mt < 4; mt++) {
        const int row = m0 + wm*64 + mt*16 + g;
        #pragma unroll
        for (int nf = 0; nf < 4; nf++) {
            const int colg = n0 + wn*32 + nf*8 + t*2;
            if (Cf32) {
                const float b0 = bs0[colg], b1 = bs0[colg+1];
                float2 lo2 = { acc[mt][nf][0] + b0, acc[mt][nf][1] + b1 };
                float2 hi2 = { acc[mt][nf][2] + b0, acc[mt][nf][3] + b1 };
                *(float2*)(Cf32 + (size_t)row * N + colg)       = lo2;
                *(float2*)(Cf32 + (size_t)(row + 8) * N + colg) = hi2;
            } else {
                const int seg = colg >> 10;
                const int col = colg & 1023;
                const float* bp = (seg == 0) ? bs0 : (seg == 1) ? bs1 : bs2;
                const float b0 = bp[col], b1 = bp[col+1];
                float v00 = acc[mt][nf][0] + b0, v01 = acc[mt][nf][1] + b1;
                float v10 = acc[mt][nf][2] + b0, v11 = acc[mt][nf][3] + b1;
                __half2 h0 = __floats2half2_rn(v00, v01);
                __half2 h1 = __floats2half2_rn(v10, v11);
                const size_t o0 = (size_t)row * D_ + col;
                const size_t o1 = (size_t)(row + 8) * D_ + col;
                if (seg == 0) {
                    __half2 l0 = __floats2half2_rn(v00 - __low2float(h0), v01 - __high2float(h0));
                    __half2 l1 = __floats2half2_rn(v10 - __low2float(h1), v11 - __high2float(h1));
                    *(uint32_t*)(oQhi + o0) = *(const uint32_t*)&h0;
                    *(uint32_t*)(oQlo + o0) = *(const uint32_t*)&l0;
                    *(uint32_t*)(oQhi + o1) = *(const uint32_t*)&h1;
                    *(uint32_t*)(oQlo + o1) = *(const uint32_t*)&l1;
                } else if (seg == 1) {
                    *(uint32_t*)(oKhi + o0) = *(const uint32_t*)&h0;
                    *(uint32_t*)(oKhi + o1) = *(const uint32_t*)&h1;
                } else {
                    *(uint32_t*)(oVhi + o0) = *(const uint32_t*)&h0;
                    *(uint32_t*)(oVhi + o1) = *(const uint32_t*)&h1;
                }
            }
        }
    }
}

// ---------------------------------------------------------------------------
// HMMA fused causal attention. Corrections via f16-acc MMA (A/B experiment),
// softmax normalize folded into P-convert, convert before VT wait,
// early zero-fill, streaming attnw stores. 512 threads.
// ---------------------------------------------------------------------------
#define KST 72     // 144 B rows
#define VST 264    // 528 B rows
#define OFF_KV 131072
#define KVBUF  36864
#define OFF_P  204800
#define OFF_Q  221696
#define SM_ATT 226304

__global__ __launch_bounds__(512)
void attn_hmma(const __half* __restrict__ qhi, const __half* __restrict__ qlo,
               const __half* __restrict__ khi, const __half* __restrict__ vthi,
               float* __restrict__ attnw, __half* __restrict__ aohi)
{
    extern __shared__ char smb[];
    const uint32_t sbm = smem_u32(smb);
    float* rows = (float*)smb;
    __half* Phi = (__half*)(smb + OFF_P);
    __half* Plo = Phi + 16*VST;
    __half* Qhi = (__half*)(smb + OFF_Q);
    __half* Qlo = Qhi + 16*KST;
    float* sinv = (float*)(smb + OFF_Q);         // after Q frags consumed
    float* pbuf = (float*)(smb + OFF_Q + 64);

    const int qt = blockIdx.x, h = blockIdx.y, b = blockIdx.z;
    const int q0 = qt * TQ;
    const int tid  = threadIdx.x;
    const int lane = tid & 31;
    const int wid  = tid >> 5;
    const int nk   = q0 + TQ;
    const int nChunk = (nk + KCA - 1) / KCA;
    const int nkc = nChunk * KCA;
    const float scale = 0.125f;
    const size_t abase = (((size_t)b * H_ + h) * S_ + q0) * (size_t)S_;

    const int sub = lane >> 3, rr = lane & 7;
    const int arow = ((sub & 1) << 3) + rr;
    const int akoff = (sub >> 1) << 4;

    // ---- early zero-fill attnw cols [nkc, S) — drains behind phase 1 ----
    if (nkc < S_) {
        float* zrow = attnw + abase + (size_t)wid * S_;
        for (int j = nkc + lane*4; j < S_; j += 128)
            stg_cs_f4z(zrow + j);
    }

    // ---- Q tile (hi/lo) ----
    {
        const size_t qgb = ((size_t)(b*S_ + q0)) * D_ + h*HD_;
        for (int i = tid; i < 256; i += 512) {
            int which = i >> 7, u = i & 127;
            int token = u >> 3, seg = u & 7;
            const __half* src = (which ? qlo : qhi) + qgb + (size_t)token * D_ + seg*8;
            __half* dst = (which ? Qlo : Qhi) + token*KST + seg*8;
            *(uint4*)dst = *(const uint4*)src;
        }
    }
    __syncthreads();

    uint32_t qfh[4][4], qfl[4][4];
    {
        const uint32_t qa_hi = smem_u32(Qhi) + (uint32_t)(arow*144 + akoff);
        const uint32_t qa_lo = smem_u32(Qlo) + (uint32_t)(arow*144 + akoff);
        #pragma unroll
        for (int ks = 0; ks < 4; ks++) {
            ldm_x4(qfh[ks], qa_hi + ks*32);
            ldm_x4(qfl[ks], qa_lo + ks*32);
        }
    }

    const int gq = lane >> 2, t2 = (lane & 3) << 1;
    const size_t kgb = ((size_t)b*S_) * D_ + h*HD_;

    // ---- Phase 1: scores, cp.async double-buffered K ----
    {
        #pragma unroll
        for (int it = 0; it < 4; it++) {            // chunk 0 -> buf 0
            int u = tid + it * 512;
            int token = u >> 3, seg = u & 7;
            cp16(sbm + OFF_KV + (uint32_t)(token*144 + seg*16),
                 khi + kgb + (size_t)token * D_ + seg*8);
        }
        CP_COMMIT();
    }

    for (int c = 0; c < nChunk; c++) {
        CP_WAIT0();
        __syncthreads();

        if (c + 1 < nChunk) {
            const int k1 = (c + 1) * KCA;
            const uint32_t dstb = sbm + OFF_KV + (uint32_t)(((c + 1) & 1) * KVBUF);
            #pragma unroll
            for (int it = 0; it < 4; it++) {
                int u = tid + it * 512;
                int token = u >> 3, seg = u & 7;
                cp16(dstb + (uint32_t)(token*144 + seg*16),
                     khi + kgb + (size_t)(k1 + token) * D_ + seg*8);
            }
            CP_COMMIT();
        }

        const int k0c = c * KCA;
        float sc[2][4];
        uint32_t scc[2][2];
        #pragma unroll
        for (int ns = 0; ns < 2; ns++) {
            #pragma unroll
            for (int j = 0; j < 4; j++) sc[ns][j] = 0.f;
            scc[ns][0] = 0u; scc[ns][1] = 0u;
        }

        if (k0c + wid*16 <= q0 + 15) {          // causal skip
            const uint32_t kbase = sbm + OFF_KV + (uint32_t)((c & 1) * KVBUF)
                                 + (uint32_t)((wid*16 + arow)*144 + akoff);
            #pragma unroll
            for (int ks = 0; ks < 4; ks++) {
                uint32_t kh[4];
                ldm_x4(kh, kbase + ks*32);
                #pragma unroll
                for (int ns = 0; ns < 2; ns++) {
                    mma_f32(sc[ns], qfh[ks], kh[ns], kh[2+ns]);
                    mma_f16(scc[ns], qfl[ks], kh[ns], kh[2+ns]);   // correction, f16-acc
                }
            }
        }

        #pragma unroll
        for (int ns = 0; ns < 2; ns++) {
            corr_merge(sc[ns], scc[ns]);
            const int kg = k0c + wid*16 + ns*8 + t2;
            rows[(size_t)gq*S_ + kg]      = (kg   <= q0+gq) ? sc[ns][0]*scale : -INFINITY;
            rows[(size_t)gq*S_ + kg+1]    = (kg+1 <= q0+gq) ? sc[ns][1]*scale : -INFINITY;
            rows[(size_t)(gq+8)*S_ + kg]  = (kg   <= q0+gq+8) ? sc[ns][2]*scale : -INFINITY;
            rows[(size_t)(gq+8)*S_ + kg+1]= (kg+1 <= q0+gq+8) ? sc[ns][3]*scale : -INFINITY;
        }
    }
    __syncthreads();

    // ---- Phase 2: softmax max + exp/sum; store 1/s, skip normalize pass ----
    {
        const int r = wid;
        const int nr = q0 + r + 1;                 // valid keys for this row
        float* prow = rows + (size_t)r * S_;
        float m = -INFINITY;
        for (int i = lane; i < nr; i += 32) m = fmaxf(m, prow[i]);
        #pragma unroll
        for (int off = 16; off; off >>= 1) m = fmaxf(m, __shfl_xor_sync(0xffffffffu, m, off));
        float s = 0.f;
        for (int i = lane; i < nkc; i += 32) {
            float e = __expf(prow[i] - m);         // exp(-INF)=0 beyond nr
            prow[i] = e;
            s += e;
        }
        #pragma unroll
        for (int off = 16; off; off >>= 1) s += __shfl_xor_sync(0xffffffffu, s, off);
        if (lane == 0) sinv[r] = 1.f / s;
    }
    __syncthreads();

    // ---- Phase 4: AV; convert(P)+attnw before VT wait; dbuf VT ----
    const int khalf = wid >> 3, ntile = wid & 7;
    const uint32_t pA_hi = smem_u32(Phi) + (uint32_t)(arow*528 + akoff + khalf*256);
    const uint32_t pA_lo = smem_u32(Plo) + (uint32_t)(arow*528 + akoff + khalf*256);
    const size_t vgb = ((size_t)(b*H_ + h)) * 64 * S_;

    {
        #pragma unroll
        for (int it = 0; it < 4; it++) {            // chunk 0 -> buf 0
            int u = tid + it * 512;
            int d = u >> 5, seg = u & 31;
            cp16(sbm + OFF_KV + (uint32_t)(d*528 + seg*16),
                 vthi + vgb + (size_t)d * S_ + seg*8);
        }
        CP_COMMIT();
    }

    float oc[4] = {0.f, 0.f, 0.f, 0.f};
    uint32_t occ[2] = {0u, 0u};
    for (int c = 0; c < nChunk; c++) {
        const int k0c = c * KCA;
        if (c) __syncthreads();        // prev MMA done with Phi/Plo + prev buf

        // fused: rows -> (attnw streaming store) + (Phi/Plo fp16 convert), normalized here
        #pragma unroll
        for (int it = 0; it < 4; it++) {
            int p = tid + it * 512;
            int r = p >> 7, j2 = (p & 127) << 1;
            float inv = sinv[r];
            float v0 = rows[(size_t)r*S_ + k0c + j2] * inv;
            float v1 = rows[(size_t)r*S_ + k0c + j2 + 1] * inv;
            stg_cs_f2(attnw + abase + (size_t)r*S_ + k0c + j2, v0, v1);
            __half2 hb = __floats2half2_rn(v0, v1);
            __half2 lb = __floats2half2_rn(v0 - __low2float(hb), v1 - __high2float(hb));
            *(uint32_t*)(Phi + r*VST + j2) = *(const uint32_t*)&hb;
            *(uint32_t*)(Plo + r*VST + j2) = *(const uint32_t*)&lb;
        }

        CP_WAIT0();
        __syncthreads();               // VT + Phi/Plo visible to all

        if (c + 1 < nChunk) {
            const int k1 = (c + 1) * KCA;
            const uint32_t dstb = sbm + OFF_KV + (uint32_t)(((c + 1) & 1) * KVBUF);
            #pragma unroll
            for (int it = 0; it < 4; it++) {
                int u = tid + it * 512;
                int d = u >> 5, seg = u & 31;
                cp16(dstb + (uint32_t)(d*528 + seg*16),
                     vthi + vgb + (size_t)d * S_ + k1 + seg*8);
            }
            CP_COMMIT();
        }

        if (k0c + khalf*128 < nk) {               // skip all-zero-P half-chunks
            const uint32_t vbase = sbm + OFF_KV + (uint32_t)((c & 1) * KVBUF)
                                 + (uint32_t)((ntile*8 + rr)*528
                                 + (((lane >> 3) & 1) << 4) + khalf*256);
            #pragma unroll
            for (int ks = 0; ks < 8; ks++) {
                uint32_t ph[4], pl[4], vh[2];
                ldm_x4(ph, pA_hi + ks*32);
                ldm_x4(pl, pA_lo + ks*32);
                ldm_x2(vh, vbase + ks*32);
                mma_f32(oc, ph, vh[0], vh[1]);
                mma_f16(occ, pl, vh[0], vh[1]);    // correction, f16-acc
            }
        }
    }
    corr_merge(oc, occ);

    // combine k-halves via pbuf
    __syncthreads();
    if (khalf == 1) {
        pbuf[gq*HD_ + ntile*8 + t2]       = oc[0];
        pbuf[gq*HD_ + ntile*8 + t2 + 1]   = oc[1];
        pbuf[(gq+8)*HD_ + ntile*8 + t2]   = oc[2];
        pbuf[(gq+8)*HD_ + ntile*8 + t2+1] = oc[3];
    }
    __syncthreads();
    if (khalf == 0) {
        const int col = h*HD_ + ntile*8 + t2;
        const size_t o0 = ((size_t)(b*S_ + q0 + gq)) * D_ + col;
        const size_t o1 = ((size_t)(b*S_ + q0 + gq + 8)) * D_ + col;
        float v00 = oc[0] + pbuf[gq*HD_ + ntile*8 + t2];
        float v01 = oc[1] + pbuf[gq*HD_ + ntile*8 + t2 + 1];
        float v10 = oc[2] + pbuf[(gq+8)*HD_ + ntile*8 + t2];
        float v11 = oc[3] + pbuf[(gq+8)*HD_ + ntile*8 + t2 + 1];
        __half2 h0 = __floats2half2_rn(v00, v01);
        __half2 h1 = __floats2half2_rn(v10, v11);
        *(uint32_t*)(aohi + o0) = *(const uint32_t*)&h0;
        *(uint32_t*)(aohi + o1) = *(const uint32_t*)&h1;
    }
}

// ---------------------------------------------------------------------------
extern "C" void kernel_launch(void* const* d_in, const int* in_sizes, int n_in,
                              void* d_out, int out_size)
{
    const float* x  = (const float*)d_in[0];
    const float* Wq = (const float*)d_in[1];
    const float* bq = (const float*)d_in[2];
    const float* Wk = (const float*)d_in[3];
    const float* bk = (const float*)d_in[4];
    const float* Wv = (const float*)d_in[5];
    const float* bv = (const float*)d_in[6];
    const float* Wo = (const float*)d_in[7];
    const float* bo = (const float*)d_in[8];

    float* out   = (float*)d_out;                       // [B,S,D]
    float* attnw = out + (size_t)B_ * S_ * D_;          // [B,H,S,S]

    __half *xhi, *whi, *wlo, *aohi, *qhi, *qlo, *khi, *vhi, *vthi;
    cudaGetSymbolAddress((void**)&xhi,  g_xhi);
    cudaGetSymbolAddress((void**)&whi,  g_whi);
    cudaGetSymbolAddress((void**)&wlo,  g_wlo);
    cudaGetSymbolAddress((void**)&aohi, g_aohi);
    cudaGetSymbolAddress((void**)&qhi,  g_qhi);
    cudaGetSymbolAddress((void**)&qlo,  g_qlo);
    cudaGetSymbolAddress((void**)&khi,  g_khi);
    cudaGetSymbolAddress((void**)&vhi,  g_vhi);
    cudaGetSymbolAddress((void**)&vthi, g_vthi);

    const int M = MSZ;               // 4096
    const int NPX = M * D_ / 4;      // 1048576 float4

    convert_hi4<<<NPX/1024, 256>>>((const float4*)x, (uint2*)xhi);
    convert_w4<<<(4*WSZ/4)/1024, 256>>>(
        (const float4*)Wq, (const float4*)Wk, (const float4*)Wv, (const float4*)Wo,
        (uint2*)whi, (uint2*)wlo);

    cudaFuncSetAttribute(gemm2, cudaFuncAttributeMaxDynamicSharedMemorySize, SM_GEMM);

    // fused QKV: N = 3072 (Wq|Wk|Wv stacked in whi/wlo)
    {
        dim3 g(3072/128, M/128);     // (24, 32)
        gemm2<<<g, 256, SM_GEMM>>>(xhi, whi, wlo, bq, bk, bv,
                                   nullptr, qhi, qlo, khi, vhi, M, 3072, D_);
    }
    {
        dim3 tg(S_/32, D_/32, B_);
        transpose_v<<<tg, 256>>>(vhi, vthi);
    }

    cudaFuncSetAttribute(attn_hmma, cudaFuncAttributeMaxDynamicSharedMemorySize, SM_ATT);
    dim3 attn_grid(S_ / TQ, H_, B_);
    attn_hmma<<<attn_grid, 512, SM_ATT>>>(qhi, qlo, khi, vthi, attnw, aohi);

    // output projection
    {
        dim3 g(D_/128, M/128);       // (8, 32)
        gemm2<<<g, 256, SM_GEMM>>>(aohi, whi + 3*(size_t)WSZ, wlo + 3*(size_t)WSZ,
                                   bo, nullptr, nullptr, out,
                                   nullptr, nullptr, nullptr, nullptr, M, D_, D_);
    }
}

// round 12
// speedup vs baseline: 1.6331x; 1.0189x over previous
#include <cuda_runtime.h>
#include <cuda_fp16.h>
#include <math.h>
#include <stdint.h>

#define B_  2
#define S_  2048
#define D_  1024
#define H_  16
#define HD_ 64

#define TQ  16
#define KCA 256              // attention key-chunk

#define MSZ (B_*S_)          // 4096 rows
#define WSZ (D_*D_)

// ---------------------------------------------------------------------------
// Scratch (allocation-free rule: __device__ globals)
// ---------------------------------------------------------------------------
__device__ __half g_xhi [MSZ*D_];
__device__ __half g_whi [4*D_*D_];   // Wq, Wk, Wv, Wo stacked
__device__ __half g_wlo [4*D_*D_];
__device__ __half g_aohi[MSZ*D_];
__device__ __half g_qhi [MSZ*D_];
__device__ __half g_qlo [MSZ*D_];
__device__ __half g_khi [MSZ*D_];
__device__ __half g_vhi [MSZ*D_];    // v row-major fp16 (consumed via ldmatrix.trans)

// ---------------------------------------------------------------------------
// Fused convert: x -> fp16 hi; Wq|Wk|Wv|Wo -> fp16 (hi, lo). MLP=4.
// index space: [0, NPX) = x ; [NPX, NPX + WN) = weights
// ---------------------------------------------------------------------------
#define NPX4 (MSZ*D_/4)              // 1048576 float4 of x
#define NW4  (4*WSZ/4)               // 1048576 float4 of W

__global__ __launch_bounds__(256)
void convert_all(const float4* __restrict__ x,
                 const float4* __restrict__ w0, const float4* __restrict__ w1,
                 const float4* __restrict__ w2, const float4* __restrict__ w3,
                 uint2* __restrict__ xhi, uint2* __restrict__ whi,
                 uint2* __restrict__ wlo)
{
    const int base = blockIdx.x * 1024 + threadIdx.x;
    float4 v[4];
    #pragma unroll
    for (int j = 0; j < 4; j++) {
        int i = base + j*256;
        if (i < NPX4) {
            v[j] = x[i];
        } else {
            int k = i - NPX4;
            int which = k >> 18;             // WSZ/4 = 262144
            int idx = k & 262143;
            const float4* src = (which == 0) ? w0 : (which == 1) ? w1
                              : (which == 2) ? w2 : w3;
            v[j] = src[idx];
        }
    }
    #pragma unroll
    for (int j = 0; j < 4; j++) {
        int i = base + j*256;
        __half2 h0 = __floats2half2_rn(v[j].x, v[j].y);
        __half2 h1 = __floats2half2_rn(v[j].z, v[j].w);
        uint2 H;
        H.x = *(const uint32_t*)&h0; H.y = *(const uint32_t*)&h1;
        if (i < NPX4) {
            xhi[i] = H;
        } else {
            int k = i - NPX4;
            __half2 l0 = __floats2half2_rn(v[j].x - __low2float(h0), v[j].y - __high2float(h0));
            __half2 l1 = __floats2half2_rn(v[j].z - __low2float(h1), v[j].w - __high2float(h1));
            uint2 L;
            L.x = *(const uint32_t*)&l0; L.y = *(const uint32_t*)&l1;
            whi[k] = H; wlo[k] = L;
        }
    }
}

// ---------------------------------------------------------------------------
// PTX helpers (non-variant ISA)
// ---------------------------------------------------------------------------
__device__ __forceinline__ uint32_t smem_u32(const void* p) {
    uint32_t a;
    asm("{ .reg .u64 t; cvta.to.shared.u64 t, %1; cvt.u32.u64 %0, t; }" : "=r"(a) : "l"(p));
    return a;
}
__device__ __forceinline__ void ldm_x4(uint32_t* r, uint32_t addr) {
    asm volatile("ldmatrix.sync.aligned.m8n8.x4.shared.b16 {%0,%1,%2,%3}, [%4];"
        : "=r"(r[0]), "=r"(r[1]), "=r"(r[2]), "=r"(r[3]) : "r"(addr));
}
__device__ __forceinline__ void ldm_x2_trans(uint32_t* r, uint32_t addr) {
    asm volatile("ldmatrix.sync.aligned.m8n8.x2.trans.shared.b16 {%0,%1}, [%2];"
        : "=r"(r[0]), "=r"(r[1]) : "r"(addr));
}
__device__ __forceinline__ void mma_f32(float* c, const uint32_t* a,
                                        uint32_t b0, uint32_t b1) {
    asm volatile(
        "mma.sync.aligned.m16n8k16.row.col.f32.f16.f16.f32 "
        "{%0,%1,%2,%3}, {%4,%5,%6,%7}, {%8,%9}, {%0,%1,%2,%3};"
        : "+f"(c[0]), "+f"(c[1]), "+f"(c[2]), "+f"(c[3])
        : "r"(a[0]), "r"(a[1]), "r"(a[2]), "r"(a[3]), "r"(b0), "r"(b1));
}
// fp16 accumulate (correction terms)
__device__ __forceinline__ void mma_f16(uint32_t* c, const uint32_t* a,
                                        uint32_t b0, uint32_t b1) {
    asm volatile(
        "mma.sync.aligned.m16n8k16.row.col.f16.f16.f16.f16 "
        "{%0,%1}, {%2,%3,%4,%5}, {%6,%7}, {%0,%1};"
        : "+r"(c[0]), "+r"(c[1])
        : "r"(a[0]), "r"(a[1]), "r"(a[2]), "r"(a[3]), "r"(b0), "r"(b1));
}
__device__ __forceinline__ void corr_merge(float* c, const uint32_t* cc) {
    __half2 h0 = *(const __half2*)&cc[0];
    __half2 h1 = *(const __half2*)&cc[1];
    c[0] += __low2float(h0); c[1] += __high2float(h0);
    c[2] += __low2float(h1); c[3] += __high2float(h1);
}
__device__ __forceinline__ void cp16(uint32_t dst, const void* src) {
    asm volatile("cp.async.cg.shared.global [%0], [%1], 16;" :: "r"(dst), "l"(src));
}
#define CP_COMMIT() asm volatile("cp.async.commit_group;" ::: "memory")
#define CP_WAIT0()  asm volatile("cp.async.wait_group 0;" ::: "memory")
__device__ __forceinline__ void stg_cs_f2(float* p, float a, float b) {
    asm volatile("st.global.cs.v2.f32 [%0], {%1,%2};" :: "l"(p), "f"(a), "f"(b) : "memory");
}
__device__ __forceinline__ void stg_cs_f4z(float* p) {
    asm volatile("st.global.cs.v4.f32 [%0], {%1,%1,%1,%1};" :: "l"(p), "f"(0.f) : "memory");
}

// ---------------------------------------------------------------------------
// HMMA GEMM, 2-term fp16 split (bench-proven R9-R11): C = A @ (Whi+Wlo)^T + bias.
// ---------------------------------------------------------------------------
#define LDT 40
#define TILE_B   (128*LDT*2)         // 10240 bytes
#define STAGE_B  (3*TILE_B)          // 30720 bytes
#define SM_GEMM  (2*STAGE_B)         // 61440 bytes

__global__ __launch_bounds__(256, 2)
void gemm2(const __half* __restrict__ A,
           const __half* __restrict__ Bhi, const __half* __restrict__ Blo,
           const float* __restrict__ bs0, const float* __restrict__ bs1,
           const float* __restrict__ bs2,
           float* __restrict__ Cf32,
           __half* __restrict__ oQhi, __half* __restrict__ oQlo,
           __half* __restrict__ oKhi, __half* __restrict__ oVhi,
           int M, int N, int K)
{
    extern __shared__ __half dsm[];
    const uint32_t sb = smem_u32(dsm);

    const int tid = threadIdx.x;
    const int lane = tid & 31;
    const int wid  = tid >> 5;
    const int wm = wid & 1;
    const int wn = wid >> 1;
    const int m0 = blockIdx.y * 128;
    const int n0 = blockIdx.x * 128;

    const int sub = lane >> 3, rr = lane & 7;
    const int rowoff = ((sub & 1) << 3) + rr;
    const int koffb  = (sub >> 1) << 4;

    const uint32_t offA = (uint32_t)((wm*64 + rowoff) * 80 + koffb);
    const uint32_t offB = (uint32_t)((wn*32 + rowoff) * 80 + koffb);

    const int crow0 = tid >> 2, cvv = tid & 3;
    const __half* gsrc[3] = {
        A + (size_t)m0 * K, Bhi + (size_t)n0 * K, Blo + (size_t)n0 * K };

    float acc[4][4][4];
    #pragma unroll
    for (int i = 0; i < 4; i++)
        #pragma unroll
        for (int j = 0; j < 4; j++)
            #pragma unroll
            for (int q = 0; q < 4; q++) acc[i][j][q] = 0.f;

    const int nChunk = K / 32;

    #pragma unroll
    for (int t = 0; t < 3; t++)
        #pragma unroll
        for (int it = 0; it < 2; it++) {
            int row = crow0 + it * 64;
            cp16(sb + (uint32_t)(t*TILE_B + row*80 + cvv*16),
                 gsrc[t] + (size_t)row * K + cvv*8);
        }
    CP_COMMIT();

    for (int c = 0; c < nChunk; c++) {
        CP_WAIT0();
        __syncthreads();

        if (c + 1 < nChunk) {
            const int k1 = (c + 1) * 32;
            const uint32_t stg = (uint32_t)(((c + 1) & 1) * STAGE_B);
            #pragma unroll
            for (int t = 0; t < 3; t++)
                #pragma unroll
                for (int it = 0; it < 2; it++) {
                    int row = crow0 + it * 64;
                    cp16(sb + stg + (uint32_t)(t*TILE_B + row*80 + cvv*16),
                         gsrc[t] + (size_t)row * K + k1 + cvv*8);
                }
            CP_COMMIT();
        }

        const uint32_t stg = (uint32_t)((c & 1) * STAGE_B);
        const uint32_t aBase = sb + stg + offA;
        const uint32_t bHi = sb + stg + TILE_B + offB;
        const uint32_t bLo = bHi + TILE_B;

        #pragma unroll
        for (int ks = 0; ks < 2; ks++) {
            const uint32_t kb = (uint32_t)(ks * 32);
            uint32_t ah[4][4], bh[2][4], bl[2][4];
            #pragma unroll
            for (int mt = 0; mt < 4; mt++) ldm_x4(ah[mt], aBase + mt * (16*80) + kb);
            ldm_x4(bh[0], bHi + kb);
            ldm_x4(bh[1], bHi + 16*80 + kb);
            ldm_x4(bl[0], bLo + kb);
            ldm_x4(bl[1], bLo + 16*80 + kb);

            #pragma unroll
            for (int mt = 0; mt < 4; mt++)
                #pragma unroll
                for (int nf = 0; nf < 4; nf++) {
                    const int nb = nf >> 1, sel = nf & 1;
                    mma_f32(acc[mt][nf], ah[mt], bh[nb][sel], bh[nb][2+sel]);
                    mma_f32(acc[mt][nf], ah[mt], bl[nb][sel], bl[nb][2+sel]);
                }
        }
    }

    const int g = lane >> 2, t = lane & 3;
    #pragma unroll
    for (int mt = 0; mt < 4; mt++) {
        const int row = m0 + wm*64 + mt*16 + g;
        #pragma unroll
        for (int nf = 0; nf < 4; nf++) {
            const int colg = n0 + wn*32 + nf*8 + t*2;
            if (Cf32) {
                const float b0 = bs0[colg], b1 = bs0[colg+1];
                float2 lo2 = { acc[mt][nf][0] + b0, acc[mt][nf][1] + b1 };
                float2 hi2 = { acc[mt][nf][2] + b0, acc[mt][nf][3] + b1 };
                *(float2*)(Cf32 + (size_t)row * N + colg)       = lo2;
                *(float2*)(Cf32 + (size_t)(row + 8) * N + colg) = hi2;
            } else {
                const int seg = colg >> 10;
                const int col = colg & 1023;
                const float* bp = (seg == 0) ? bs0 : (seg == 1) ? bs1 : bs2;
                const float b0 = bp[col], b1 = bp[col+1];
                float v00 = acc[mt][nf][0] + b0, v01 = acc[mt][nf][1] + b1;
                float v10 = acc[mt][nf][2] + b0, v11 = acc[mt][nf][3] + b1;
                __half2 h0 = __floats2half2_rn(v00, v01);
                __half2 h1 = __floats2half2_rn(v10, v11);
                const size_t o0 = (size_t)row * D_ + col;
                const size_t o1 = (size_t)(row + 8) * D_ + col;
                if (seg == 0) {
                    __half2 l0 = __floats2half2_rn(v00 - __low2float(h0), v01 - __high2float(h0));
                    __half2 l1 = __floats2half2_rn(v10 - __low2float(h1), v11 - __high2float(h1));
                    *(uint32_t*)(oQhi + o0) = *(const uint32_t*)&h0;
                    *(uint32_t*)(oQlo + o0) = *(const uint32_t*)&l0;
                    *(uint32_t*)(oQhi + o1) = *(const uint32_t*)&h1;
                    *(uint32_t*)(oQlo + o1) = *(const uint32_t*)&l1;
                } else if (seg == 1) {
                    *(uint32_t*)(oKhi + o0) = *(const uint32_t*)&h0;
                    *(uint32_t*)(oKhi + o1) = *(const uint32_t*)&h1;
                } else {
                    *(uint32_t*)(oVhi + o0) = *(const uint32_t*)&h0;
                    *(uint32_t*)(oVhi + o1) = *(const uint32_t*)&h1;
                }
            }
        }
    }
}

// ---------------------------------------------------------------------------
// HMMA fused causal attention. V consumed row-major via ldmatrix.trans —
// K and V chunk loads share the identical [256][144B] smem pattern.
// 512 threads; softmax normalize folded into P-convert; streaming attnw.
// ---------------------------------------------------------------------------
#define KST 72     // 144 B rows
#define VST 264    // 528 B rows (P buffers)
#define OFF_KV 131072
#define KVBUF  36864
#define OFF_P  204800
#define OFF_Q  221696
#define SM_ATT 226304

__global__ __launch_bounds__(512)
void attn_hmma(const __half* __restrict__ qhi, const __half* __restrict__ qlo,
               const __half* __restrict__ khi, const __half* __restrict__ vhi,
               float* __restrict__ attnw, __half* __restrict__ aohi)
{
    extern __shared__ char smb[];
    const uint32_t sbm = smem_u32(smb);
    float* rows = (float*)smb;
    __half* Phi = (__half*)(smb + OFF_P);
    __half* Plo = Phi + 16*VST;
    __half* Qhi = (__half*)(smb + OFF_Q);
    __half* Qlo = Qhi + 16*KST;
    float* sinv = (float*)(smb + OFF_Q);         // after Q frags consumed
    float* pbuf = (float*)(smb + OFF_Q + 64);

    const int qt = blockIdx.x, h = blockIdx.y, b = blockIdx.z;
    const int q0 = qt * TQ;
    const int tid  = threadIdx.x;
    const int lane = tid & 31;
    const int wid  = tid >> 5;
    const int nk   = q0 + TQ;
    const int nChunk = (nk + KCA - 1) / KCA;
    const int nkc = nChunk * KCA;
    const float scale = 0.125f;
    const size_t abase = (((size_t)b * H_ + h) * S_ + q0) * (size_t)S_;

    const int sub = lane >> 3, rr = lane & 7;
    const int arow = ((sub & 1) << 3) + rr;
    const int akoff = (sub >> 1) << 4;

    // ---- early zero-fill attnw cols [nkc, S) — drains behind phase 1 ----
    if (nkc < S_) {
        float* zrow = attnw + abase + (size_t)wid * S_;
        for (int j = nkc + lane*4; j < S_; j += 128)
            stg_cs_f4z(zrow + j);
    }

    // ---- Q tile (hi/lo) ----
    {
        const size_t qgb = ((size_t)(b*S_ + q0)) * D_ + h*HD_;
        for (int i = tid; i < 256; i += 512) {
            int which = i >> 7, u = i & 127;
            int token = u >> 3, seg = u & 7;
            const __half* src = (which ? qlo : qhi) + qgb + (size_t)token * D_ + seg*8;
            __half* dst = (which ? Qlo : Qhi) + token*KST + seg*8;
            *(uint4*)dst = *(const uint4*)src;
        }
    }
    __syncthreads();

    uint32_t qfh[4][4], qfl[4][4];
    {
        const uint32_t qa_hi = smem_u32(Qhi) + (uint32_t)(arow*144 + akoff);
        const uint32_t qa_lo = smem_u32(Qlo) + (uint32_t)(arow*144 + akoff);
        #pragma unroll
        for (int ks = 0; ks < 4; ks++) {
            ldm_x4(qfh[ks], qa_hi + ks*32);
            ldm_x4(qfl[ks], qa_lo + ks*32);
        }
    }

    const int gq = lane >> 2, t2 = (lane & 3) << 1;
    const size_t kgb = ((size_t)b*S_) * D_ + h*HD_;   // same base for K and V

    // ---- Phase 1: scores, cp.async double-buffered K ----
    {
        #pragma unroll
        for (int it = 0; it < 4; it++) {            // chunk 0 -> buf 0
            int u = tid + it * 512;
            int token = u >> 3, seg = u & 7;
            cp16(sbm + OFF_KV + (uint32_t)(token*144 + seg*16),
                 khi + kgb + (size_t)token * D_ + seg*8);
        }
        CP_COMMIT();
    }

    for (int c = 0; c < nChunk; c++) {
        CP_WAIT0();
        __syncthreads();

        if (c + 1 < nChunk) {
            const int k1 = (c + 1) * KCA;
            const uint32_t dstb = sbm + OFF_KV + (uint32_t)(((c + 1) & 1) * KVBUF);
            #pragma unroll
            for (int it = 0; it < 4; it++) {
                int u = tid + it * 512;
                int token = u >> 3, seg = u & 7;
                cp16(dstb + (uint32_t)(token*144 + seg*16),
                     khi + kgb + (size_t)(k1 + token) * D_ + seg*8);
            }
            CP_COMMIT();
        }

        const int k0c = c * KCA;
        float sc[2][4];
        uint32_t scc[2][2];
        #pragma unroll
        for (int ns = 0; ns < 2; ns++) {
            #pragma unroll
            for (int j = 0; j < 4; j++) sc[ns][j] = 0.f;
            scc[ns][0] = 0u; scc[ns][1] = 0u;
        }

        if (k0c + wid*16 <= q0 + 15) {          // causal skip
            const uint32_t kbase = sbm + OFF_KV + (uint32_t)((c & 1) * KVBUF)
                                 + (uint32_t)((wid*16 + arow)*144 + akoff);
            #pragma unroll
            for (int ks = 0; ks < 4; ks++) {
                uint32_t kh[4];
                ldm_x4(kh, kbase + ks*32);
                #pragma unroll
                for (int ns = 0; ns < 2; ns++) {
                    mma_f32(sc[ns], qfh[ks], kh[ns], kh[2+ns]);
                    mma_f16(scc[ns], qfl[ks], kh[ns], kh[2+ns]);   // correction
                }
            }
        }

        #pragma unroll
        for (int ns = 0; ns < 2; ns++) {
            corr_merge(sc[ns], scc[ns]);
            const int kg = k0c + wid*16 + ns*8 + t2;
            rows[(size_t)gq*S_ + kg]      = (kg   <= q0+gq) ? sc[ns][0]*scale : -INFINITY;
            rows[(size_t)gq*S_ + kg+1]    = (kg+1 <= q0+gq) ? sc[ns][1]*scale : -INFINITY;
            rows[(size_t)(gq+8)*S_ + kg]  = (kg   <= q0+gq+8) ? sc[ns][2]*scale : -INFINITY;
            rows[(size_t)(gq+8)*S_ + kg+1]= (kg+1 <= q0+gq+8) ? sc[ns][3]*scale : -INFINITY;
        }
    }
    __syncthreads();

    // ---- Phase 2: softmax max + exp/sum; store 1/s, no normalize pass ----
    {
        const int r = wid;
        const int nr = q0 + r + 1;
        float* prow = rows + (size_t)r * S_;
        float m = -INFINITY;
        for (int i = lane; i < nr; i += 32) m = fmaxf(m, prow[i]);
        #pragma unroll
        for (int off = 16; off; off >>= 1) m = fmaxf(m, __shfl_xor_sync(0xffffffffu, m, off));
        float s = 0.f;
        for (int i = lane; i < nkc; i += 32) {
            float e = __expf(prow[i] - m);
            prow[i] = e;
            s += e;
        }
        #pragma unroll
        for (int off = 16; off; off >>= 1) s += __shfl_xor_sync(0xffffffffu, s, off);
        if (lane == 0) sinv[r] = 1.f / s;
    }
    __syncthreads();

    // ---- Phase 4: AV; row-major V via ldmatrix.trans; dbuf V ----
    const int khalf = wid >> 3, ntile = wid & 7;
    const uint32_t pA_hi = smem_u32(Phi) + (uint32_t)(arow*528 + akoff + khalf*256);
    const uint32_t pA_lo = smem_u32(Plo) + (uint32_t)(arow*528 + akoff + khalf*256);

    {
        #pragma unroll
        for (int it = 0; it < 4; it++) {            // chunk 0 -> buf 0
            int u = tid + it * 512;
            int token = u >> 3, seg = u & 7;
            cp16(sbm + OFF_KV + (uint32_t)(token*144 + seg*16),
                 vhi + kgb + (size_t)token * D_ + seg*8);
        }
        CP_COMMIT();
    }

    float oc[4] = {0.f, 0.f, 0.f, 0.f};
    uint32_t occ[2] = {0u, 0u};
    // trans-ldmatrix per-lane row address: token = khalf*128 + ks*16 + (lane&15)
    const uint32_t vlanebase = (uint32_t)((khalf*128 + (lane & 15))*144 + ntile*16);

    for (int c = 0; c < nChunk; c++) {
        const int k0c = c * KCA;
        if (c) __syncthreads();        // prev MMA done with Phi/Plo + prev buf

        // fused: rows -> (attnw streaming store) + (Phi/Plo fp16 convert), normalized
        #pragma unroll
        for (int it = 0; it < 4; it++) {
            int p = tid + it * 512;
            int r = p >> 7, j2 = (p & 127) << 1;
            float inv = sinv[r];
            float v0 = rows[(size_t)r*S_ + k0c + j2] * inv;
            float v1 = rows[(size_t)r*S_ + k0c + j2 + 1] * inv;
            stg_cs_f2(attnw + abase + (size_t)r*S_ + k0c + j2, v0, v1);
            __half2 hb = __floats2half2_rn(v0, v1);
            __half2 lb = __floats2half2_rn(v0 - __low2float(hb), v1 - __high2float(hb));
            *(uint32_t*)(Phi + r*VST + j2) = *(const uint32_t*)&hb;
            *(uint32_t*)(Plo + r*VST + j2) = *(const uint32_t*)&lb;
        }

        CP_WAIT0();
        __syncthreads();               // V + Phi/Plo visible to all

        if (c + 1 < nChunk) {
            const int k1 = (c + 1) * KCA;
            const uint32_t dstb = sbm + OFF_KV + (uint32_t)(((c + 1) & 1) * KVBUF);
            #pragma unroll
            for (int it = 0; it < 4; it++) {
                int u = tid + it * 512;
                int token = u >> 3, seg = u & 7;
                cp16(dstb + (uint32_t)(token*144 + seg*16),
                     vhi + kgb + (size_t)(k1 + token) * D_ + seg*8);
            }
            CP_COMMIT();
        }

        if (k0c + khalf*128 < nk) {               // skip all-zero-P half-chunks
            const uint32_t vbase = sbm + OFF_KV + (uint32_t)((c & 1) * KVBUF) + vlanebase;
            #pragma unroll
            for (int ks = 0; ks < 8; ks++) {
                uint32_t ph[4], pl[4], vh[2];
                ldm_x4(ph, pA_hi + ks*32);
                ldm_x4(pl, pA_lo + ks*32);
                ldm_x2_trans(vh, vbase + (uint32_t)(ks * 16 * 144));
                mma_f32(oc, ph, vh[0], vh[1]);
                mma_f16(occ, pl, vh[0], vh[1]);    // correction
            }
        }
    }
    corr_merge(oc, occ);

    // combine k-halves via pbuf
    __syncthreads();
    if (khalf == 1) {
        pbuf[gq*HD_ + ntile*8 + t2]       = oc[0];
        pbuf[gq*HD_ + ntile*8 + t2 + 1]   = oc[1];
        pbuf[(gq+8)*HD_ + ntile*8 + t2]   = oc[2];
        pbuf[(gq+8)*HD_ + ntile*8 + t2+1] = oc[3];
    }
    __syncthreads();
    if (khalf == 0) {
        const int col = h*HD_ + ntile*8 + t2;
        const size_t o0 = ((size_t)(b*S_ + q0 + gq)) * D_ + col;
        const size_t o1 = ((size_t)(b*S_ + q0 + gq + 8)) * D_ + col;
        float v00 = oc[0] + pbuf[gq*HD_ + ntile*8 + t2];
        float v01 = oc[1] + pbuf[gq*HD_ + ntile*8 + t2 + 1];
        float v10 = oc[2] + pbuf[(gq+8)*HD_ + ntile*8 + t2];
        float v11 = oc[3] + pbuf[(gq+8)*HD_ + ntile*8 + t2 + 1];
        __half2 h0 = __floats2half2_rn(v00, v01);
        __half2 h1 = __floats2half2_rn(v10, v11);
        *(uint32_t*)(aohi + o0) = *(const uint32_t*)&h0;
        *(uint32_t*)(aohi + o1) = *(const uint32_t*)&h1;
    }
}

// ---------------------------------------------------------------------------
extern "C" void kernel_launch(void* const* d_in, const int* in_sizes, int n_in,
                              void* d_out, int out_size)
{
    const float* x  = (const float*)d_in[0];
    const float* Wq = (const float*)d_in[1];
    const float* bq = (const float*)d_in[2];
    const float* Wk = (const float*)d_in[3];
    const float* bk = (const float*)d_in[4];
    const float* Wv = (const float*)d_in[5];
    const float* bv = (const float*)d_in[6];
    const float* Wo = (const float*)d_in[7];
    const float* bo = (const float*)d_in[8];

    float* out   = (float*)d_out;                       // [B,S,D]
    float* attnw = out + (size_t)B_ * S_ * D_;          // [B,H,S,S]

    __half *xhi, *whi, *wlo, *aohi, *qhi, *qlo, *khi, *vhi;
    cudaGetSymbolAddress((void**)&xhi,  g_xhi);
    cudaGetSymbolAddress((void**)&whi,  g_whi);
    cudaGetSymbolAddress((void**)&wlo,  g_wlo);
    cudaGetSymbolAddress((void**)&aohi, g_aohi);
    cudaGetSymbolAddress((void**)&qhi,  g_qhi);
    cudaGetSymbolAddress((void**)&qlo,  g_qlo);
    cudaGetSymbolAddress((void**)&khi,  g_khi);
    cudaGetSymbolAddress((void**)&vhi,  g_vhi);

    const int M = MSZ;               // 4096

    convert_all<<<(NPX4 + NW4)/1024, 256>>>(
        (const float4*)x,
        (const float4*)Wq, (const float4*)Wk, (const float4*)Wv, (const float4*)Wo,
        (uint2*)xhi, (uint2*)whi, (uint2*)wlo);

    cudaFuncSetAttribute(gemm2, cudaFuncAttributeMaxDynamicSharedMemorySize, SM_GEMM);

    // fused QKV: N = 3072 (Wq|Wk|Wv stacked in whi/wlo)
    {
        dim3 g(3072/128, M/128);     // (24, 32)
        gemm2<<<g, 256, SM_GEMM>>>(xhi, whi, wlo, bq, bk, bv,
                                   nullptr, qhi, qlo, khi, vhi, M, 3072, D_);
    }

    cudaFuncSetAttribute(attn_hmma, cudaFuncAttributeMaxDynamicSharedMemorySize, SM_ATT);
    dim3 attn_grid(S_ / TQ, H_, B_);
    attn_hmma<<<attn_grid, 512, SM_ATT>>>(qhi, qlo, khi, vhi, attnw, aohi);

    // output projection
    {
        dim3 g(D_/128, M/128);       // (8, 32)
        gemm2<<<g, 256, SM_GEMM>>>(aohi, whi + 3*(size_t)WSZ, wlo + 3*(size_t)WSZ,
                                   bo, nullptr, nullptr, out,
                                   nullptr, nullptr, nullptr, nullptr, M, D_, D_);
    }
}

// round 13
// speedup vs baseline: 1.8276x; 1.1191x over previous
#include <cuda_runtime.h>
#include <cuda_fp16.h>
#include <math.h>
#include <stdint.h>

#define B_  2
#define S_  2048
#define D_  1024
#define H_  16
#define HD_ 64

#define TQ  16
#define KCA 256              // attention key-chunk

#define MSZ (B_*S_)          // 4096 rows
#define WSZ (D_*D_)

// ---------------------------------------------------------------------------
// Scratch (allocation-free rule: __device__ globals)
// ---------------------------------------------------------------------------
__device__ __half g_xhi [MSZ*D_];
__device__ __half g_whi [4*D_*D_];   // Wq, Wk, Wv, Wo stacked
__device__ __half g_wlo [3*D_*D_];   // lo terms for Wq, Wk, Wv only
__device__ __half g_aohi[MSZ*D_];
__device__ __half g_qhi [MSZ*D_];
__device__ __half g_qlo [MSZ*D_];
__device__ __half g_khi [MSZ*D_];
__device__ __half g_vhi [MSZ*D_];    // v row-major fp16 (consumed via ldmatrix.trans)

// ---------------------------------------------------------------------------
// Fused convert: x -> fp16 hi; W -> fp16 hi (all 4) + lo (first 3). MLP=4.
// ---------------------------------------------------------------------------
#define NPX4 (MSZ*D_/4)              // 1048576 float4 of x
#define NW4  (4*WSZ/4)               // 1048576 float4 of W

__global__ __launch_bounds__(256)
void convert_all(const float4* __restrict__ x,
                 const float4* __restrict__ w0, const float4* __restrict__ w1,
                 const float4* __restrict__ w2, const float4* __restrict__ w3,
                 uint2* __restrict__ xhi, uint2* __restrict__ whi,
                 uint2* __restrict__ wlo)
{
    const int base = blockIdx.x * 1024 + threadIdx.x;
    float4 v[4];
    #pragma unroll
    for (int j = 0; j < 4; j++) {
        int i = base + j*256;
        if (i < NPX4) {
            v[j] = x[i];
        } else {
            int k = i - NPX4;
            int which = k >> 18;             // WSZ/4 = 262144
            int idx = k & 262143;
            const float4* src = (which == 0) ? w0 : (which == 1) ? w1
                              : (which == 2) ? w2 : w3;
            v[j] = src[idx];
        }
    }
    #pragma unroll
    for (int j = 0; j < 4; j++) {
        int i = base + j*256;
        __half2 h0 = __floats2half2_rn(v[j].x, v[j].y);
        __half2 h1 = __floats2half2_rn(v[j].z, v[j].w);
        uint2 H;
        H.x = *(const uint32_t*)&h0; H.y = *(const uint32_t*)&h1;
        if (i < NPX4) {
            xhi[i] = H;
        } else {
            int k = i - NPX4;
            whi[k] = H;
            if (k < 3*(WSZ/4)) {             // lo only for Wq/Wk/Wv
                __half2 l0 = __floats2half2_rn(v[j].x - __low2float(h0), v[j].y - __high2float(h0));
                __half2 l1 = __floats2half2_rn(v[j].z - __low2float(h1), v[j].w - __high2float(h1));
                uint2 L;
                L.x = *(const uint32_t*)&l0; L.y = *(const uint32_t*)&l1;
                wlo[k] = L;
            }
        }
    }
}

// ---------------------------------------------------------------------------
// PTX helpers (non-variant ISA)
// ---------------------------------------------------------------------------
__device__ __forceinline__ uint32_t smem_u32(const void* p) {
    uint32_t a;
    asm("{ .reg .u64 t; cvta.to.shared.u64 t, %1; cvt.u32.u64 %0, t; }" : "=r"(a) : "l"(p));
    return a;
}
__device__ __forceinline__ void ldm_x4(uint32_t* r, uint32_t addr) {
    asm volatile("ldmatrix.sync.aligned.m8n8.x4.shared.b16 {%0,%1,%2,%3}, [%4];"
        : "=r"(r[0]), "=r"(r[1]), "=r"(r[2]), "=r"(r[3]) : "r"(addr));
}
__device__ __forceinline__ void ldm_x2_trans(uint32_t* r, uint32_t addr) {
    asm volatile("ldmatrix.sync.aligned.m8n8.x2.trans.shared.b16 {%0,%1}, [%2];"
        : "=r"(r[0]), "=r"(r[1]) : "r"(addr));
}
__device__ __forceinline__ void mma_f32(float* c, const uint32_t* a,
                                        uint32_t b0, uint32_t b1) {
    asm volatile(
        "mma.sync.aligned.m16n8k16.row.col.f32.f16.f16.f32 "
        "{%0,%1,%2,%3}, {%4,%5,%6,%7}, {%8,%9}, {%0,%1,%2,%3};"
        : "+f"(c[0]), "+f"(c[1]), "+f"(c[2]), "+f"(c[3])
        : "r"(a[0]), "r"(a[1]), "r"(a[2]), "r"(a[3]), "r"(b0), "r"(b1));
}
// fp16 accumulate (score correction term)
__device__ __forceinline__ void mma_f16(uint32_t* c, const uint32_t* a,
                                        uint32_t b0, uint32_t b1) {
    asm volatile(
        "mma.sync.aligned.m16n8k16.row.col.f16.f16.f16.f16 "
        "{%0,%1}, {%2,%3,%4,%5}, {%6,%7}, {%0,%1};"
        : "+r"(c[0]), "+r"(c[1])
        : "r"(a[0]), "r"(a[1]), "r"(a[2]), "r"(a[3]), "r"(b0), "r"(b1));
}
__device__ __forceinline__ void corr_merge(float* c, const uint32_t* cc) {
    __half2 h0 = *(const __half2*)&cc[0];
    __half2 h1 = *(const __half2*)&cc[1];
    c[0] += __low2float(h0); c[1] += __high2float(h0);
    c[2] += __low2float(h1); c[3] += __high2float(h1);
}
__device__ __forceinline__ void cp16(uint32_t dst, const void* src) {
    asm volatile("cp.async.cg.shared.global [%0], [%1], 16;" :: "r"(dst), "l"(src));
}
#define CP_COMMIT() asm volatile("cp.async.commit_group;" ::: "memory")
#define CP_WAIT0()  asm volatile("cp.async.wait_group 0;" ::: "memory")
__device__ __forceinline__ void stg_cs_f2(float* p, float a, float b) {
    asm volatile("st.global.cs.v2.f32 [%0], {%1,%2};" :: "l"(p), "f"(a), "f"(b) : "memory");
}
__device__ __forceinline__ void stg_cs_f4z(float* p) {
    asm volatile("st.global.cs.v4.f32 [%0], {%1,%1,%1,%1};" :: "l"(p), "f"(0.f) : "memory");
}

// ---------------------------------------------------------------------------
// HMMA GEMM: C = A @ (Whi [+ Wlo])^T + bias. TWOB selects 2-term vs 1-term.
// ---------------------------------------------------------------------------
#define LDT 40
#define TILE_B   (128*LDT*2)         // 10240 bytes
#define STAGE_B  (3*TILE_B)          // 30720 bytes
#define SM_GEMM  (2*STAGE_B)         // 61440 bytes

template<bool TWOB>
__global__ __launch_bounds__(256, 2)
void gemm2(const __half* __restrict__ A,
           const __half* __restrict__ Bhi, const __half* __restrict__ Blo,
           const float* __restrict__ bs0, const float* __restrict__ bs1,
           const float* __restrict__ bs2,
           float* __restrict__ Cf32,
           __half* __restrict__ oQhi, __half* __restrict__ oQlo,
           __half* __restrict__ oKhi, __half* __restrict__ oVhi,
           int M, int N, int K)
{
    extern __shared__ __half dsm[];
    const uint32_t sb = smem_u32(dsm);

    const int tid = threadIdx.x;
    const int lane = tid & 31;
    const int wid  = tid >> 5;
    const int wm = wid & 1;
    const int wn = wid >> 1;
    const int m0 = blockIdx.y * 128;
    const int n0 = blockIdx.x * 128;

    const int sub = lane >> 3, rr = lane & 7;
    const int rowoff = ((sub & 1) << 3) + rr;
    const int koffb  = (sub >> 1) << 4;

    const uint32_t offA = (uint32_t)((wm*64 + rowoff) * 80 + koffb);
    const uint32_t offB = (uint32_t)((wn*32 + rowoff) * 80 + koffb);

    const int crow0 = tid >> 2, cvv = tid & 3;
    const int NT = TWOB ? 3 : 2;
    const __half* gsrc[3] = {
        A + (size_t)m0 * K, Bhi + (size_t)n0 * K,
        TWOB ? Blo + (size_t)n0 * K : Bhi + (size_t)n0 * K };

    float acc[4][4][4];
    #pragma unroll
    for (int i = 0; i < 4; i++)
        #pragma unroll
        for (int j = 0; j < 4; j++)
            #pragma unroll
            for (int q = 0; q < 4; q++) acc[i][j][q] = 0.f;

    const int nChunk = K / 32;

    for (int t = 0; t < NT; t++)
        #pragma unroll
        for (int it = 0; it < 2; it++) {
            int row = crow0 + it * 64;
            cp16(sb + (uint32_t)(t*TILE_B + row*80 + cvv*16),
                 gsrc[t] + (size_t)row * K + cvv*8);
        }
    CP_COMMIT();

    for (int c = 0; c < nChunk; c++) {
        CP_WAIT0();
        __syncthreads();

        if (c + 1 < nChunk) {
            const int k1 = (c + 1) * 32;
            const uint32_t stg = (uint32_t)(((c + 1) & 1) * STAGE_B);
            for (int t = 0; t < NT; t++)
                #pragma unroll
                for (int it = 0; it < 2; it++) {
                    int row = crow0 + it * 64;
                    cp16(sb + stg + (uint32_t)(t*TILE_B + row*80 + cvv*16),
                         gsrc[t] + (size_t)row * K + k1 + cvv*8);
                }
            CP_COMMIT();
        }

        const uint32_t stg = (uint32_t)((c & 1) * STAGE_B);
        const uint32_t aBase = sb + stg + offA;
        const uint32_t bHi = sb + stg + TILE_B + offB;
        const uint32_t bLo = bHi + TILE_B;

        #pragma unroll
        for (int ks = 0; ks < 2; ks++) {
            const uint32_t kb = (uint32_t)(ks * 32);
            uint32_t ah[4][4], bh[2][4], bl[2][4];
            #pragma unroll
            for (int mt = 0; mt < 4; mt++) ldm_x4(ah[mt], aBase + mt * (16*80) + kb);
            ldm_x4(bh[0], bHi + kb);
            ldm_x4(bh[1], bHi + 16*80 + kb);
            if (TWOB) {
                ldm_x4(bl[0], bLo + kb);
                ldm_x4(bl[1], bLo + 16*80 + kb);
            }

            #pragma unroll
            for (int mt = 0; mt < 4; mt++)
                #pragma unroll
                for (int nf = 0; nf < 4; nf++) {
                    const int nb = nf >> 1, sel = nf & 1;
                    mma_f32(acc[mt][nf], ah[mt], bh[nb][sel], bh[nb][2+sel]);
                    if (TWOB)
                        mma_f32(acc[mt][nf], ah[mt], bl[nb][sel], bl[nb][2+sel]);
                }
        }
    }

    const int g = lane >> 2, t = lane & 3;
    #pragma unroll
    for (int mt = 0; mt < 4; mt++) {
        const int row = m0 + wm*64 + mt*16 + g;
        #pragma unroll
        for (int nf = 0; nf < 4; nf++) {
            const int colg = n0 + wn*32 + nf*8 + t*2;
            if (Cf32) {
                const float b0 = bs0[colg], b1 = bs0[colg+1];
                float2 lo2 = { acc[mt][nf][0] + b0, acc[mt][nf][1] + b1 };
                float2 hi2 = { acc[mt][nf][2] + b0, acc[mt][nf][3] + b1 };
                *(float2*)(Cf32 + (size_t)row * N + colg)       = lo2;
                *(float2*)(Cf32 + (size_t)(row + 8) * N + colg) = hi2;
            } else {
                const int seg = colg >> 10;
                const int col = colg & 1023;
                const float* bp = (seg == 0) ? bs0 : (seg == 1) ? bs1 : bs2;
                const float b0 = bp[col], b1 = bp[col+1];
                float v00 = acc[mt][nf][0] + b0, v01 = acc[mt][nf][1] + b1;
                float v10 = acc[mt][nf][2] + b0, v11 = acc[mt][nf][3] + b1;
                __half2 h0 = __floats2half2_rn(v00, v01);
                __half2 h1 = __floats2half2_rn(v10, v11);
                const size_t o0 = (size_t)row * D_ + col;
                const size_t o1 = (size_t)(row + 8) * D_ + col;
                if (seg == 0) {
                    __half2 l0 = __floats2half2_rn(v00 - __low2float(h0), v01 - __high2float(h0));
                    __half2 l1 = __floats2half2_rn(v10 - __low2float(h1), v11 - __high2float(h1));
                    *(uint32_t*)(oQhi + o0) = *(const uint32_t*)&h0;
                    *(uint32_t*)(oQlo + o0) = *(const uint32_t*)&l0;
                    *(uint32_t*)(oQhi + o1) = *(const uint32_t*)&h1;
                    *(uint32_t*)(oQlo + o1) = *(const uint32_t*)&l1;
                } else if (seg == 1) {
                    *(uint32_t*)(oKhi + o0) = *(const uint32_t*)&h0;
                    *(uint32_t*)(oKhi + o1) = *(const uint32_t*)&h1;
                } else {
                    *(uint32_t*)(oVhi + o0) = *(const uint32_t*)&h0;
                    *(uint32_t*)(oVhi + o1) = *(const uint32_t*)&h1;
                }
            }
        }
    }
}

// ---------------------------------------------------------------------------
// HMMA fused causal attention. Scores: 2-term (Qhi+Qlo)*K. AV: 1-term Phi*V.
// V row-major via ldmatrix.trans. 512 threads.
// ---------------------------------------------------------------------------
#define KST 72     // 144 B rows
#define VST 264    // 528 B rows (P buffer)
#define OFF_KV 131072
#define KVBUF  36864
#define OFF_P  204800
#define OFF_Q  221696
#define SM_ATT 226304

__global__ __launch_bounds__(512)
void attn_hmma(const __half* __restrict__ qhi, const __half* __restrict__ qlo,
               const __half* __restrict__ khi, const __half* __restrict__ vhi,
               float* __restrict__ attnw, __half* __restrict__ aohi)
{
    extern __shared__ char smb[];
    const uint32_t sbm = smem_u32(smb);
    float* rows = (float*)smb;
    __half* Phi = (__half*)(smb + OFF_P);
    __half* Qhi = (__half*)(smb + OFF_Q);
    __half* Qlo = Qhi + 16*KST;
    float* sinv = (float*)(smb + OFF_Q);         // after Q frags consumed
    float* pbuf = (float*)(smb + OFF_Q + 64);

    const int qt = blockIdx.x, h = blockIdx.y, b = blockIdx.z;
    const int q0 = qt * TQ;
    const int tid  = threadIdx.x;
    const int lane = tid & 31;
    const int wid  = tid >> 5;
    const int nk   = q0 + TQ;
    const int nChunk = (nk + KCA - 1) / KCA;
    const int nkc = nChunk * KCA;
    const float scale = 0.125f;
    const size_t abase = (((size_t)b * H_ + h) * S_ + q0) * (size_t)S_;

    const int sub = lane >> 3, rr = lane & 7;
    const int arow = ((sub & 1) << 3) + rr;
    const int akoff = (sub >> 1) << 4;

    // ---- early zero-fill attnw cols [nkc, S) — drains behind phase 1 ----
    if (nkc < S_) {
        float* zrow = attnw + abase + (size_t)wid * S_;
        for (int j = nkc + lane*4; j < S_; j += 128)
            stg_cs_f4z(zrow + j);
    }

    // ---- Q tile (hi/lo) ----
    {
        const size_t qgb = ((size_t)(b*S_ + q0)) * D_ + h*HD_;
        for (int i = tid; i < 256; i += 512) {
            int which = i >> 7, u = i & 127;
            int token = u >> 3, seg = u & 7;
            const __half* src = (which ? qlo : qhi) + qgb + (size_t)token * D_ + seg*8;
            __half* dst = (which ? Qlo : Qhi) + token*KST + seg*8;
            *(uint4*)dst = *(const uint4*)src;
        }
    }
    __syncthreads();

    uint32_t qfh[4][4], qfl[4][4];
    {
        const uint32_t qa_hi = smem_u32(Qhi) + (uint32_t)(arow*144 + akoff);
        const uint32_t qa_lo = smem_u32(Qlo) + (uint32_t)(arow*144 + akoff);
        #pragma unroll
        for (int ks = 0; ks < 4; ks++) {
            ldm_x4(qfh[ks], qa_hi + ks*32);
            ldm_x4(qfl[ks], qa_lo + ks*32);
        }
    }

    const int gq = lane >> 2, t2 = (lane & 3) << 1;
    const size_t kgb = ((size_t)b*S_) * D_ + h*HD_;   // same base for K and V

    // ---- Phase 1: scores, cp.async double-buffered K ----
    {
        #pragma unroll
        for (int it = 0; it < 4; it++) {            // chunk 0 -> buf 0
            int u = tid + it * 512;
            int token = u >> 3, seg = u & 7;
            cp16(sbm + OFF_KV + (uint32_t)(token*144 + seg*16),
                 khi + kgb + (size_t)token * D_ + seg*8);
        }
        CP_COMMIT();
    }

    for (int c = 0; c < nChunk; c++) {
        CP_WAIT0();
        __syncthreads();

        if (c + 1 < nChunk) {
            const int k1 = (c + 1) * KCA;
            const uint32_t dstb = sbm + OFF_KV + (uint32_t)(((c + 1) & 1) * KVBUF);
            #pragma unroll
            for (int it = 0; it < 4; it++) {
                int u = tid + it * 512;
                int token = u >> 3, seg = u & 7;
                cp16(dstb + (uint32_t)(token*144 + seg*16),
                     khi + kgb + (size_t)(k1 + token) * D_ + seg*8);
            }
            CP_COMMIT();
        }

        const int k0c = c * KCA;
        float sc[2][4];
        uint32_t scc[2][2];
        #pragma unroll
        for (int ns = 0; ns < 2; ns++) {
            #pragma unroll
            for (int j = 0; j < 4; j++) sc[ns][j] = 0.f;
            scc[ns][0] = 0u; scc[ns][1] = 0u;
        }

        if (k0c + wid*16 <= q0 + 15) {          // causal skip
            const uint32_t kbase = sbm + OFF_KV + (uint32_t)((c & 1) * KVBUF)
                                 + (uint32_t)((wid*16 + arow)*144 + akoff);
            #pragma unroll
            for (int ks = 0; ks < 4; ks++) {
                uint32_t kh[4];
                ldm_x4(kh, kbase + ks*32);
                #pragma unroll
                for (int ns = 0; ns < 2; ns++) {
                    mma_f32(sc[ns], qfh[ks], kh[ns], kh[2+ns]);
                    mma_f16(scc[ns], qfl[ks], kh[ns], kh[2+ns]);   // correction
                }
            }
        }

        #pragma unroll
        for (int ns = 0; ns < 2; ns++) {
            corr_merge(sc[ns], scc[ns]);
            const int kg = k0c + wid*16 + ns*8 + t2;
            rows[(size_t)gq*S_ + kg]      = (kg   <= q0+gq) ? sc[ns][0]*scale : -INFINITY;
            rows[(size_t)gq*S_ + kg+1]    = (kg+1 <= q0+gq) ? sc[ns][1]*scale : -INFINITY;
            rows[(size_t)(gq+8)*S_ + kg]  = (kg   <= q0+gq+8) ? sc[ns][2]*scale : -INFINITY;
            rows[(size_t)(gq+8)*S_ + kg+1]= (kg+1 <= q0+gq+8) ? sc[ns][3]*scale : -INFINITY;
        }
    }
    __syncthreads();

    // ---- Phase 2: softmax max + exp/sum; store 1/s, no normalize pass ----
    {
        const int r = wid;
        const int nr = q0 + r + 1;
        float* prow = rows + (size_t)r * S_;
        float m = -INFINITY;
        for (int i = lane; i < nr; i += 32) m = fmaxf(m, prow[i]);
        #pragma unroll
        for (int off = 16; off; off >>= 1) m = fmaxf(m, __shfl_xor_sync(0xffffffffu, m, off));
        float s = 0.f;
        for (int i = lane; i < nkc; i += 32) {
            float e = __expf(prow[i] - m);
            prow[i] = e;
            s += e;
        }
        #pragma unroll
        for (int off = 16; off; off >>= 1) s += __shfl_xor_sync(0xffffffffu, s, off);
        if (lane == 0) sinv[r] = 1.f / s;
    }
    __syncthreads();

    // ---- Phase 4: AV (1-term); row-major V via ldmatrix.trans; dbuf V ----
    const int khalf = wid >> 3, ntile = wid & 7;
    const uint32_t pA_hi = smem_u32(Phi) + (uint32_t)(arow*528 + akoff + khalf*256);

    {
        #pragma unroll
        for (int it = 0; it < 4; it++) {            // chunk 0 -> buf 0
            int u = tid + it * 512;
            int token = u >> 3, seg = u & 7;
            cp16(sbm + OFF_KV + (uint32_t)(token*144 + seg*16),
                 vhi + kgb + (size_t)token * D_ + seg*8);
        }
        CP_COMMIT();
    }

    float oc[4] = {0.f, 0.f, 0.f, 0.f};
    const uint32_t vlanebase = (uint32_t)((khalf*128 + (lane & 15))*144 + ntile*16);

    for (int c = 0; c < nChunk; c++) {
        const int k0c = c * KCA;
        if (c) __syncthreads();        // prev MMA done with Phi + prev buf

        // fused: rows -> (attnw streaming store) + (Phi fp16 convert), normalized
        #pragma unroll
        for (int it = 0; it < 4; it++) {
            int p = tid + it * 512;
            int r = p >> 7, j2 = (p & 127) << 1;
            float inv = sinv[r];
            float v0 = rows[(size_t)r*S_ + k0c + j2] * inv;
            float v1 = rows[(size_t)r*S_ + k0c + j2 + 1] * inv;
            stg_cs_f2(attnw + abase + (size_t)r*S_ + k0c + j2, v0, v1);
            __half2 hb = __floats2half2_rn(v0, v1);
            *(uint32_t*)(Phi + r*VST + j2) = *(const uint32_t*)&hb;
        }

        CP_WAIT0();
        __syncthreads();               // V + Phi visible to all

        if (c + 1 < nChunk) {
            const int k1 = (c + 1) * KCA;
            const uint32_t dstb = sbm + OFF_KV + (uint32_t)(((c + 1) & 1) * KVBUF);
            #pragma unroll
            for (int it = 0; it < 4; it++) {
                int u = tid + it * 512;
                int token = u >> 3, seg = u & 7;
                cp16(dstb + (uint32_t)(token*144 + seg*16),
                     vhi + kgb + (size_t)(k1 + token) * D_ + seg*8);
            }
            CP_COMMIT();
        }

        if (k0c + khalf*128 < nk) {               // skip all-zero-P half-chunks
            const uint32_t vbase = sbm + OFF_KV + (uint32_t)((c & 1) * KVBUF) + vlanebase;
            #pragma unroll
            for (int ks = 0; ks < 8; ks++) {
                uint32_t ph[4], vh[2];
                ldm_x4(ph, pA_hi + ks*32);
                ldm_x2_trans(vh, vbase + (uint32_t)(ks * 16 * 144));
                mma_f32(oc, ph, vh[0], vh[1]);
            }
        }
    }

    // combine k-halves via pbuf
    __syncthreads();
    if (khalf == 1) {
        pbuf[gq*HD_ + ntile*8 + t2]       = oc[0];
        pbuf[gq*HD_ + ntile*8 + t2 + 1]   = oc[1];
        pbuf[(gq+8)*HD_ + ntile*8 + t2]   = oc[2];
        pbuf[(gq+8)*HD_ + ntile*8 + t2+1] = oc[3];
    }
    __syncthreads();
    if (khalf == 0) {
        const int col = h*HD_ + ntile*8 + t2;
        const size_t o0 = ((size_t)(b*S_ + q0 + gq)) * D_ + col;
        const size_t o1 = ((size_t)(b*S_ + q0 + gq + 8)) * D_ + col;
        float v00 = oc[0] + pbuf[gq*HD_ + ntile*8 + t2];
        float v01 = oc[1] + pbuf[gq*HD_ + ntile*8 + t2 + 1];
        float v10 = oc[2] + pbuf[(gq+8)*HD_ + ntile*8 + t2];
        float v11 = oc[3] + pbuf[(gq+8)*HD_ + ntile*8 + t2 + 1];
        __half2 h0 = __floats2half2_rn(v00, v01);
        __half2 h1 = __floats2half2_rn(v10, v11);
        *(uint32_t*)(aohi + o0) = *(const uint32_t*)&h0;
        *(uint32_t*)(aohi + o1) = *(const uint32_t*)&h1;
    }
}

// ---------------------------------------------------------------------------
extern "C" void kernel_launch(void* const* d_in, const int* in_sizes, int n_in,
                              void* d_out, int out_size)
{
    const float* x  = (const float*)d_in[0];
    const float* Wq = (const float*)d_in[1];
    const float* bq = (const float*)d_in[2];
    const float* Wk = (const float*)d_in[3];
    const float* bk = (const float*)d_in[4];
    const float* Wv = (const float*)d_in[5];
    const float* bv = (const float*)d_in[6];
    const float* Wo = (const float*)d_in[7];
    const float* bo = (const float*)d_in[8];

    float* out   = (float*)d_out;                       // [B,S,D]
    float* attnw = out + (size_t)B_ * S_ * D_;          // [B,H,S,S]

    __half *xhi, *whi, *wlo, *aohi, *qhi, *qlo, *khi, *vhi;
    cudaGetSymbolAddress((void**)&xhi,  g_xhi);
    cudaGetSymbolAddress((void**)&whi,  g_whi);
    cudaGetSymbolAddress((void**)&wlo,  g_wlo);
    cudaGetSymbolAddress((void**)&aohi, g_aohi);
    cudaGetSymbolAddress((void**)&qhi,  g_qhi);
    cudaGetSymbolAddress((void**)&qlo,  g_qlo);
    cudaGetSymbolAddress((void**)&khi,  g_khi);
    cudaGetSymbolAddress((void**)&vhi,  g_vhi);

    const int M = MSZ;               // 4096

    convert_all<<<(NPX4 + NW4)/1024, 256>>>(
        (const float4*)x,
        (const float4*)Wq, (const float4*)Wk, (const float4*)Wv, (const float4*)Wo,
        (uint2*)xhi, (uint2*)whi, (uint2*)wlo);

    cudaFuncSetAttribute(gemm2<true>,  cudaFuncAttributeMaxDynamicSharedMemorySize, SM_GEMM);
    cudaFuncSetAttribute(gemm2<false>, cudaFuncAttributeMaxDynamicSharedMemorySize, SM_GEMM);

    // fused QKV: N = 3072 (Wq|Wk|Wv stacked in whi/wlo), 2-term
    {
        dim3 g(3072/128, M/128);     // (24, 32)
        gemm2<true><<<g, 256, SM_GEMM>>>(xhi, whi, wlo, bq, bk, bv,
                                         nullptr, qhi, qlo, khi, vhi, M, 3072, D_);
    }

    cudaFuncSetAttribute(attn_hmma, cudaFuncAttributeMaxDynamicSharedMemorySize, SM_ATT);
    dim3 attn_grid(S_ / TQ, H_, B_);
    attn_hmma<<<attn_grid, 512, SM_ATT>>>(qhi, qlo, khi, vhi, attnw, aohi);

    // output projection: 1-term (Wo hi only)
    {
        dim3 g(D_/128, M/128);       // (8, 32)
        gemm2<false><<<g, 256, SM_GEMM>>>(aohi, whi + 3*(size_t)WSZ, nullptr,
                                          bo, nullptr, nullptr, out,
                                          nullptr, nullptr, nullptr, nullptr, M, D_, D_);
    }
}

// round 14
// speedup vs baseline: 1.8765x; 1.0267x over previous
#include <cuda_runtime.h>
#include <cuda_fp16.h>
#include <math.h>
#include <stdint.h>

#define B_  2
#define S_  2048
#define D_  1024
#define H_  16
#define HD_ 64

#define TQ  16
#define KCA 256              // attention key-chunk

#define MSZ (B_*S_)          // 4096 rows
#define WSZ (D_*D_)

// ---------------------------------------------------------------------------
// Scratch (allocation-free rule: __device__ globals)
// ---------------------------------------------------------------------------
__device__ __half g_xhi [MSZ*D_];
__device__ __half g_whi [4*D_*D_];   // Wq, Wk, Wv, Wo stacked
__device__ __half g_wlo [D_*D_];     // lo term for Wq only
__device__ __half g_aohi[MSZ*D_];
__device__ __half g_qhi [MSZ*D_];
__device__ __half g_qlo [MSZ*D_];
__device__ __half g_khi [MSZ*D_];
__device__ __half g_vhi [MSZ*D_];    // v row-major fp16 (consumed via ldmatrix.trans)

// ---------------------------------------------------------------------------
// Fused convert: x -> fp16 hi; W -> fp16 hi (all 4) + lo (Wq only). MLP=4.
// ---------------------------------------------------------------------------
#define NPX4 (MSZ*D_/4)              // 1048576 float4 of x
#define NW4  (4*WSZ/4)               // 1048576 float4 of W

__global__ __launch_bounds__(256)
void convert_all(const float4* __restrict__ x,
                 const float4* __restrict__ w0, const float4* __restrict__ w1,
                 const float4* __restrict__ w2, const float4* __restrict__ w3,
                 uint2* __restrict__ xhi, uint2* __restrict__ whi,
                 uint2* __restrict__ wlo)
{
    const int base = blockIdx.x * 1024 + threadIdx.x;
    float4 v[4];
    #pragma unroll
    for (int j = 0; j < 4; j++) {
        int i = base + j*256;
        if (i < NPX4) {
            v[j] = x[i];
        } else {
            int k = i - NPX4;
            int which = k >> 18;             // WSZ/4 = 262144
            int idx = k & 262143;
            const float4* src = (which == 0) ? w0 : (which == 1) ? w1
                              : (which == 2) ? w2 : w3;
            v[j] = src[idx];
        }
    }
    #pragma unroll
    for (int j = 0; j < 4; j++) {
        int i = base + j*256;
        __half2 h0 = __floats2half2_rn(v[j].x, v[j].y);
        __half2 h1 = __floats2half2_rn(v[j].z, v[j].w);
        uint2 H;
        H.x = *(const uint32_t*)&h0; H.y = *(const uint32_t*)&h1;
        if (i < NPX4) {
            xhi[i] = H;
        } else {
            int k = i - NPX4;
            whi[k] = H;
            if (k < (WSZ/4)) {               // lo only for Wq
                __half2 l0 = __floats2half2_rn(v[j].x - __low2float(h0), v[j].y - __high2float(h0));
                __half2 l1 = __floats2half2_rn(v[j].z - __low2float(h1), v[j].w - __high2float(h1));
                uint2 L;
                L.x = *(const uint32_t*)&l0; L.y = *(const uint32_t*)&l1;
                wlo[k] = L;
            }
        }
    }
}

// ---------------------------------------------------------------------------
// PTX helpers (non-variant ISA)
// ---------------------------------------------------------------------------
__device__ __forceinline__ uint32_t smem_u32(const void* p) {
    uint32_t a;
    asm("{ .reg .u64 t; cvta.to.shared.u64 t, %1; cvt.u32.u64 %0, t; }" : "=r"(a) : "l"(p));
    return a;
}
__device__ __forceinline__ void ldm_x4(uint32_t* r, uint32_t addr) {
    asm volatile("ldmatrix.sync.aligned.m8n8.x4.shared.b16 {%0,%1,%2,%3}, [%4];"
        : "=r"(r[0]), "=r"(r[1]), "=r"(r[2]), "=r"(r[3]) : "r"(addr));
}
__device__ __forceinline__ void ldm_x2_trans(uint32_t* r, uint32_t addr) {
    asm volatile("ldmatrix.sync.aligned.m8n8.x2.trans.shared.b16 {%0,%1}, [%2];"
        : "=r"(r[0]), "=r"(r[1]) : "r"(addr));
}
__device__ __forceinline__ void mma_f32(float* c, const uint32_t* a,
                                        uint32_t b0, uint32_t b1) {
    asm volatile(
        "mma.sync.aligned.m16n8k16.row.col.f32.f16.f16.f32 "
        "{%0,%1,%2,%3}, {%4,%5,%6,%7}, {%8,%9}, {%0,%1,%2,%3};"
        : "+f"(c[0]), "+f"(c[1]), "+f"(c[2]), "+f"(c[3])
        : "r"(a[0]), "r"(a[1]), "r"(a[2]), "r"(a[3]), "r"(b0), "r"(b1));
}
// fp16 accumulate (score correction term)
__device__ __forceinline__ void mma_f16(uint32_t* c, const uint32_t* a,
                                        uint32_t b0, uint32_t b1) {
    asm volatile(
        "mma.sync.aligned.m16n8k16.row.col.f16.f16.f16.f16 "
        "{%0,%1}, {%2,%3,%4,%5}, {%6,%7}, {%0,%1};"
        : "+r"(c[0]), "+r"(c[1])
        : "r"(a[0]), "r"(a[1]), "r"(a[2]), "r"(a[3]), "r"(b0), "r"(b1));
}
__device__ __forceinline__ void corr_merge(float* c, const uint32_t* cc) {
    __half2 h0 = *(const __half2*)&cc[0];
    __half2 h1 = *(const __half2*)&cc[1];
    c[0] += __low2float(h0); c[1] += __high2float(h0);
    c[2] += __low2float(h1); c[3] += __high2float(h1);
}
__device__ __forceinline__ void cp16(uint32_t dst, const void* src) {
    asm volatile("cp.async.cg.shared.global [%0], [%1], 16;" :: "r"(dst), "l"(src));
}
#define CP_COMMIT() asm volatile("cp.async.commit_group;" ::: "memory")
#define CP_WAIT0()  asm volatile("cp.async.wait_group 0;" ::: "memory")
__device__ __forceinline__ void stg_cs_f2(float* p, float a, float b) {
    asm volatile("st.global.cs.v2.f32 [%0], {%1,%2};" :: "l"(p), "f"(a), "f"(b) : "memory");
}
__device__ __forceinline__ void stg_cs_f4z(float* p) {
    asm volatile("st.global.cs.v4.f32 [%0], {%1,%1,%1,%1};" :: "l"(p), "f"(0.f) : "memory");
}

// ---------------------------------------------------------------------------
// HMMA GEMM: C = A @ (Whi [+ Wlo])^T + bias.
// 2-term only for output cols < twob_limit (uniform per 128-col CTA tile).
// ---------------------------------------------------------------------------
#define LDT 40
#define TILE_B   (128*LDT*2)         // 10240 bytes
#define STAGE_B  (3*TILE_B)          // 30720 bytes
#define SM_GEMM  (2*STAGE_B)         // 61440 bytes

__global__ __launch_bounds__(256, 2)
void gemm2(const __half* __restrict__ A,
           const __half* __restrict__ Bhi, const __half* __restrict__ Blo,
           int twob_limit,
           const float* __restrict__ bs0, const float* __restrict__ bs1,
           const float* __restrict__ bs2,
           float* __restrict__ Cf32,
           __half* __restrict__ oQhi, __half* __restrict__ oQlo,
           __half* __restrict__ oKhi, __half* __restrict__ oVhi,
           int M, int N, int K)
{
    extern __shared__ __half dsm[];
    const uint32_t sb = smem_u32(dsm);

    const int tid = threadIdx.x;
    const int lane = tid & 31;
    const int wid  = tid >> 5;
    const int wm = wid & 1;
    const int wn = wid >> 1;
    const int m0 = blockIdx.y * 128;
    const int n0 = blockIdx.x * 128;
    const bool twob = (n0 < twob_limit);

    const int sub = lane >> 3, rr = lane & 7;
    const int rowoff = ((sub & 1) << 3) + rr;
    const int koffb  = (sub >> 1) << 4;

    const uint32_t offA = (uint32_t)((wm*64 + rowoff) * 80 + koffb);
    const uint32_t offB = (uint32_t)((wn*32 + rowoff) * 80 + koffb);

    const int crow0 = tid >> 2, cvv = tid & 3;
    const int NT = twob ? 3 : 2;
    const __half* gsrc[3] = {
        A + (size_t)m0 * K, Bhi + (size_t)n0 * K,
        twob ? Blo + (size_t)n0 * K : Bhi + (size_t)n0 * K };

    float acc[4][4][4];
    #pragma unroll
    for (int i = 0; i < 4; i++)
        #pragma unroll
        for (int j = 0; j < 4; j++)
            #pragma unroll
            for (int q = 0; q < 4; q++) acc[i][j][q] = 0.f;

    const int nChunk = K / 32;

    for (int t = 0; t < NT; t++)
        #pragma unroll
        for (int it = 0; it < 2; it++) {
            int row = crow0 + it * 64;
            cp16(sb + (uint32_t)(t*TILE_B + row*80 + cvv*16),
                 gsrc[t] + (size_t)row * K + cvv*8);
        }
    CP_COMMIT();

    for (int c = 0; c < nChunk; c++) {
        CP_WAIT0();
        __syncthreads();

        if (c + 1 < nChunk) {
            const int k1 = (c + 1) * 32;
            const uint32_t stg = (uint32_t)(((c + 1) & 1) * STAGE_B);
            for (int t = 0; t < NT; t++)
                #pragma unroll
                for (int it = 0; it < 2; it++) {
                    int row = crow0 + it * 64;
                    cp16(sb + stg + (uint32_t)(t*TILE_B + row*80 + cvv*16),
                         gsrc[t] + (size_t)row * K + k1 + cvv*8);
                }
            CP_COMMIT();
        }

        const uint32_t stg = (uint32_t)((c & 1) * STAGE_B);
        const uint32_t aBase = sb + stg + offA;
        const uint32_t bHi = sb + stg + TILE_B + offB;
        const uint32_t bLo = bHi + TILE_B;

        #pragma unroll
        for (int ks = 0; ks < 2; ks++) {
            const uint32_t kb = (uint32_t)(ks * 32);
            uint32_t ah[4][4], bh[2][4], bl[2][4];
            #pragma unroll
            for (int mt = 0; mt < 4; mt++) ldm_x4(ah[mt], aBase + mt * (16*80) + kb);
            ldm_x4(bh[0], bHi + kb);
            ldm_x4(bh[1], bHi + 16*80 + kb);
            if (twob) {
                ldm_x4(bl[0], bLo + kb);
                ldm_x4(bl[1], bLo + 16*80 + kb);
            }

            #pragma unroll
            for (int mt = 0; mt < 4; mt++)
                #pragma unroll
                for (int nf = 0; nf < 4; nf++) {
                    const int nb = nf >> 1, sel = nf & 1;
                    mma_f32(acc[mt][nf], ah[mt], bh[nb][sel], bh[nb][2+sel]);
                    if (twob)
                        mma_f32(acc[mt][nf], ah[mt], bl[nb][sel], bl[nb][2+sel]);
                }
        }
    }

    const int g = lane >> 2, t = lane & 3;
    #pragma unroll
    for (int mt = 0; mt < 4; mt++) {
        const int row = m0 + wm*64 + mt*16 + g;
        #pragma unroll
        for (int nf = 0; nf < 4; nf++) {
            const int colg = n0 + wn*32 + nf*8 + t*2;
            if (Cf32) {
                const float b0 = bs0[colg], b1 = bs0[colg+1];
                float2 lo2 = { acc[mt][nf][0] + b0, acc[mt][nf][1] + b1 };
                float2 hi2 = { acc[mt][nf][2] + b0, acc[mt][nf][3] + b1 };
                *(float2*)(Cf32 + (size_t)row * N + colg)       = lo2;
                *(float2*)(Cf32 + (size_t)(row + 8) * N + colg) = hi2;
            } else {
                const int seg = colg >> 10;
                const int col = colg & 1023;
                const float* bp = (seg == 0) ? bs0 : (seg == 1) ? bs1 : bs2;
                const float b0 = bp[col], b1 = bp[col+1];
                float v00 = acc[mt][nf][0] + b0, v01 = acc[mt][nf][1] + b1;
                float v10 = acc[mt][nf][2] + b0, v11 = acc[mt][nf][3] + b1;
                __half2 h0 = __floats2half2_rn(v00, v01);
                __half2 h1 = __floats2half2_rn(v10, v11);
                const size_t o0 = (size_t)row * D_ + col;
                const size_t o1 = (size_t)(row + 8) * D_ + col;
                if (seg == 0) {
                    __half2 l0 = __floats2half2_rn(v00 - __low2float(h0), v01 - __high2float(h0));
                    __half2 l1 = __floats2half2_rn(v10 - __low2float(h1), v11 - __high2float(h1));
                    *(uint32_t*)(oQhi + o0) = *(const uint32_t*)&h0;
                    *(uint32_t*)(oQlo + o0) = *(const uint32_t*)&l0;
                    *(uint32_t*)(oQhi + o1) = *(const uint32_t*)&h1;
                    *(uint32_t*)(oQlo + o1) = *(const uint32_t*)&l1;
                } else if (seg == 1) {
                    *(uint32_t*)(oKhi + o0) = *(const uint32_t*)&h0;
                    *(uint32_t*)(oKhi + o1) = *(const uint32_t*)&h1;
                } else {
                    *(uint32_t*)(oVhi + o0) = *(const uint32_t*)&h0;
                    *(uint32_t*)(oVhi + o1) = *(const uint32_t*)&h1;
                }
            }
        }
    }
}

// ---------------------------------------------------------------------------
// HMMA fused causal attention. Scores: 2-term (Qhi+Qlo)*K. AV: 1-term Phi*V.
// rows stride padded to 2052 floats (conflict-free score STS). 512 threads.
// ---------------------------------------------------------------------------
#define ROWST 2052   // rows stride in floats (8208 B)
#define KST 72       // 144 B rows
#define VST 264      // 528 B rows (P buffer)
#define OFF_KV 131328            // 16*ROWST*4
#define KVBUF  36864
#define OFF_P  205056            // OFF_KV + 2*KVBUF
#define OFF_Q  213504            // OFF_P + 16*VST*2
#define SM_ATT 218112            // OFF_Q + 2*16*KST*2

__global__ __launch_bounds__(512)
void attn_hmma(const __half* __restrict__ qhi, const __half* __restrict__ qlo,
               const __half* __restrict__ khi, const __half* __restrict__ vhi,
               float* __restrict__ attnw, __half* __restrict__ aohi)
{
    extern __shared__ char smb[];
    const uint32_t sbm = smem_u32(smb);
    float* rows = (float*)smb;
    __half* Phi = (__half*)(smb + OFF_P);
    __half* Qhi = (__half*)(smb + OFF_Q);
    __half* Qlo = Qhi + 16*KST;
    float* sinv = (float*)(smb + OFF_Q);         // after Q frags consumed
    float* pbuf = (float*)(smb + OFF_Q + 64);

    const int qt = blockIdx.x, h = blockIdx.y, b = blockIdx.z;
    const int q0 = qt * TQ;
    const int tid  = threadIdx.x;
    const int lane = tid & 31;
    const int wid  = tid >> 5;
    const int nk   = q0 + TQ;
    const int nChunk = (nk + KCA - 1) / KCA;
    const int nkc = nChunk * KCA;
    const float scale = 0.125f;
    const size_t abase = (((size_t)b * H_ + h) * S_ + q0) * (size_t)S_;

    const int sub = lane >> 3, rr = lane & 7;
    const int arow = ((sub & 1) << 3) + rr;
    const int akoff = (sub >> 1) << 4;

    // ---- early zero-fill attnw cols [nkc, S) — drains behind phase 1 ----
    if (nkc < S_) {
        float* zrow = attnw + abase + (size_t)wid * S_;
        for (int j = nkc + lane*4; j < S_; j += 128)
            stg_cs_f4z(zrow + j);
    }

    // ---- Q tile (hi/lo) ----
    {
        const size_t qgb = ((size_t)(b*S_ + q0)) * D_ + h*HD_;
        for (int i = tid; i < 256; i += 512) {
            int which = i >> 7, u = i & 127;
            int token = u >> 3, seg = u & 7;
            const __half* src = (which ? qlo : qhi) + qgb + (size_t)token * D_ + seg*8;
            __half* dst = (which ? Qlo : Qhi) + token*KST + seg*8;
            *(uint4*)dst = *(const uint4*)src;
        }
    }
    __syncthreads();

    uint32_t qfh[4][4], qfl[4][4];
    {
        const uint32_t qa_hi = smem_u32(Qhi) + (uint32_t)(arow*144 + akoff);
        const uint32_t qa_lo = smem_u32(Qlo) + (uint32_t)(arow*144 + akoff);
        #pragma unroll
        for (int ks = 0; ks < 4; ks++) {
            ldm_x4(qfh[ks], qa_hi + ks*32);
            ldm_x4(qfl[ks], qa_lo + ks*32);
        }
    }

    const int gq = lane >> 2, t2 = (lane & 3) << 1;
    const size_t kgb = ((size_t)b*S_) * D_ + h*HD_;   // same base for K and V

    // ---- Phase 1: scores, cp.async double-buffered K ----
    {
        #pragma unroll
        for (int it = 0; it < 4; it++) {            // chunk 0 -> buf 0
            int u = tid + it * 512;
            int token = u >> 3, seg = u & 7;
            cp16(sbm + OFF_KV + (uint32_t)(token*144 + seg*16),
                 khi + kgb + (size_t)token * D_ + seg*8);
        }
        CP_COMMIT();
    }

    for (int c = 0; c < nChunk; c++) {
        CP_WAIT0();
        __syncthreads();

        if (c + 1 < nChunk) {
            const int k1 = (c + 1) * KCA;
            const uint32_t dstb = sbm + OFF_KV + (uint32_t)(((c + 1) & 1) * KVBUF);
            #pragma unroll
            for (int it = 0; it < 4; it++) {
                int u = tid + it * 512;
                int token = u >> 3, seg = u & 7;
                cp16(dstb + (uint32_t)(token*144 + seg*16),
                     khi + kgb + (size_t)(k1 + token) * D_ + seg*8);
            }
            CP_COMMIT();
        }

        const int k0c = c * KCA;
        float sc[2][4];
        uint32_t scc[2][2];
        #pragma unroll
        for (int ns = 0; ns < 2; ns++) {
            #pragma unroll
            for (int j = 0; j < 4; j++) sc[ns][j] = 0.f;
            scc[ns][0] = 0u; scc[ns][1] = 0u;
        }

        if (k0c + wid*16 <= q0 + 15) {          // causal skip
            const uint32_t kbase = sbm + OFF_KV + (uint32_t)((c & 1) * KVBUF)
                                 + (uint32_t)((wid*16 + arow)*144 + akoff);
            #pragma unroll
            for (int ks = 0; ks < 4; ks++) {
                uint32_t kh[4];
                ldm_x4(kh, kbase + ks*32);
                #pragma unroll
                for (int ns = 0; ns < 2; ns++) {
                    mma_f32(sc[ns], qfh[ks], kh[ns], kh[2+ns]);
                    mma_f16(scc[ns], qfl[ks], kh[ns], kh[2+ns]);   // correction
                }
            }
        }

        #pragma unroll
        for (int ns = 0; ns < 2; ns++) {
            corr_merge(sc[ns], scc[ns]);
            const int kg = k0c + wid*16 + ns*8 + t2;
            rows[(size_t)gq*ROWST + kg]      = (kg   <= q0+gq) ? sc[ns][0]*scale : -INFINITY;
            rows[(size_t)gq*ROWST + kg+1]    = (kg+1 <= q0+gq) ? sc[ns][1]*scale : -INFINITY;
            rows[(size_t)(gq+8)*ROWST + kg]  = (kg   <= q0+gq+8) ? sc[ns][2]*scale : -INFINITY;
            rows[(size_t)(gq+8)*ROWST + kg+1]= (kg+1 <= q0+gq+8) ? sc[ns][3]*scale : -INFINITY;
        }
    }
    __syncthreads();

    // ---- Phase 2: softmax max + exp/sum; store 1/s, no normalize pass ----
    {
        const int r = wid;
        const int nr = q0 + r + 1;
        float* prow = rows + (size_t)r * ROWST;
        float m = -INFINITY;
        for (int i = lane; i < nr; i += 32) m = fmaxf(m, prow[i]);
        #pragma unroll
        for (int off = 16; off; off >>= 1) m = fmaxf(m, __shfl_xor_sync(0xffffffffu, m, off));
        float s = 0.f;
        for (int i = lane; i < nkc; i += 32) {
            float e = __expf(prow[i] - m);
            prow[i] = e;
            s += e;
        }
        #pragma unroll
        for (int off = 16; off; off >>= 1) s += __shfl_xor_sync(0xffffffffu, s, off);
        if (lane == 0) sinv[r] = 1.f / s;
    }
    __syncthreads();

    // ---- Phase 4: AV (1-term); row-major V via ldmatrix.trans; dbuf V ----
    const int khalf = wid >> 3, ntile = wid & 7;
    const uint32_t pA_hi = smem_u32(Phi) + (uint32_t)(arow*528 + akoff + khalf*256);

    {
        #pragma unroll
        for (int it = 0; it < 4; it++) {            // chunk 0 -> buf 0
            int u = tid + it * 512;
            int token = u >> 3, seg = u & 7;
            cp16(sbm + OFF_KV + (uint32_t)(token*144 + seg*16),
                 vhi + kgb + (size_t)token * D_ + seg*8);
        }
        CP_COMMIT();
    }

    float oc[4] = {0.f, 0.f, 0.f, 0.f};
    const uint32_t vlanebase = (uint32_t)((khalf*128 + (lane & 15))*144 + ntile*16);

    for (int c = 0; c < nChunk; c++) {
        const int k0c = c * KCA;
        if (c) __syncthreads();        // prev MMA done with Phi + prev buf

        // fused: rows -> (attnw streaming store) + (Phi fp16 convert), normalized
        #pragma unroll
        for (int it = 0; it < 4; it++) {
            int p = tid + it * 512;
            int r = p >> 7, j2 = (p & 127) << 1;
            float inv = sinv[r];
            float v0 = rows[(size_t)r*ROWST + k0c + j2] * inv;
            float v1 = rows[(size_t)r*ROWST + k0c + j2 + 1] * inv;
            stg_cs_f2(attnw + abase + (size_t)r*S_ + k0c + j2, v0, v1);
            __half2 hb = __floats2half2_rn(v0, v1);
            *(uint32_t*)(Phi + r*VST + j2) = *(const uint32_t*)&hb;
        }

        CP_WAIT0();
        __syncthreads();               // V + Phi visible to all

        if (c + 1 < nChunk) {
            const int k1 = (c + 1) * KCA;
            const uint32_t dstb = sbm + OFF_KV + (uint32_t)(((c + 1) & 1) * KVBUF);
            #pragma unroll
            for (int it = 0; it < 4; it++) {
                int u = tid + it * 512;
                int token = u >> 3, seg = u & 7;
                cp16(dstb + (uint32_t)(token*144 + seg*16),
                     vhi + kgb + (size_t)(k1 + token) * D_ + seg*8);
            }
            CP_COMMIT();
        }

        if (k0c + khalf*128 < nk) {               // skip all-zero-P half-chunks
            const uint32_t vbase = sbm + OFF_KV + (uint32_t)((c & 1) * KVBUF) + vlanebase;
            #pragma unroll
            for (int ks = 0; ks < 8; ks++) {
                uint32_t ph[4], vh[2];
                ldm_x4(ph, pA_hi + ks*32);
                ldm_x2_trans(vh, vbase + (uint32_t)(ks * 16 * 144));
                mma_f32(oc, ph, vh[0], vh[1]);
            }
        }
    }

    // combine k-halves via pbuf
    __syncthreads();
    if (khalf == 1) {
        pbuf[gq*HD_ + ntile*8 + t2]       = oc[0];
        pbuf[gq*HD_ + ntile*8 + t2 + 1]   = oc[1];
        pbuf[(gq+8)*HD_ + ntile*8 + t2]   = oc[2];
        pbuf[(gq+8)*HD_ + ntile*8 + t2+1] = oc[3];
    }
    __syncthreads();
    if (khalf == 0) {
        const int col = h*HD_ + ntile*8 + t2;
        const size_t o0 = ((size_t)(b*S_ + q0 + gq)) * D_ + col;
        const size_t o1 = ((size_t)(b*S_ + q0 + gq + 8)) * D_ + col;
        float v00 = oc[0] + pbuf[gq*HD_ + ntile*8 + t2];
        float v01 = oc[1] + pbuf[gq*HD_ + ntile*8 + t2 + 1];
        float v10 = oc[2] + pbuf[(gq+8)*HD_ + ntile*8 + t2];
        float v11 = oc[3] + pbuf[(gq+8)*HD_ + ntile*8 + t2 + 1];
        __half2 h0 = __floats2half2_rn(v00, v01);
        __half2 h1 = __floats2half2_rn(v10, v11);
        *(uint32_t*)(aohi + o0) = *(const uint32_t*)&h0;
        *(uint32_t*)(aohi + o1) = *(const uint32_t*)&h1;
    }
}

// ---------------------------------------------------------------------------
extern "C" void kernel_launch(void* const* d_in, const int* in_sizes, int n_in,
                              void* d_out, int out_size)
{
    const float* x  = (const float*)d_in[0];
    const float* Wq = (const float*)d_in[1];
    const float* bq = (const float*)d_in[2];
    const float* Wk = (const float*)d_in[3];
    const float* bk = (const float*)d_in[4];
    const float* Wv = (const float*)d_in[5];
    const float* bv = (const float*)d_in[6];
    const float* Wo = (const float*)d_in[7];
    const float* bo = (const float*)d_in[8];

    float* out   = (float*)d_out;                       // [B,S,D]
    float* attnw = out + (size_t)B_ * S_ * D_;          // [B,H,S,S]

    __half *xhi, *whi, *wlo, *aohi, *qhi, *qlo, *khi, *vhi;
    cudaGetSymbolAddress((void**)&xhi,  g_xhi);
    cudaGetSymbolAddress((void**)&whi,  g_whi);
    cudaGetSymbolAddress((void**)&wlo,  g_wlo);
    cudaGetSymbolAddress((void**)&aohi, g_aohi);
    cudaGetSymbolAddress((void**)&qhi,  g_qhi);
    cudaGetSymbolAddress((void**)&qlo,  g_qlo);
    cudaGetSymbolAddress((void**)&khi,  g_khi);
    cudaGetSymbolAddress((void**)&vhi,  g_vhi);

    const int M = MSZ;               // 4096

    convert_all<<<(NPX4 + NW4)/1024, 256>>>(
        (const float4*)x,
        (const float4*)Wq, (const float4*)Wk, (const float4*)Wv, (const float4*)Wo,
        (uint2*)xhi, (uint2*)whi, (uint2*)wlo);

    cudaFuncSetAttribute(gemm2, cudaFuncAttributeMaxDynamicSharedMemorySize, SM_GEMM);

    // fused QKV: N = 3072; Q cols (< 1024) 2-term, K/V cols 1-term
    {
        dim3 g(3072/128, M/128);     // (24, 32)
        gemm2<<<g, 256, SM_GEMM>>>(xhi, whi, wlo, 1024, bq, bk, bv,
                                   nullptr, qhi, qlo, khi, vhi, M, 3072, D_);
    }

    cudaFuncSetAttribute(attn_hmma, cudaFuncAttributeMaxDynamicSharedMemorySize, SM_ATT);
    dim3 attn_grid(S_ / TQ, H_, B_);
    attn_hmma<<<attn_grid, 512, SM_ATT>>>(qhi, qlo, khi, vhi, attnw, aohi);

    // output projection: 1-term (Wo hi only)
    {
        dim3 g(D_/128, M/128);       // (8, 32)
        gemm2<<<g, 256, SM_GEMM>>>(aohi, whi + 3*(size_t)WSZ, nullptr, 0,
                                   bo, nullptr, nullptr, out,
                                   nullptr, nullptr, nullptr, nullptr, M, D_, D_);
    }
}

// round 15
// speedup vs baseline: 1.9910x; 1.0611x over previous
#include <cuda_runtime.h>
#include <cuda_fp16.h>
#include <math.h>
#include <stdint.h>

#define B_  2
#define S_  2048
#define D_  1024
#define H_  16
#define HD_ 64

#define TQ  16
#define KCA 256              // attention key-chunk

#define MSZ (B_*S_)          // 4096 rows
#define WSZ (D_*D_)

// ---------------------------------------------------------------------------
// Scratch (allocation-free rule: __device__ globals)
// ---------------------------------------------------------------------------
__device__ __half g_xhi [MSZ*D_];
__device__ __half g_whi [4*D_*D_];   // Wq, Wk, Wv, Wo stacked
__device__ __half g_wlo [D_*D_];     // lo term for Wq only
__device__ __half g_aohi[MSZ*D_];
__device__ __half g_qhi [MSZ*D_];
__device__ __half g_qlo [MSZ*D_];
__device__ __half g_khi [MSZ*D_];
__device__ __half g_vhi [MSZ*D_];    // v row-major fp16 (consumed via ldmatrix.trans)

// ---------------------------------------------------------------------------
// Fused convert: x -> fp16 hi; W -> fp16 hi (all 4) + lo (Wq only). MLP=4.
// ---------------------------------------------------------------------------
#define NPX4 (MSZ*D_/4)              // 1048576 float4 of x
#define NW4  (4*WSZ/4)               // 1048576 float4 of W

__global__ __launch_bounds__(256)
void convert_all(const float4* __restrict__ x,
                 const float4* __restrict__ w0, const float4* __restrict__ w1,
                 const float4* __restrict__ w2, const float4* __restrict__ w3,
                 uint2* __restrict__ xhi, uint2* __restrict__ whi,
                 uint2* __restrict__ wlo)
{
    const int base = blockIdx.x * 1024 + threadIdx.x;
    float4 v[4];
    #pragma unroll
    for (int j = 0; j < 4; j++) {
        int i = base + j*256;
        if (i < NPX4) {
            v[j] = x[i];
        } else {
            int k = i - NPX4;
            int which = k >> 18;             // WSZ/4 = 262144
            int idx = k & 262143;
            const float4* src = (which == 0) ? w0 : (which == 1) ? w1
                              : (which == 2) ? w2 : w3;
            v[j] = src[idx];
        }
    }
    #pragma unroll
    for (int j = 0; j < 4; j++) {
        int i = base + j*256;
        __half2 h0 = __floats2half2_rn(v[j].x, v[j].y);
        __half2 h1 = __floats2half2_rn(v[j].z, v[j].w);
        uint2 H;
        H.x = *(const uint32_t*)&h0; H.y = *(const uint32_t*)&h1;
        if (i < NPX4) {
            xhi[i] = H;
        } else {
            int k = i - NPX4;
            whi[k] = H;
            if (k < (WSZ/4)) {               // lo only for Wq
                __half2 l0 = __floats2half2_rn(v[j].x - __low2float(h0), v[j].y - __high2float(h0));
                __half2 l1 = __floats2half2_rn(v[j].z - __low2float(h1), v[j].w - __high2float(h1));
                uint2 L;
                L.x = *(const uint32_t*)&l0; L.y = *(const uint32_t*)&l1;
                wlo[k] = L;
            }
        }
    }
}

// ---------------------------------------------------------------------------
// PTX helpers (non-variant ISA)
// ---------------------------------------------------------------------------
__device__ __forceinline__ uint32_t smem_u32(const void* p) {
    uint32_t a;
    asm("{ .reg .u64 t; cvta.to.shared.u64 t, %1; cvt.u32.u64 %0, t; }" : "=r"(a) : "l"(p));
    return a;
}
__device__ __forceinline__ void ldm_x4(uint32_t* r, uint32_t addr) {
    asm volatile("ldmatrix.sync.aligned.m8n8.x4.shared.b16 {%0,%1,%2,%3}, [%4];"
        : "=r"(r[0]), "=r"(r[1]), "=r"(r[2]), "=r"(r[3]) : "r"(addr));
}
__device__ __forceinline__ void ldm_x2_trans(uint32_t* r, uint32_t addr) {
    asm volatile("ldmatrix.sync.aligned.m8n8.x2.trans.shared.b16 {%0,%1}, [%2];"
        : "=r"(r[0]), "=r"(r[1]) : "r"(addr));
}
__device__ __forceinline__ void mma_f32(float* c, const uint32_t* a,
                                        uint32_t b0, uint32_t b1) {
    asm volatile(
        "mma.sync.aligned.m16n8k16.row.col.f32.f16.f16.f32 "
        "{%0,%1,%2,%3}, {%4,%5,%6,%7}, {%8,%9}, {%0,%1,%2,%3};"
        : "+f"(c[0]), "+f"(c[1]), "+f"(c[2]), "+f"(c[3])
        : "r"(a[0]), "r"(a[1]), "r"(a[2]), "r"(a[3]), "r"(b0), "r"(b1));
}
// fp16 accumulate (score correction term)
__device__ __forceinline__ void mma_f16(uint32_t* c, const uint32_t* a,
                                        uint32_t b0, uint32_t b1) {
    asm volatile(
        "mma.sync.aligned.m16n8k16.row.col.f16.f16.f16.f16 "
        "{%0,%1}, {%2,%3,%4,%5}, {%6,%7}, {%0,%1};"
        : "+r"(c[0]), "+r"(c[1])
        : "r"(a[0]), "r"(a[1]), "r"(a[2]), "r"(a[3]), "r"(b0), "r"(b1));
}
__device__ __forceinline__ void corr_merge(float* c, const uint32_t* cc) {
    __half2 h0 = *(const __half2*)&cc[0];
    __half2 h1 = *(const __half2*)&cc[1];
    c[0] += __low2float(h0); c[1] += __high2float(h0);
    c[2] += __low2float(h1); c[3] += __high2float(h1);
}
__device__ __forceinline__ void cp16(uint32_t dst, const void* src) {
    asm volatile("cp.async.cg.shared.global [%0], [%1], 16;" :: "r"(dst), "l"(src));
}
#define CP_COMMIT() asm volatile("cp.async.commit_group;" ::: "memory")
#define CP_WAIT0()  asm volatile("cp.async.wait_group 0;" ::: "memory")
__device__ __forceinline__ void stg_cs_f4(float* p, float4 v) {
    asm volatile("st.global.cs.v4.f32 [%0], {%1,%2,%3,%4};"
        :: "l"(p), "f"(v.x), "f"(v.y), "f"(v.z), "f"(v.w) : "memory");
}
__device__ __forceinline__ void stg_cs_f4z(float* p) {
    asm volatile("st.global.cs.v4.f32 [%0], {%1,%1,%1,%1};" :: "l"(p), "f"(0.f) : "memory");
}

// ---------------------------------------------------------------------------
// HMMA GEMM: C = A @ (Whi [+ Wlo])^T + bias. TWOB compile-time; ofsN shifts
// the output-column window (for segmented QKV launches).
// ---------------------------------------------------------------------------
#define LDT 40
#define TILE_B   (128*LDT*2)         // 10240 bytes
#define STAGE_B  (3*TILE_B)          // 30720 bytes
#define SM_GEMM  (2*STAGE_B)         // 61440 bytes

template<bool TWOB>
__global__ __launch_bounds__(256, 2)
void gemm2(const __half* __restrict__ A,
           const __half* __restrict__ Bhi, const __half* __restrict__ Blo,
           int ofsN,
           const float* __restrict__ bs0, const float* __restrict__ bs1,
           const float* __restrict__ bs2,
           float* __restrict__ Cf32,
           __half* __restrict__ oQhi, __half* __restrict__ oQlo,
           __half* __restrict__ oKhi, __half* __restrict__ oVhi,
           int M, int N, int K)
{
    extern __shared__ __half dsm[];
    const uint32_t sb = smem_u32(dsm);

    const int tid = threadIdx.x;
    const int lane = tid & 31;
    const int wid  = tid >> 5;
    const int wm = wid & 1;
    const int wn = wid >> 1;
    const int m0 = blockIdx.y * 128;
    const int n0 = ofsN + blockIdx.x * 128;

    const int sub = lane >> 3, rr = lane & 7;
    const int rowoff = ((sub & 1) << 3) + rr;
    const int koffb  = (sub >> 1) << 4;

    const uint32_t offA = (uint32_t)((wm*64 + rowoff) * 80 + koffb);
    const uint32_t offB = (uint32_t)((wn*32 + rowoff) * 80 + koffb);

    const int crow0 = tid >> 2, cvv = tid & 3;
    const int NT = TWOB ? 3 : 2;
    const __half* gsrc[3] = {
        A + (size_t)m0 * K, Bhi + (size_t)n0 * K,
        TWOB ? Blo + (size_t)n0 * K : Bhi + (size_t)n0 * K };

    float acc[4][4][4];
    #pragma unroll
    for (int i = 0; i < 4; i++)
        #pragma unroll
        for (int j = 0; j < 4; j++)
            #pragma unroll
            for (int q = 0; q < 4; q++) acc[i][j][q] = 0.f;

    const int nChunk = K / 32;

    #pragma unroll
    for (int t = 0; t < NT; t++)
        #pragma unroll
        for (int it = 0; it < 2; it++) {
            int row = crow0 + it * 64;
            cp16(sb + (uint32_t)(t*TILE_B + row*80 + cvv*16),
                 gsrc[t] + (size_t)row * K + cvv*8);
        }
    CP_COMMIT();

    for (int c = 0; c < nChunk; c++) {
        CP_WAIT0();
        __syncthreads();

        if (c + 1 < nChunk) {
            const int k1 = (c + 1) * 32;
            const uint32_t stg = (uint32_t)(((c + 1) & 1) * STAGE_B);
            #pragma unroll
            for (int t = 0; t < NT; t++)
                #pragma unroll
                for (int it = 0; it < 2; it++) {
                    int row = crow0 + it * 64;
                    cp16(sb + stg + (uint32_t)(t*TILE_B + row*80 + cvv*16),
                         gsrc[t] + (size_t)row * K + k1 + cvv*8);
                }
            CP_COMMIT();
        }

        const uint32_t stg = (uint32_t)((c & 1) * STAGE_B);
        const uint32_t aBase = sb + stg + offA;
        const uint32_t bHi = sb + stg + TILE_B + offB;
        const uint32_t bLo = bHi + TILE_B;

        #pragma unroll
        for (int ks = 0; ks < 2; ks++) {
            const uint32_t kb = (uint32_t)(ks * 32);
            uint32_t ah[4][4], bh[2][4], bl[2][4];
            #pragma unroll
            for (int mt = 0; mt < 4; mt++) ldm_x4(ah[mt], aBase + mt * (16*80) + kb);
            ldm_x4(bh[0], bHi + kb);
            ldm_x4(bh[1], bHi + 16*80 + kb);
            if (TWOB) {
                ldm_x4(bl[0], bLo + kb);
                ldm_x4(bl[1], bLo + 16*80 + kb);
            }

            #pragma unroll
            for (int mt = 0; mt < 4; mt++)
                #pragma unroll
                for (int nf = 0; nf < 4; nf++) {
                    const int nb = nf >> 1, sel = nf & 1;
                    mma_f32(acc[mt][nf], ah[mt], bh[nb][sel], bh[nb][2+sel]);
                    if (TWOB)
                        mma_f32(acc[mt][nf], ah[mt], bl[nb][sel], bl[nb][2+sel]);
                }
        }
    }

    const int g = lane >> 2, t = lane & 3;
    #pragma unroll
    for (int mt = 0; mt < 4; mt++) {
        const int row = m0 + wm*64 + mt*16 + g;
        #pragma unroll
        for (int nf = 0; nf < 4; nf++) {
            const int colg = n0 + wn*32 + nf*8 + t*2;
            if (Cf32) {
                const float b0 = bs0[colg], b1 = bs0[colg+1];
                float2 lo2 = { acc[mt][nf][0] + b0, acc[mt][nf][1] + b1 };
                float2 hi2 = { acc[mt][nf][2] + b0, acc[mt][nf][3] + b1 };
                *(float2*)(Cf32 + (size_t)row * N + colg)       = lo2;
                *(float2*)(Cf32 + (size_t)(row + 8) * N + colg) = hi2;
            } else {
                const int seg = colg >> 10;
                const int col = colg & 1023;
                const float* bp = (seg == 0) ? bs0 : (seg == 1) ? bs1 : bs2;
                const float b0 = bp[col], b1 = bp[col+1];
                float v00 = acc[mt][nf][0] + b0, v01 = acc[mt][nf][1] + b1;
                float v10 = acc[mt][nf][2] + b0, v11 = acc[mt][nf][3] + b1;
                __half2 h0 = __floats2half2_rn(v00, v01);
                __half2 h1 = __floats2half2_rn(v10, v11);
                const size_t o0 = (size_t)row * D_ + col;
                const size_t o1 = (size_t)(row + 8) * D_ + col;
                if (seg == 0) {
                    __half2 l0 = __floats2half2_rn(v00 - __low2float(h0), v01 - __high2float(h0));
                    __half2 l1 = __floats2half2_rn(v10 - __low2float(h1), v11 - __high2float(h1));
                    *(uint32_t*)(oQhi + o0) = *(const uint32_t*)&h0;
                    *(uint32_t*)(oQlo + o0) = *(const uint32_t*)&l0;
                    *(uint32_t*)(oQhi + o1) = *(const uint32_t*)&h1;
                    *(uint32_t*)(oQlo + o1) = *(const uint32_t*)&l1;
                } else if (seg == 1) {
                    *(uint32_t*)(oKhi + o0) = *(const uint32_t*)&h0;
                    *(uint32_t*)(oKhi + o1) = *(const uint32_t*)&h1;
                } else {
                    *(uint32_t*)(oVhi + o0) = *(const uint32_t*)&h0;
                    *(uint32_t*)(oVhi + o1) = *(const uint32_t*)&h1;
                }
            }
        }
    }
}

// ---------------------------------------------------------------------------
// HMMA fused causal attention. Scores: 2-term (Qhi+Qlo)*K. AV: 1-term Phi*V.
// rows stride 2052 floats (conflict-free score STS). P-convert in float4.
// ---------------------------------------------------------------------------
#define ROWST 2052   // rows stride in floats (8208 B)
#define KST 72       // 144 B rows
#define VST 264      // 528 B rows (P buffer)
#define OFF_KV 131328            // 16*ROWST*4
#define KVBUF  36864
#define OFF_P  205056            // OFF_KV + 2*KVBUF
#define OFF_Q  213504            // OFF_P + 16*VST*2
#define SM_ATT 218112            // OFF_Q + 2*16*KST*2

__global__ __launch_bounds__(512)
void attn_hmma(const __half* __restrict__ qhi, const __half* __restrict__ qlo,
               const __half* __restrict__ khi, const __half* __restrict__ vhi,
               float* __restrict__ attnw, __half* __restrict__ aohi)
{
    extern __shared__ char smb[];
    const uint32_t sbm = smem_u32(smb);
    float* rows = (float*)smb;
    __half* Phi = (__half*)(smb + OFF_P);
    __half* Qhi = (__half*)(smb + OFF_Q);
    __half* Qlo = Qhi + 16*KST;
    float* sinv = (float*)(smb + OFF_Q);         // after Q frags consumed
    float* pbuf = (float*)(smb + OFF_Q + 64);

    const int qt = blockIdx.x, h = blockIdx.y, b = blockIdx.z;
    const int q0 = qt * TQ;
    const int tid  = threadIdx.x;
    const int lane = tid & 31;
    const int wid  = tid >> 5;
    const int nk   = q0 + TQ;
    const int nChunk = (nk + KCA - 1) / KCA;
    const int nkc = nChunk * KCA;
    const float scale = 0.125f;
    const size_t abase = (((size_t)b * H_ + h) * S_ + q0) * (size_t)S_;

    const int sub = lane >> 3, rr = lane & 7;
    const int arow = ((sub & 1) << 3) + rr;
    const int akoff = (sub >> 1) << 4;

    // ---- early zero-fill attnw cols [nkc, S) — drains behind phase 1 ----
    if (nkc < S_) {
        float* zrow = attnw + abase + (size_t)wid * S_;
        for (int j = nkc + lane*4; j < S_; j += 128)
            stg_cs_f4z(zrow + j);
    }

    // ---- Q tile (hi/lo) ----
    {
        const size_t qgb = ((size_t)(b*S_ + q0)) * D_ + h*HD_;
        for (int i = tid; i < 256; i += 512) {
            int which = i >> 7, u = i & 127;
            int token = u >> 3, seg = u & 7;
            const __half* src = (which ? qlo : qhi) + qgb + (size_t)token * D_ + seg*8;
            __half* dst = (which ? Qlo : Qhi) + token*KST + seg*8;
            *(uint4*)dst = *(const uint4*)src;
        }
    }
    __syncthreads();

    uint32_t qfh[4][4], qfl[4][4];
    {
        const uint32_t qa_hi = smem_u32(Qhi) + (uint32_t)(arow*144 + akoff);
        const uint32_t qa_lo = smem_u32(Qlo) + (uint32_t)(arow*144 + akoff);
        #pragma unroll
        for (int ks = 0; ks < 4; ks++) {
            ldm_x4(qfh[ks], qa_hi + ks*32);
            ldm_x4(qfl[ks], qa_lo + ks*32);
        }
    }

    const int gq = lane >> 2, t2 = (lane & 3) << 1;
    const size_t kgb = ((size_t)b*S_) * D_ + h*HD_;   // same base for K and V

    // ---- Phase 1: scores, cp.async double-buffered K ----
    {
        #pragma unroll
        for (int it = 0; it < 4; it++) {            // chunk 0 -> buf 0
            int u = tid + it * 512;
            int token = u >> 3, seg = u & 7;
            cp16(sbm + OFF_KV + (uint32_t)(token*144 + seg*16),
                 khi + kgb + (size_t)token * D_ + seg*8);
        }
        CP_COMMIT();
    }

    for (int c = 0; c < nChunk; c++) {
        CP_WAIT0();
        __syncthreads();

        if (c + 1 < nChunk) {
            const int k1 = (c + 1) * KCA;
            const uint32_t dstb = sbm + OFF_KV + (uint32_t)(((c + 1) & 1) * KVBUF);
            #pragma unroll
            for (int it = 0; it < 4; it++) {
                int u = tid + it * 512;
                int token = u >> 3, seg = u & 7;
                cp16(dstb + (uint32_t)(token*144 + seg*16),
                     khi + kgb + (size_t)(k1 + token) * D_ + seg*8);
            }
            CP_COMMIT();
        }

        const int k0c = c * KCA;
        float sc[2][4];
        uint32_t scc[2][2];
        #pragma unroll
        for (int ns = 0; ns < 2; ns++) {
            #pragma unroll
            for (int j = 0; j < 4; j++) sc[ns][j] = 0.f;
            scc[ns][0] = 0u; scc[ns][1] = 0u;
        }

        if (k0c + wid*16 <= q0 + 15) {          // causal skip
            const uint32_t kbase = sbm + OFF_KV + (uint32_t)((c & 1) * KVBUF)
                                 + (uint32_t)((wid*16 + arow)*144 + akoff);
            #pragma unroll
            for (int ks = 0; ks < 4; ks++) {
                uint32_t kh[4];
                ldm_x4(kh, kbase + ks*32);
                #pragma unroll
                for (int ns = 0; ns < 2; ns++) {
                    mma_f32(sc[ns], qfh[ks], kh[ns], kh[2+ns]);
                    mma_f16(scc[ns], qfl[ks], kh[ns], kh[2+ns]);   // correction
                }
            }
        }

        #pragma unroll
        for (int ns = 0; ns < 2; ns++) {
            corr_merge(sc[ns], scc[ns]);
            const int kg = k0c + wid*16 + ns*8 + t2;
            rows[(size_t)gq*ROWST + kg]      = (kg   <= q0+gq) ? sc[ns][0]*scale : -INFINITY;
            rows[(size_t)gq*ROWST + kg+1]    = (kg+1 <= q0+gq) ? sc[ns][1]*scale : -INFINITY;
            rows[(size_t)(gq+8)*ROWST + kg]  = (kg   <= q0+gq+8) ? sc[ns][2]*scale : -INFINITY;
            rows[(size_t)(gq+8)*ROWST + kg+1]= (kg+1 <= q0+gq+8) ? sc[ns][3]*scale : -INFINITY;
        }
    }
    __syncthreads();

    // ---- Phase 2: softmax max + exp/sum; store 1/s, no normalize pass ----
    {
        const int r = wid;
        const int nr = q0 + r + 1;
        float* prow = rows + (size_t)r * ROWST;
        float m = -INFINITY;
        for (int i = lane; i < nr; i += 32) m = fmaxf(m, prow[i]);
        #pragma unroll
        for (int off = 16; off; off >>= 1) m = fmaxf(m, __shfl_xor_sync(0xffffffffu, m, off));
        float s = 0.f;
        for (int i = lane; i < nkc; i += 32) {
            float e = __expf(prow[i] - m);
            prow[i] = e;
            s += e;
        }
        #pragma unroll
        for (int off = 16; off; off >>= 1) s += __shfl_xor_sync(0xffffffffu, s, off);
        if (lane == 0) sinv[r] = 1.f / s;
    }
    __syncthreads();

    // ---- Phase 4: AV (1-term); row-major V via ldmatrix.trans; dbuf V ----
    const int khalf = wid >> 3, ntile = wid & 7;
    const uint32_t pA_hi = smem_u32(Phi) + (uint32_t)(arow*528 + akoff + khalf*256);

    {
        #pragma unroll
        for (int it = 0; it < 4; it++) {            // chunk 0 -> buf 0
            int u = tid + it * 512;
            int token = u >> 3, seg = u & 7;
            cp16(sbm + OFF_KV + (uint32_t)(token*144 + seg*16),
                 vhi + kgb + (size_t)token * D_ + seg*8);
        }
        CP_COMMIT();
    }

    float oc[4] = {0.f, 0.f, 0.f, 0.f};
    const uint32_t vlanebase = (uint32_t)((khalf*128 + (lane & 15))*144 + ntile*16);

    for (int c = 0; c < nChunk; c++) {
        const int k0c = c * KCA;
        if (c) __syncthreads();        // prev MMA done with Phi + prev buf

        // fused: rows -> (attnw v4 streaming store) + (Phi fp16 convert), normalized
        #pragma unroll
        for (int it = 0; it < 2; it++) {
            int p = tid + it * 512;                  // 0..1023
            int r = p >> 6, j4 = (p & 63) << 2;      // 16 rows x 64 quads
            float inv = sinv[r];
            float4 v = *(const float4*)(rows + (size_t)r*ROWST + k0c + j4);
            v.x *= inv; v.y *= inv; v.z *= inv; v.w *= inv;
            stg_cs_f4(attnw + abase + (size_t)r*S_ + k0c + j4, v);
            __half2 hb0 = __floats2half2_rn(v.x, v.y);
            __half2 hb1 = __floats2half2_rn(v.z, v.w);
            uint2 hp;
            hp.x = *(const uint32_t*)&hb0; hp.y = *(const uint32_t*)&hb1;
            *(uint2*)(Phi + r*VST + j4) = hp;
        }

        CP_WAIT0();
        __syncthreads();               // V + Phi visible to all

        if (c + 1 < nChunk) {
            const int k1 = (c + 1) * KCA;
            const uint32_t dstb = sbm + OFF_KV + (uint32_t)(((c + 1) & 1) * KVBUF);
            #pragma unroll
            for (int it = 0; it < 4; it++) {
                int u = tid + it * 512;
                int token = u >> 3, seg = u & 7;
                cp16(dstb + (uint32_t)(token*144 + seg*16),
                     vhi + kgb + (size_t)(k1 + token) * D_ + seg*8);
            }
            CP_COMMIT();
        }

        if (k0c + khalf*128 < nk) {               // skip all-zero-P half-chunks
            const uint32_t vbase = sbm + OFF_KV + (uint32_t)((c & 1) * KVBUF) + vlanebase;
            #pragma unroll
            for (int ks = 0; ks < 8; ks++) {
                uint32_t ph[4], vh[2];
                ldm_x4(ph, pA_hi + ks*32);
                ldm_x2_trans(vh, vbase + (uint32_t)(ks * 16 * 144));
                mma_f32(oc, ph, vh[0], vh[1]);
            }
        }
    }

    // combine k-halves via pbuf
    __syncthreads();
    if (khalf == 1) {
        pbuf[gq*HD_ + ntile*8 + t2]       = oc[0];
        pbuf[gq*HD_ + ntile*8 + t2 + 1]   = oc[1];
        pbuf[(gq+8)*HD_ + ntile*8 + t2]   = oc[2];
        pbuf[(gq+8)*HD_ + ntile*8 + t2+1] = oc[3];
    }
    __syncthreads();
    if (khalf == 0) {
        const int col = h*HD_ + ntile*8 + t2;
        const size_t o0 = ((size_t)(b*S_ + q0 + gq)) * D_ + col;
        const size_t o1 = ((size_t)(b*S_ + q0 + gq + 8)) * D_ + col;
        float v00 = oc[0] + pbuf[gq*HD_ + ntile*8 + t2];
        float v01 = oc[1] + pbuf[gq*HD_ + ntile*8 + t2 + 1];
        float v10 = oc[2] + pbuf[(gq+8)*HD_ + ntile*8 + t2];
        float v11 = oc[3] + pbuf[(gq+8)*HD_ + ntile*8 + t2 + 1];
        __half2 h0 = __floats2half2_rn(v00, v01);
        __half2 h1 = __floats2half2_rn(v10, v11);
        *(uint32_t*)(aohi + o0) = *(const uint32_t*)&h0;
        *(uint32_t*)(aohi + o1) = *(const uint32_t*)&h1;
    }
}

// ---------------------------------------------------------------------------
extern "C" void kernel_launch(void* const* d_in, const int* in_sizes, int n_in,
                              void* d_out, int out_size)
{
    const float* x  = (const float*)d_in[0];
    const float* Wq = (const float*)d_in[1];
    const float* bq = (const float*)d_in[2];
    const float* Wk = (const float*)d_in[3];
    const float* bk = (const float*)d_in[4];
    const float* Wv = (const float*)d_in[5];
    const float* bv = (const float*)d_in[6];
    const float* Wo = (const float*)d_in[7];
    const float* bo = (const float*)d_in[8];

    float* out   = (float*)d_out;                       // [B,S,D]
    float* attnw = out + (size_t)B_ * S_ * D_;          // [B,H,S,S]

    __half *xhi, *whi, *wlo, *aohi, *qhi, *qlo, *khi, *vhi;
    cudaGetSymbolAddress((void**)&xhi,  g_xhi);
    cudaGetSymbolAddress((void**)&whi,  g_whi);
    cudaGetSymbolAddress((void**)&wlo,  g_wlo);
    cudaGetSymbolAddress((void**)&aohi, g_aohi);
    cudaGetSymbolAddress((void**)&qhi,  g_qhi);
    cudaGetSymbolAddress((void**)&qlo,  g_qlo);
    cudaGetSymbolAddress((void**)&khi,  g_khi);
    cudaGetSymbolAddress((void**)&vhi,  g_vhi);

    const int M = MSZ;               // 4096

    convert_all<<<(NPX4 + NW4)/1024, 256>>>(
        (const float4*)x,
        (const float4*)Wq, (const float4*)Wk, (const float4*)Wv, (const float4*)Wo,
        (uint2*)xhi, (uint2*)whi, (uint2*)wlo);

    cudaFuncSetAttribute(gemm2<true>,  cudaFuncAttributeMaxDynamicSharedMemorySize, SM_GEMM);
    cudaFuncSetAttribute(gemm2<false>, cudaFuncAttributeMaxDynamicSharedMemorySize, SM_GEMM);

    // Q projection: 2-term, cols [0, 1024)
    {
        dim3 g(8, M/128);
        gemm2<true><<<g, 256, SM_GEMM>>>(xhi, whi, wlo, 0, bq, bk, bv,
                                         nullptr, qhi, qlo, khi, vhi, M, 3072, D_);
    }
    // K|V projection: 1-term, cols [1024, 3072)
    {
        dim3 g(16, M/128);
        gemm2<false><<<g, 256, SM_GEMM>>>(xhi, whi, nullptr, 1024, bq, bk, bv,
                                          nullptr, qhi, qlo, khi, vhi, M, 3072, D_);
    }

    cudaFuncSetAttribute(attn_hmma, cudaFuncAttributeMaxDynamicSharedMemorySize, SM_ATT);
    dim3 attn_grid(S_ / TQ, H_, B_);
    attn_hmma<<<attn_grid, 512, SM_ATT>>>(qhi, qlo, khi, vhi, attnw, aohi);

    // output projection: 1-term (Wo hi only)
    {
        dim3 g(8, M/128);
        gemm2<false><<<g, 256, SM_GEMM>>>(aohi, whi + 3*(size_t)WSZ, nullptr, 0,
                                          bo, nullptr, nullptr, out,
                                          nullptr, nullptr, nullptr, nullptr, M, D_, D_);
    }
}